// round 12
// baseline (speedup 1.0000x reference)
#include <cuda_runtime.h>
#include <cuda_bf16.h>
#include <math.h>
#include <stdint.h>

// ---------------------------------------------------------------------------
// Problem constants
// ---------------------------------------------------------------------------
namespace {
constexpr int kS = 48;          // source length
constexpr int kT = 32;          // target length
constexpr int kB = 64;          // batch
constexpr int kH = 1024;        // hidden
constexpr int kE = 512;         // embed
constexpr int kV = 32000;       // vocab
constexpr int kG = 3 * kH;      // 3072 gates
constexpr int kF = 3 * kH + kE; // 3584 out-proj features
constexpr int kXW = kE + 2*kH;  // 2560 decoder GRU input width
constexpr int kPAD = 1;
constexpr int kMR = (kT - 1) * kB; // 1984 output rows
constexpr int kMP = 2048;          // padded rows for tensor GEMM
constexpr int kME = kS * kB;       // 3072 encoder rows
}

// ---------------------------------------------------------------------------
// Packed fp32x2 helpers (FFMA2)
// ---------------------------------------------------------------------------
__device__ __forceinline__ unsigned long long pk2(float x) {
    unsigned long long r;
    unsigned u = __float_as_uint(x);
    asm("mov.b64 %0, {%1, %1};" : "=l"(r) : "r"(u));
    return r;
}
__device__ __forceinline__ void fma2(unsigned long long& d,
                                     unsigned long long a,
                                     unsigned long long b) {
    asm("fma.rn.f32x2 %0, %1, %2, %0;" : "+l"(d) : "l"(a), "l"(b));
}
__device__ __forceinline__ float lo2(unsigned long long v) {
    return __uint_as_float((unsigned)v);
}
__device__ __forceinline__ float hi2(unsigned long long v) {
    return __uint_as_float((unsigned)(v >> 32));
}

// ---------------------------------------------------------------------------
// Plain-PTX helpers: cp.async / ldmatrix / mma.sync
// ---------------------------------------------------------------------------
__device__ __forceinline__ uint32_t smem_u32(const void* p) {
    uint32_t a;
    asm("{ .reg .u64 t; cvta.to.shared.u64 t, %1; cvt.u32.u64 %0, t; }"
        : "=r"(a) : "l"(p));
    return a;
}
#define CP_ASYNC16(dst, src) \
    asm volatile("cp.async.cg.shared.global [%0], [%1], 16;" \
                 :: "r"(dst), "l"(src) : "memory")
#define CP_COMMIT() asm volatile("cp.async.commit_group;" ::: "memory")
#define CP_WAIT1()  asm volatile("cp.async.wait_group 1;" ::: "memory")
#define CP_WAIT0()  asm volatile("cp.async.wait_group 0;" ::: "memory")

__device__ __forceinline__ void ldsm4(uint32_t* r, uint32_t addr) {
    asm volatile("ldmatrix.sync.aligned.m8n8.x4.shared.b16 {%0,%1,%2,%3}, [%4];"
                 : "=r"(r[0]), "=r"(r[1]), "=r"(r[2]), "=r"(r[3])
                 : "r"(addr));
}
__device__ __forceinline__ void mma16816(float* d, const uint32_t* a,
                                         const uint32_t* b) {
    asm volatile(
        "mma.sync.aligned.m16n8k16.row.col.f32.bf16.bf16.f32 "
        "{%0,%1,%2,%3}, {%4,%5,%6,%7}, {%8,%9}, {%0,%1,%2,%3};"
        : "+f"(d[0]), "+f"(d[1]), "+f"(d[2]), "+f"(d[3])
        : "r"(a[0]), "r"(a[1]), "r"(a[2]), "r"(a[3]),
          "r"(b[0]), "r"(b[1]));
}

// ---------------------------------------------------------------------------
// Persistent scratch
// ---------------------------------------------------------------------------
__device__ float g_emb[(size_t)kME * kE];
__device__ float g_gxf[(size_t)kME * kG];
__device__ float g_gxb[(size_t)kME * kG];
__device__ float g_enc[(size_t)kME * 2 * kH];      // [b][s][2H]
__device__ float g_encproj[(size_t)kME * kH];
__device__ float g_encWi[(size_t)kME * kG];        // enc @ Wi_d[:,E:]^T
__device__ float g_h[2][2 * kB * kH];              // double-buffered h_f|h_b
__device__ float g_hcat[kB * 2 * kH];
__device__ float g_hdec[kB * kH];
__device__ float g_hp[2 * kB * kH];                // 2 K-partials
__device__ float g_ghd[2 * kB * kG];               // 2 K-partials
__device__ float g_gxet[(size_t)kMR * kG];
__device__ float g_feat[(size_t)kMR * kF];         // [h2, w, et] per step
// bf16 split operands for HMMA GEMMs
__device__ __nv_bfloat16 g_Ahi[(size_t)kMP * kF];  // decoder features
__device__ __nv_bfloat16 g_Alo[(size_t)kMP * kF];
__device__ __nv_bfloat16 g_Bhi[(size_t)kV * kF];   // W_out
__device__ __nv_bfloat16 g_Blo[(size_t)kV * kF];
__device__ __nv_bfloat16 g_Ehi[(size_t)kME * kE];  // encoder embeddings
__device__ __nv_bfloat16 g_Elo[(size_t)kME * kE];
__device__ __nv_bfloat16 g_Wifh[(size_t)kG * kE];  // Wi_f
__device__ __nv_bfloat16 g_Wifl[(size_t)kG * kE];
__device__ __nv_bfloat16 g_Wibh[(size_t)kG * kE];  // Wi_b
__device__ __nv_bfloat16 g_Wibl[(size_t)kG * kE];
__device__ __nv_bfloat16 g_Widh[(size_t)kG * kXW]; // Wi_d (full)
__device__ __nv_bfloat16 g_Widl[(size_t)kG * kXW];
__device__ __nv_bfloat16 g_Wah[(size_t)kH * kG];   // W_attn (full)
__device__ __nv_bfloat16 g_Wal[(size_t)kH * kG];
__device__ __nv_bfloat16 g_Ench[(size_t)kME * 2 * kH];
__device__ __nv_bfloat16 g_Encl[(size_t)kME * 2 * kH];

// ---------------------------------------------------------------------------
__global__ void init_kernel(float* __restrict__ out0) {
    size_t i = (size_t)blockIdx.x * blockDim.x + threadIdx.x;
    if (i < (size_t)kB * kV) out0[i] = 0.f;
    if (i < (size_t)2 * kB * kH) g_h[0][i] = 0.f;
}

// encoder embedding gather + bf16 split emit
__global__ void enc_embed_kernel(const int* __restrict__ src,
                                 const float* __restrict__ table) {
    int row = blockIdx.x;
    int tok = src[row];
    float4 v = ((const float4*)(table + (size_t)tok * kE))[threadIdx.x];
    ((float4*)(g_emb + (size_t)row * kE))[threadIdx.x] = v;
    size_t o = (size_t)row * kE + threadIdx.x * 4;
    float vv[4] = { v.x, v.y, v.z, v.w };
#pragma unroll
    for (int q = 0; q < 4; q++) {
        __nv_bfloat16 h = __float2bfloat16(vv[q]);
        g_Ehi[o + q] = h;
        g_Elo[o + q] = __float2bfloat16(vv[q] - __bfloat162float(h));
    }
}

// decoder embeddings -> feat float + bf16 split into g_Ahi/g_Alo et columns
__global__ void dec_embed_all(const int* __restrict__ trg,
                              const float* __restrict__ emb_dec) {
    int row = blockIdx.x;
    int tok = trg[row];
    float4 v = ((const float4*)(emb_dec + (size_t)tok * kE))[threadIdx.x];
    ((float4*)(g_feat + (size_t)row * kF + 3 * kH))[threadIdx.x] = v;
    size_t o = (size_t)row * kF + 3 * kH + threadIdx.x * 4;
    float vv[4] = { v.x, v.y, v.z, v.w };
#pragma unroll
    for (int q = 0; q < 4; q++) {
        __nv_bfloat16 h = __float2bfloat16(vv[q]);
        g_Ahi[o + q] = h;
        g_Alo[o + q] = __float2bfloat16(vv[q] - __bfloat162float(h));
    }
}

// ---------------------------------------------------------------------------
// bf16 split conversion (4 elements/thread, fully vectorized)
// ---------------------------------------------------------------------------
__global__ void cvt_split4(const float4* __restrict__ src,
                           __nv_bfloat162* __restrict__ hi,
                           __nv_bfloat162* __restrict__ lo, size_t n4) {
    size_t i = (size_t)blockIdx.x * blockDim.x + threadIdx.x;
    if (i >= n4) return;
    float4 v = src[i];
    __nv_bfloat16 h0 = __float2bfloat16(v.x);
    __nv_bfloat16 h1 = __float2bfloat16(v.y);
    __nv_bfloat16 h2 = __float2bfloat16(v.z);
    __nv_bfloat16 h3 = __float2bfloat16(v.w);
    hi[2 * i]     = __nv_bfloat162(h0, h1);
    hi[2 * i + 1] = __nv_bfloat162(h2, h3);
    lo[2 * i]     = __nv_bfloat162(
        __float2bfloat16(v.x - __bfloat162float(h0)),
        __float2bfloat16(v.y - __bfloat162float(h1)));
    lo[2 * i + 1] = __nv_bfloat162(
        __float2bfloat16(v.z - __bfloat162float(h2)),
        __float2bfloat16(v.w - __bfloat162float(h3)));
}

// convert feat columns [0, 3H) for all padded rows
__global__ void cvt_feat_split() {
    size_t i = (size_t)blockIdx.x * blockDim.x + threadIdx.x;
    if (i >= (size_t)kMP * (3 * kH) / 4) return;
    size_t row = i / (3 * kH / 4);
    size_t col = (i % (3 * kH / 4)) * 4;
    float4 v = make_float4(0.f, 0.f, 0.f, 0.f);
    if (row < (size_t)kMR)
        v = *(const float4*)(g_feat + row * kF + col);
    size_t o = row * kF + col;
    float vv[4] = { v.x, v.y, v.z, v.w };
#pragma unroll
    for (int q = 0; q < 4; q++) {
        __nv_bfloat16 h = __float2bfloat16(vv[q]);
        g_Ahi[o + q] = h;
        g_Alo[o + q] = __float2bfloat16(vv[q] - __bfloat162float(h));
    }
}

// ---------------------------------------------------------------------------
// Generalized HMMA GEMM (bf16x3 split, fp32 accum)
// ---------------------------------------------------------------------------
namespace outg {
constexpr int BM = 128, BN = 128, BK = 64;
constexpr int HALF = 16384;
constexpr int STAGE = 4 * HALF;
constexpr int SMEM_SZ = 2 * STAGE;          // 131072
}

__device__ __forceinline__ void hg_prefetch(
    const __nv_bfloat16* __restrict__ Ah, const __nv_bfloat16* __restrict__ Al,
    int lda,
    const __nv_bfloat16* __restrict__ Bh, const __nv_bfloat16* __restrict__ Bl,
    int ldb, int k0, uint32_t buf, int tid, int m0, int n0) {
    using namespace outg;
#pragma unroll
    for (int i = 0; i < 4; i++) {
        int id = tid + i * 256;
        int row = id >> 3, c = id & 7;
        uint32_t off = (uint32_t)(row << 7) + (c << 4);
        uint32_t sw = off ^ ((off >> 3) & 0x70);
        size_t ga = (size_t)(m0 + row) * lda + k0 + c * 8;
        size_t gb = (size_t)(n0 + row) * ldb + k0 + c * 8;
        CP_ASYNC16(buf + sw, Ah + ga);
        CP_ASYNC16(buf + HALF + sw, Al + ga);
        CP_ASYNC16(buf + 2 * HALF + sw, Bh + gb);
        CP_ASYNC16(buf + 3 * HALF + sw, Bl + gb);
    }
}

// Round-9 ordering (measured fastest): per fragment group, the three split
// passes issue back-to-back on the same accumulator.
__device__ __forceinline__ void hg_compute(uint32_t buf, int lane,
                                           int wm, int wn,
                                           float acc[2][8][4]) {
    using namespace outg;
    const int g = lane >> 3, r = lane & 7;
#pragma unroll
    for (int ks = 0; ks < 4; ks++) {
        uint32_t ahi[2][4], alo[2][4];
#pragma unroll
        for (int mi = 0; mi < 2; mi++) {
            int row = wm + mi * 16 + ((g & 1) << 3) + r;
            int chunk = ks * 2 + (g >> 1);
            uint32_t off = (uint32_t)(row << 7) + (chunk << 4);
            uint32_t sw = off ^ ((off >> 3) & 0x70);
            ldsm4(ahi[mi], buf + sw);
            ldsm4(alo[mi], buf + HALF + sw);
        }
        uint32_t bhi[4][4], blo[4][4];
#pragma unroll
        for (int np = 0; np < 4; np++) {
            int row = wn + np * 16 + ((g >> 1) << 3) + r;
            int chunk = ks * 2 + (g & 1);
            uint32_t off = (uint32_t)(row << 7) + (chunk << 4);
            uint32_t sw = off ^ ((off >> 3) & 0x70);
            ldsm4(bhi[np], buf + 2 * HALF + sw);
            ldsm4(blo[np], buf + 3 * HALF + sw);
        }
#pragma unroll
        for (int mi = 0; mi < 2; mi++) {
#pragma unroll
            for (int np = 0; np < 4; np++) {
#pragma unroll
                for (int a = 0; a < 2; a++) {
                    uint32_t bh[2] = { bhi[np][2 * a], bhi[np][2 * a + 1] };
                    uint32_t bl[2] = { blo[np][2 * a], blo[np][2 * a + 1] };
                    float* d = acc[mi][np * 2 + a];
                    mma16816(d, ahi[mi], bh);
                    mma16816(d, ahi[mi], bl);
                    mma16816(d, alo[mi], bh);
                }
            }
        }
    }
}

__global__ __launch_bounds__(256, 1)
void hgemm(const __nv_bfloat16* __restrict__ Ah,
           const __nv_bfloat16* __restrict__ Al, int lda,
           const __nv_bfloat16* __restrict__ Bh,
           const __nv_bfloat16* __restrict__ Bl, int ldb,
           const float* __restrict__ bias, float* __restrict__ C, int ldc,
           int M, int K) {
    using namespace outg;
    extern __shared__ char smem[];
    const uint32_t sb = smem_u32(smem);
    const int tid = threadIdx.x;
    const int wid = tid >> 5, lane = tid & 31;
    const int m0 = blockIdx.x * BM;
    const int n0 = blockIdx.y * BN;
    const int wm = (wid & 3) * 32;
    const int wn = (wid >> 2) * 64;
    const int nslab = K / BK;

    float acc[2][8][4];
#pragma unroll
    for (int i = 0; i < 2; i++)
#pragma unroll
        for (int j = 0; j < 8; j++)
#pragma unroll
            for (int q = 0; q < 4; q++) acc[i][j][q] = 0.f;

    hg_prefetch(Ah, Al, lda, Bh, Bl, ldb, 0, sb, tid, m0, n0);
    CP_COMMIT();
    hg_prefetch(Ah, Al, lda, Bh, Bl, ldb, BK, sb + STAGE, tid, m0, n0);
    CP_COMMIT();

    for (int s = 0; s < nslab; s++) {
        const int st = s & 1;
        if (s == nslab - 1) { CP_WAIT0(); } else { CP_WAIT1(); }
        __syncthreads();
        hg_compute(sb + st * STAGE, lane, wm, wn, acc);
        __syncthreads();
        if (s + 2 < nslab) {
            hg_prefetch(Ah, Al, lda, Bh, Bl, ldb, (s + 2) * BK,
                        sb + st * STAGE, tid, m0, n0);
            CP_COMMIT();
        }
    }

    const int r0 = m0 + wm + (lane >> 2);
    const int c0 = n0 + wn + (lane & 3) * 2;
#pragma unroll
    for (int mi = 0; mi < 2; mi++) {
#pragma unroll
        for (int ni = 0; ni < 8; ni++) {
            int row = r0 + mi * 16;
            int col = c0 + ni * 8;
            const float* d = acc[mi][ni];
            float b0 = bias ? bias[col] : 0.f;
            float b1 = bias ? bias[col + 1] : 0.f;
            if (row < M) {
                C[(size_t)row * ldc + col]     = d[0] + b0;
                C[(size_t)row * ldc + col + 1] = d[1] + b1;
            }
            if (row + 8 < M) {
                C[(size_t)(row + 8) * ldc + col]     = d[2] + b0;
                C[(size_t)(row + 8) * ldc + col + 1] = d[3] + b1;
            }
        }
    }
}

// ---------------------------------------------------------------------------
// Fused encoder recurrence step, k-lane packed FFMA2 inner loop.
// ---------------------------------------------------------------------------
__global__ __launch_bounds__(256)
void enc_step_fused(int s,
                    const float* __restrict__ Wh_f,
                    const float* __restrict__ Wh_b,
                    const float* __restrict__ bh_f,
                    const float* __restrict__ bh_b) {
    constexpr int BK = 32;
    constexpr int LDA = BK + 4;   // 36 floats = 144B rows (16B aligned)
    __shared__ __align__(16) float As[64][LDA];
    __shared__ __align__(16) float Bs[48][LDA];
    const int tid = threadIdx.x;
    const int dir = blockIdx.y;
    const int j0 = blockIdx.x * 16;
    const float* hread = g_h[s & 1] + dir * (kB * kH);
    float* hwrite = g_h[(s + 1) & 1] + dir * (kB * kH);
    const float* Wh = dir ? Wh_b : Wh_f;
    const float* bh = dir ? bh_b : bh_f;
    const float* gxbase = dir ? g_gxb : g_gxf;
    const int gpos = dir ? (kS - 1 - s) : s;

    const int tm = (tid >> 4) << 2;   // 0..60, 4 rows/thread
    const int tn = tid & 15;          // gate column within 16-wide tile

    unsigned long long acc[4][3];
#pragma unroll
    for (int i = 0; i < 4; i++)
#pragma unroll
        for (int q = 0; q < 3; q++) acc[i][q] = 0ull;

    for (int k0 = 0; k0 < kH; k0 += BK) {
#pragma unroll
        for (int h = 0; h < 2; h++) {
            int id = tid + h * 256;
            int r = id >> 3, cc = (id & 7) << 2;
            *(float4*)&As[r][cc] =
                *(const float4*)(hread + (size_t)r * kH + k0 + cc);
        }
#pragma unroll
        for (int h = 0; h < 2; h++) {
            int id = tid + h * 256;
            if (id < 384) {
                int r = id >> 3, cc = (id & 7) << 2;
                int sec = r >> 4, wi = r & 15;
                *(float4*)&Bs[r][cc] = *(const float4*)(Wh +
                    (size_t)(sec * kH + j0 + wi) * kH + k0 + cc);
            }
        }
        __syncthreads();
#pragma unroll
        for (int k = 0; k < BK; k += 2) {
            unsigned long long b0 = *(const unsigned long long*)&Bs[tn][k];
            unsigned long long b1 = *(const unsigned long long*)&Bs[16 + tn][k];
            unsigned long long b2 = *(const unsigned long long*)&Bs[32 + tn][k];
#pragma unroll
            for (int i = 0; i < 4; i++) {
                unsigned long long a =
                    *(const unsigned long long*)&As[tm + i][k];
                fma2(acc[i][0], a, b0);
                fma2(acc[i][1], a, b1);
                fma2(acc[i][2], a, b2);
            }
        }
        __syncthreads();
    }

    const int j = j0 + tn;
    const float bhr = bh[j], bhz = bh[kH + j], bhn = bh[2 * kH + j];
#pragma unroll
    for (int i = 0; i < 4; i++) {
        int b = tm + i;
        float ghr = lo2(acc[i][0]) + hi2(acc[i][0]) + bhr;
        float ghz = lo2(acc[i][1]) + hi2(acc[i][1]) + bhz;
        float ghn = lo2(acc[i][2]) + hi2(acc[i][2]) + bhn;
        const float* gx = gxbase + ((size_t)gpos * kB + b) * kG;
        float r = 1.f / (1.f + expf(-(gx[j] + ghr)));
        float z = 1.f / (1.f + expf(-(gx[kH + j] + ghz)));
        float n = tanhf(gx[2 * kH + j] + r * ghn);
        float hold = hread[(size_t)b * kH + j];
        float h2 = (1.f - z) * n + z * hold;
        hwrite[(size_t)b * kH + j] = h2;
        g_enc[((size_t)b * kS + gpos) * (2 * kH) + dir * kH + j] = h2;
    }
}

// ---------------------------------------------------------------------------
// Small-M GEMM body (FFMA2)
// ---------------------------------------------------------------------------
__device__ __forceinline__
void gemm64_body(const float* __restrict__ A, int lda,
                 const float* __restrict__ Bm, int ldb,
                 const float* __restrict__ bias,
                 float* __restrict__ C, int ldc,
                 int K, int act, int nb) {
    constexpr int BK = 32;
    __shared__ __align__(16) float As[BK][64];
    __shared__ __align__(16) float Bs[BK][64];
    const int tid = threadIdx.x;
    const int bn = nb * 64;
    const int lr = tid >> 3;
    const int lc = (tid & 7) << 2;
    const int tm = (tid >> 4) << 2;
    const int tn = (tid & 15) << 2;

    unsigned long long acc[4][2];
#pragma unroll
    for (int i = 0; i < 4; i++) { acc[i][0] = 0ull; acc[i][1] = 0ull; }

    for (int k0 = 0; k0 < K; k0 += BK) {
#pragma unroll
        for (int h = 0; h < 2; h++) {
            int r = lr + h * 32;
            float4 v = *(const float4*)(A + (size_t)r * lda + k0 + lc);
            As[lc + 0][r] = v.x; As[lc + 1][r] = v.y;
            As[lc + 2][r] = v.z; As[lc + 3][r] = v.w;
            float4 w = *(const float4*)(Bm + (size_t)(bn + r) * ldb + k0 + lc);
            Bs[lc + 0][r] = w.x; Bs[lc + 1][r] = w.y;
            Bs[lc + 2][r] = w.z; Bs[lc + 3][r] = w.w;
        }
        __syncthreads();
#pragma unroll
        for (int k = 0; k < BK; k++) {
            float4 af = *(const float4*)&As[k][tm];
            unsigned long long aa[4];
            aa[0] = pk2(af.x); aa[1] = pk2(af.y);
            aa[2] = pk2(af.z); aa[3] = pk2(af.w);
            ulonglong2 bv = *(const ulonglong2*)&Bs[k][tn];
#pragma unroll
            for (int i = 0; i < 4; i++) {
                fma2(acc[i][0], aa[i], bv.x);
                fma2(acc[i][1], aa[i], bv.y);
            }
        }
        __syncthreads();
    }
#pragma unroll
    for (int i = 0; i < 4; i++) {
        int col = bn + tn;
        float4 v;
        v.x = lo2(acc[i][0]); v.y = hi2(acc[i][0]);
        v.z = lo2(acc[i][1]); v.w = hi2(acc[i][1]);
        if (bias) {
            v.x += bias[col + 0]; v.y += bias[col + 1];
            v.z += bias[col + 2]; v.w += bias[col + 3];
        }
        if (act == 1) {
            v.x = tanhf(v.x); v.y = tanhf(v.y);
            v.z = tanhf(v.z); v.w = tanhf(v.w);
        }
        *(float4*)(C + (size_t)(tm + i) * ldc + col) = v;
    }
}

__global__ __launch_bounds__(256)
void gemm64(const float* __restrict__ A, int lda,
            const float* __restrict__ Bm, int ldb,
            const float* __restrict__ bias,
            float* __restrict__ C, int ldc, int K, int act) {
    gemm64_body(A, lda, Bm, ldb, bias, C, ldc, K, act, blockIdx.x);
}

// Decoder pre-attention GEMMs, K-split 2: hp (32 blocks) + ghd (96 blocks)
__global__ __launch_bounds__(256)
void dec_pre_gemm(const float* __restrict__ W_attn,
                  const float* __restrict__ Wh_d,
                  const float* __restrict__ bh_d) {
    int x = blockIdx.x;
    if (x < 32) {
        int ks = x >> 4, nb = x & 15;
        gemm64_body(g_hdec + ks * 512, kH, W_attn + ks * 512, kG, nullptr,
                    g_hp + (size_t)ks * kB * kH, kH, 512, 0, nb);
    } else {
        int i = x - 32;
        int ks = i / 48, nb = i % 48;
        gemm64_body(g_hdec + ks * 512, kH, Wh_d + ks * 512, kH,
                    ks == 0 ? bh_d : nullptr,
                    g_ghd + (size_t)ks * kB * kG, kG, 512, 0, nb);
    }
}

// ---------------------------------------------------------------------------
__global__ void hcat_kernel() {
    int idx = blockIdx.x * blockDim.x + threadIdx.x;
    if (idx >= 2 * kB * kH) return;
    int dir = idx / (kB * kH);
    int rem = idx - dir * (kB * kH);
    int b = rem / kH, j = rem - b * kH;
    g_hcat[(size_t)b * 2 * kH + dir * kH + j] = g_h[0][idx];
}

// ---------------------------------------------------------------------------
// Fused decoder step, split across 2 CTAs per batch element.
// grid (kB, 2), 512 threads. Block z owns gate columns [z*512, z*512+512)
// in each of the 3 gate sections, plus context columns [z*1024, z*1024+1024).
// ---------------------------------------------------------------------------
__global__ __launch_bounds__(512)
void attn_step_fused(const int* __restrict__ src,
                     const float* __restrict__ v_attn,
                     const float* __restrict__ gxet_t,
                     float* __restrict__ feat_t) {
    const int b = blockIdx.x;
    const int z = blockIdx.y;
    __shared__ float sc[kS];
    __shared__ float sgxw[3 * 512];
    const int tid = threadIdx.x, warp = tid >> 5, lane = tid & 31;
    const float* hp0 = g_hp + (size_t)b * kH;
    const float* hp1 = g_hp + (size_t)kB * kH + (size_t)b * kH;

    // 1. attention scores (duplicated across the 2 z-blocks; cheap)
    for (int s = warp; s < kS; s += 16) {
        const float* ep = g_encproj + ((size_t)b * kS + s) * kH;
        float p = 0.f;
        for (int j = lane; j < kH; j += 32)
            p += v_attn[j] * tanhf(hp0[j] + hp1[j] + ep[j]);
#pragma unroll
        for (int o = 16; o; o >>= 1) p += __shfl_xor_sync(0xffffffffu, p, o);
        if (lane == 0) sc[s] = (src[s * kB + b] != kPAD) ? p : -1e10f;
    }
    __syncthreads();

    // 2. softmax over S=48
    if (tid < 32) {
        float v1 = sc[tid];
        float v2 = (tid + 32 < kS) ? sc[tid + 32] : -1e30f;
        float mx = fmaxf(v1, v2);
#pragma unroll
        for (int o = 16; o; o >>= 1) mx = fmaxf(mx, __shfl_xor_sync(0xffffffffu, mx, o));
        float e1 = expf(v1 - mx);
        float e2 = (tid + 32 < kS) ? expf(v2 - mx) : 0.f;
        float sm = e1 + e2;
#pragma unroll
        for (int o = 16; o; o >>= 1) sm += __shfl_xor_sync(0xffffffffu, sm, o);
        float inv = 1.f / sm;
        sc[tid] = e1 * inv;
        if (tid + 32 < kS) sc[tid + 32] = e2 * inv;
    }
    __syncthreads();

    // 3a. context w half: columns [z*1024, z*1024+1024) -> float4 [z*256, +256)
    if (tid < 256) {
        int c4 = z * 256 + tid;
        float4 acc = make_float4(0.f, 0.f, 0.f, 0.f);
        const float4* base = (const float4*)(g_enc + (size_t)b * kS * 2 * kH) + c4;
#pragma unroll 8
        for (int s = 0; s < kS; s++) {
            float a = sc[s];
            float4 e = base[s * (2 * kH / 4)];
            acc.x += a * e.x; acc.y += a * e.y;
            acc.z += a * e.z; acc.w += a * e.w;
        }
        ((float4*)(feat_t + (size_t)b * kF + kH))[c4] = acc;
    }
    // 3b. gxw half: 3 sections x 512 cols = 384 float4 for this block
    if (tid < 384) {
        int sec = tid >> 7;             // 0..2
        int i = tid & 127;              // float4 within section slice
        int c4 = (sec * kH + z * 512) / 4 + i;
        float4 acc = make_float4(0.f, 0.f, 0.f, 0.f);
        const float4* base = (const float4*)(g_encWi + (size_t)b * kS * kG) + c4;
#pragma unroll 8
        for (int s = 0; s < kS; s++) {
            float a = sc[s];
            float4 e = base[s * (kG / 4)];
            acc.x += a * e.x; acc.y += a * e.y;
            acc.z += a * e.z; acc.w += a * e.w;
        }
        *(float4*)(sgxw + tid * 4) = acc;   // local layout: sec*512 + i*4
    }
    __syncthreads();

    // 4. GRU gate for j in [z*512, z*512+512), one per thread
    {
        const int jl = tid;             // local j within half
        const int j = z * 512 + jl;
        const float* q0 = g_ghd + (size_t)b * kG;
        const float* q1 = g_ghd + (size_t)kB * kG + (size_t)b * kG;
        const float* gx = gxet_t + (size_t)b * kG;
        float h = g_hdec[(size_t)b * kH + j];
        float xr = gx[j] + sgxw[jl];
        float xz = gx[kH + j] + sgxw[512 + jl];
        float xn = gx[2 * kH + j] + sgxw[1024 + jl];
        float ghr = q0[j] + q1[j];
        float ghz = q0[kH + j] + q1[kH + j];
        float ghn = q0[2 * kH + j] + q1[2 * kH + j];
        float r = 1.f / (1.f + expf(-(xr + ghr)));
        float zt = 1.f / (1.f + expf(-(xz + ghz)));
        float n = tanhf(xn + r * ghn);
        float h2 = (1.f - zt) * n + zt * h;
        g_hdec[(size_t)b * kH + j] = h2;
        feat_t[(size_t)b * kF + j] = h2;
    }
}

// ---------------------------------------------------------------------------
// Host orchestration (two-stream fork/join, graph-capturable)
// ---------------------------------------------------------------------------
extern "C" void kernel_launch(void* const* d_in, const int* in_sizes, int n_in,
                              void* d_out, int out_size) {
    const int*   src     = (const int*)d_in[0];
    const int*   trg     = (const int*)d_in[1];
    const float* emb_enc = (const float*)d_in[2];
    const float* Wi_f    = (const float*)d_in[3];
    const float* Wh_f    = (const float*)d_in[4];
    const float* bi_f    = (const float*)d_in[5];
    const float* bh_f    = (const float*)d_in[6];
    const float* Wi_b    = (const float*)d_in[7];
    const float* Wh_b    = (const float*)d_in[8];
    const float* bi_b    = (const float*)d_in[9];
    const float* bh_b    = (const float*)d_in[10];
    const float* W_fc    = (const float*)d_in[11];
    const float* b_fc    = (const float*)d_in[12];
    const float* W_attn  = (const float*)d_in[13];
    const float* b_attn  = (const float*)d_in[14];
    const float* v_attn  = (const float*)d_in[15];
    const float* emb_dec = (const float*)d_in[16];
    const float* Wi_d    = (const float*)d_in[17];
    const float* Wh_d    = (const float*)d_in[18];
    const float* bi_d    = (const float*)d_in[19];
    const float* bh_d    = (const float*)d_in[20];
    const float* W_out   = (const float*)d_in[21];
    const float* b_out   = (const float*)d_in[22];
    float* out = (float*)d_out;

    float *p_enc, *p_ep, *p_encWi, *p_hcat, *p_hdec, *p_gxet, *p_feat,
          *p_gxf, *p_gxb;
    __nv_bfloat16 *p_Ahi, *p_Alo, *p_Bhi, *p_Blo, *p_Ehi, *p_Elo;
    __nv_bfloat16 *p_Wifh, *p_Wifl, *p_Wibh, *p_Wibl;
    __nv_bfloat16 *p_Widh, *p_Widl, *p_Wah, *p_Wal, *p_Ench, *p_Encl;
    cudaGetSymbolAddress((void**)&p_enc, g_enc);
    cudaGetSymbolAddress((void**)&p_ep, g_encproj);
    cudaGetSymbolAddress((void**)&p_encWi, g_encWi);
    cudaGetSymbolAddress((void**)&p_hcat, g_hcat);
    cudaGetSymbolAddress((void**)&p_hdec, g_hdec);
    cudaGetSymbolAddress((void**)&p_gxet, g_gxet);
    cudaGetSymbolAddress((void**)&p_feat, g_feat);
    cudaGetSymbolAddress((void**)&p_gxf, g_gxf);
    cudaGetSymbolAddress((void**)&p_gxb, g_gxb);
    cudaGetSymbolAddress((void**)&p_Ahi, g_Ahi);
    cudaGetSymbolAddress((void**)&p_Alo, g_Alo);
    cudaGetSymbolAddress((void**)&p_Bhi, g_Bhi);
    cudaGetSymbolAddress((void**)&p_Blo, g_Blo);
    cudaGetSymbolAddress((void**)&p_Ehi, g_Ehi);
    cudaGetSymbolAddress((void**)&p_Elo, g_Elo);
    cudaGetSymbolAddress((void**)&p_Wifh, g_Wifh);
    cudaGetSymbolAddress((void**)&p_Wifl, g_Wifl);
    cudaGetSymbolAddress((void**)&p_Wibh, g_Wibh);
    cudaGetSymbolAddress((void**)&p_Wibl, g_Wibl);
    cudaGetSymbolAddress((void**)&p_Widh, g_Widh);
    cudaGetSymbolAddress((void**)&p_Widl, g_Widl);
    cudaGetSymbolAddress((void**)&p_Wah, g_Wah);
    cudaGetSymbolAddress((void**)&p_Wal, g_Wal);
    cudaGetSymbolAddress((void**)&p_Ench, g_Ench);
    cudaGetSymbolAddress((void**)&p_Encl, g_Encl);

    static cudaStream_t s1 = nullptr;
    static cudaEvent_t evFork = nullptr, evJoin = nullptr;
    if (s1 == nullptr) {
        cudaStreamCreateWithFlags(&s1, cudaStreamNonBlocking);
        cudaEventCreateWithFlags(&evFork, cudaEventDisableTiming);
        cudaEventCreateWithFlags(&evJoin, cudaEventDisableTiming);
        cudaFuncSetAttribute(hgemm,
                             cudaFuncAttributeMaxDynamicSharedMemorySize,
                             outg::SMEM_SZ);
    }

    // fork side stream off the capture stream
    cudaEventRecord(evFork, 0);
    cudaStreamWaitEvent(s1, evFork, 0);

    // --- main stream: encoder-critical path ---
    init_kernel<<<((size_t)kB * kV + 255) / 256, 256>>>(out);
    enc_embed_kernel<<<kME, 128>>>(src, emb_enc);
    {
        size_t n4 = (size_t)kG * kE / 4;
        cvt_split4<<<(unsigned)((n4 + 255) / 256), 256>>>(
            (const float4*)Wi_f, (__nv_bfloat162*)p_Wifh,
            (__nv_bfloat162*)p_Wifl, n4);
        cvt_split4<<<(unsigned)((n4 + 255) / 256), 256>>>(
            (const float4*)Wi_b, (__nv_bfloat162*)p_Wibh,
            (__nv_bfloat162*)p_Wibl, n4);
    }
    // --- side stream: decoder-prep + big weight conversions ---
    dec_embed_all<<<kMR, 128, 0, s1>>>(trg, emb_dec);
    // --- main: input-gate GEMMs ---
    hgemm<<<dim3(kME / 128, kG / 128), 256, outg::SMEM_SZ>>>(
        p_Ehi, p_Elo, kE, p_Wifh, p_Wifl, kE, bi_f, p_gxf, kG, kME, kE);
    hgemm<<<dim3(kME / 128, kG / 128), 256, outg::SMEM_SZ>>>(
        p_Ehi, p_Elo, kE, p_Wibh, p_Wibl, kE, bi_b, p_gxb, kG, kME, kE);
    // --- side stream continues ---
    {
        size_t n4 = (size_t)kG * kXW / 4;
        cvt_split4<<<(unsigned)((n4 + 255) / 256), 256, 0, s1>>>(
            (const float4*)Wi_d, (__nv_bfloat162*)p_Widh,
            (__nv_bfloat162*)p_Widl, n4);
        n4 = (size_t)kH * kG / 4;
        cvt_split4<<<(unsigned)((n4 + 255) / 256), 256, 0, s1>>>(
            (const float4*)W_attn, (__nv_bfloat162*)p_Wah,
            (__nv_bfloat162*)p_Wal, n4);
        hgemm<<<dim3(kMP / 128, kG / 128), 256, outg::SMEM_SZ, s1>>>(
            p_Ahi + 3 * kH, p_Alo + 3 * kH, kF, p_Widh, p_Widl, kXW, bi_d,
            p_gxet, kG, kMR, kE);
        n4 = (size_t)kV * kF / 4;
        cvt_split4<<<(unsigned)((n4 + 255) / 256), 256, 0, s1>>>(
            (const float4*)W_out, (__nv_bfloat162*)p_Bhi,
            (__nv_bfloat162*)p_Blo, n4);
    }
    cudaEventRecord(evJoin, s1);

    // --- main: encoder recurrence (overlaps side stream) ---
    for (int s = 0; s < kS; s++)
        enc_step_fused<<<dim3(64, 2), 256>>>(s, Wh_f, Wh_b, bh_f, bh_b);

    // decoder init hidden
    hcat_kernel<<<(2 * kB * kH) / 256, 256>>>();
    gemm64<<<kH / 64, 256>>>(p_hcat, 2 * kH, W_fc, 2 * kH, b_fc,
                             p_hdec, kH, 2 * kH, 1);

    // encoder split + attention projection + encWi (needs side stream)
    {
        size_t n4 = (size_t)kME * 2 * kH / 4;
        cvt_split4<<<(unsigned)((n4 + 255) / 256), 256>>>(
            (const float4*)p_enc, (__nv_bfloat162*)p_Ench,
            (__nv_bfloat162*)p_Encl, n4);
        cudaStreamWaitEvent(0, evJoin, 0);
        hgemm<<<dim3(kME / 128, kH / 128), 256, outg::SMEM_SZ>>>(
            p_Ench, p_Encl, 2 * kH, p_Wah + kH, p_Wal + kH, kG, b_attn,
            p_ep, kH, kME, 2 * kH);
        hgemm<<<dim3(kME / 128, kG / 128), 256, outg::SMEM_SZ>>>(
            p_Ench, p_Encl, 2 * kH, p_Widh + kE, p_Widl + kE, kXW,
            (const float*)nullptr, p_encWi, kG, kME, 2 * kH);
    }

    // decoder loop: 2 launches per step (L2 stays decoder-owned)
    for (int t = 0; t < kT - 1; t++) {
        float* feat_t = p_feat + (size_t)t * kB * kF;
        dec_pre_gemm<<<128, 256>>>(W_attn, Wh_d, bh_d);
        attn_step_fused<<<dim3(kB, 2), 512>>>(src, v_attn,
                                              p_gxet + (size_t)t * kB * kG,
                                              feat_t);
    }

    // split-convert features, single full HMMA output projection
    {
        size_t n = (size_t)kMP * (3 * kH) / 4;
        cvt_feat_split<<<(unsigned)((n + 255) / 256), 256>>>();
        hgemm<<<dim3(kMP / 128, kV / 128), 256, outg::SMEM_SZ>>>(
            p_Ahi, p_Alo, kF, p_Bhi, p_Blo, kF, b_out,
            out + (size_t)kB * kV, kV, kMR, kF);
    }
}

// round 14
// speedup vs baseline: 1.1442x; 1.1442x over previous
#include <cuda_runtime.h>
#include <cuda_bf16.h>
#include <cuda_fp16.h>
#include <math.h>
#include <stdint.h>

// ---------------------------------------------------------------------------
// Problem constants
// ---------------------------------------------------------------------------
namespace {
constexpr int kS = 48;          // source length
constexpr int kT = 32;          // target length
constexpr int kB = 64;          // batch
constexpr int kH = 1024;        // hidden
constexpr int kE = 512;         // embed
constexpr int kV = 32000;       // vocab
constexpr int kG = 3 * kH;      // 3072 gates
constexpr int kF = 3 * kH + kE; // 3584 out-proj features
constexpr int kXW = kE + 2*kH;  // 2560 decoder GRU input width
constexpr int kPAD = 1;
constexpr int kMR = (kT - 1) * kB; // 1984 output rows
constexpr int kMP = 2048;          // padded rows for tensor GEMM
constexpr int kME = kS * kB;       // 3072 encoder rows
}

// ---------------------------------------------------------------------------
// Packed fp32x2 helpers (FFMA2)
// ---------------------------------------------------------------------------
__device__ __forceinline__ unsigned long long pk2(float x) {
    unsigned long long r;
    unsigned u = __float_as_uint(x);
    asm("mov.b64 %0, {%1, %1};" : "=l"(r) : "r"(u));
    return r;
}
__device__ __forceinline__ void fma2(unsigned long long& d,
                                     unsigned long long a,
                                     unsigned long long b) {
    asm("fma.rn.f32x2 %0, %1, %2, %0;" : "+l"(d) : "l"(a), "l"(b));
}
__device__ __forceinline__ float lo2(unsigned long long v) {
    return __uint_as_float((unsigned)v);
}
__device__ __forceinline__ float hi2(unsigned long long v) {
    return __uint_as_float((unsigned)(v >> 32));
}

// ---------------------------------------------------------------------------
// Plain-PTX helpers: cp.async / ldmatrix / mma.sync
// ---------------------------------------------------------------------------
__device__ __forceinline__ uint32_t smem_u32(const void* p) {
    uint32_t a;
    asm("{ .reg .u64 t; cvta.to.shared.u64 t, %1; cvt.u32.u64 %0, t; }"
        : "=r"(a) : "l"(p));
    return a;
}
#define CP_ASYNC16(dst, src) \
    asm volatile("cp.async.cg.shared.global [%0], [%1], 16;" \
                 :: "r"(dst), "l"(src) : "memory")
#define CP_COMMIT() asm volatile("cp.async.commit_group;" ::: "memory")
#define CP_WAIT1()  asm volatile("cp.async.wait_group 1;" ::: "memory")
#define CP_WAIT0()  asm volatile("cp.async.wait_group 0;" ::: "memory")

__device__ __forceinline__ void ldsm4(uint32_t* r, uint32_t addr) {
    asm volatile("ldmatrix.sync.aligned.m8n8.x4.shared.b16 {%0,%1,%2,%3}, [%4];"
                 : "=r"(r[0]), "=r"(r[1]), "=r"(r[2]), "=r"(r[3])
                 : "r"(addr));
}
__device__ __forceinline__ void mma16816(float* d, const uint32_t* a,
                                         const uint32_t* b) {
    asm volatile(
        "mma.sync.aligned.m16n8k16.row.col.f32.bf16.bf16.f32 "
        "{%0,%1,%2,%3}, {%4,%5,%6,%7}, {%8,%9}, {%0,%1,%2,%3};"
        : "+f"(d[0]), "+f"(d[1]), "+f"(d[2]), "+f"(d[3])
        : "r"(a[0]), "r"(a[1]), "r"(a[2]), "r"(a[3]),
          "r"(b[0]), "r"(b[1]));
}
__device__ __forceinline__ void mma16816h(float* d, const uint32_t* a,
                                          const uint32_t* b) {
    asm volatile(
        "mma.sync.aligned.m16n8k16.row.col.f32.f16.f16.f32 "
        "{%0,%1,%2,%3}, {%4,%5,%6,%7}, {%8,%9}, {%0,%1,%2,%3};"
        : "+f"(d[0]), "+f"(d[1]), "+f"(d[2]), "+f"(d[3])
        : "r"(a[0]), "r"(a[1]), "r"(a[2]), "r"(a[3]),
          "r"(b[0]), "r"(b[1]));
}

// ---------------------------------------------------------------------------
// Persistent scratch
// ---------------------------------------------------------------------------
__device__ float g_emb[(size_t)kME * kE];
__device__ float g_gxf[(size_t)kME * kG];
__device__ float g_gxb[(size_t)kME * kG];
__device__ float g_enc[(size_t)kME * 2 * kH];      // [b][s][2H]
__device__ float g_encproj[(size_t)kME * kH];
__device__ float g_encWi[(size_t)kME * kG];        // enc @ Wi_d[:,E:]^T
__device__ float g_h[2][2 * kB * kH];              // double-buffered h_f|h_b
__device__ float g_hcat[kB * 2 * kH];
__device__ float g_hdec[kB * kH];
__device__ float g_hp[2 * kB * kH];                // 2 K-partials
__device__ float g_ghd[2 * kB * kG];               // 2 K-partials
__device__ float g_gxet[(size_t)kMR * kG];
__device__ float g_feat[(size_t)kMR * kF];         // [h2, w, et] per step
// bf16 split operands for bf16x3 HMMA GEMMs
__device__ __nv_bfloat16 g_Ahi[(size_t)kMP * kF];  // decoder et cols (gxet gemm)
__device__ __nv_bfloat16 g_Alo[(size_t)kMP * kF];
__device__ __nv_bfloat16 g_Ehi[(size_t)kME * kE];  // encoder embeddings
__device__ __nv_bfloat16 g_Elo[(size_t)kME * kE];
__device__ __nv_bfloat16 g_Wifh[(size_t)kG * kE];  // Wi_f
__device__ __nv_bfloat16 g_Wifl[(size_t)kG * kE];
__device__ __nv_bfloat16 g_Wibh[(size_t)kG * kE];  // Wi_b
__device__ __nv_bfloat16 g_Wibl[(size_t)kG * kE];
__device__ __nv_bfloat16 g_Widh[(size_t)kG * kXW]; // Wi_d (full)
__device__ __nv_bfloat16 g_Widl[(size_t)kG * kXW];
__device__ __nv_bfloat16 g_Wah[(size_t)kH * kG];   // W_attn (full)
__device__ __nv_bfloat16 g_Wal[(size_t)kH * kG];
__device__ __nv_bfloat16 g_Ench[(size_t)kME * 2 * kH];
__device__ __nv_bfloat16 g_Encl[(size_t)kME * 2 * kH];
// fp16 operands for the 2-pass final GEMM (A split, B single)
__device__ __half g_Fhi[(size_t)kMP * kF];         // feat hi
__device__ __half g_Flo[(size_t)kMP * kF];         // feat lo
__device__ __half g_Bf16[(size_t)kV * kF];         // W_out fp16

// ---------------------------------------------------------------------------
__global__ void init_kernel(float* __restrict__ out0) {
    size_t i = (size_t)blockIdx.x * blockDim.x + threadIdx.x;
    if (i < (size_t)kB * kV) out0[i] = 0.f;
    if (i < (size_t)2 * kB * kH) g_h[0][i] = 0.f;
}

// encoder embedding gather + bf16 split emit
__global__ void enc_embed_kernel(const int* __restrict__ src,
                                 const float* __restrict__ table) {
    int row = blockIdx.x;
    int tok = src[row];
    float4 v = ((const float4*)(table + (size_t)tok * kE))[threadIdx.x];
    ((float4*)(g_emb + (size_t)row * kE))[threadIdx.x] = v;
    size_t o = (size_t)row * kE + threadIdx.x * 4;
    float vv[4] = { v.x, v.y, v.z, v.w };
#pragma unroll
    for (int q = 0; q < 4; q++) {
        __nv_bfloat16 h = __float2bfloat16(vv[q]);
        g_Ehi[o + q] = h;
        g_Elo[o + q] = __float2bfloat16(vv[q] - __bfloat162float(h));
    }
}

// decoder embeddings -> feat float + bf16 split into g_Ahi/g_Alo et columns
__global__ void dec_embed_all(const int* __restrict__ trg,
                              const float* __restrict__ emb_dec) {
    int row = blockIdx.x;
    int tok = trg[row];
    float4 v = ((const float4*)(emb_dec + (size_t)tok * kE))[threadIdx.x];
    ((float4*)(g_feat + (size_t)row * kF + 3 * kH))[threadIdx.x] = v;
    size_t o = (size_t)row * kF + 3 * kH + threadIdx.x * 4;
    float vv[4] = { v.x, v.y, v.z, v.w };
#pragma unroll
    for (int q = 0; q < 4; q++) {
        __nv_bfloat16 h = __float2bfloat16(vv[q]);
        g_Ahi[o + q] = h;
        g_Alo[o + q] = __float2bfloat16(vv[q] - __bfloat162float(h));
    }
}

// ---------------------------------------------------------------------------
// bf16 split conversion (4 elements/thread, fully vectorized)
// ---------------------------------------------------------------------------
__global__ void cvt_split4(const float4* __restrict__ src,
                           __nv_bfloat162* __restrict__ hi,
                           __nv_bfloat162* __restrict__ lo, size_t n4) {
    size_t i = (size_t)blockIdx.x * blockDim.x + threadIdx.x;
    if (i >= n4) return;
    float4 v = src[i];
    __nv_bfloat16 h0 = __float2bfloat16(v.x);
    __nv_bfloat16 h1 = __float2bfloat16(v.y);
    __nv_bfloat16 h2 = __float2bfloat16(v.z);
    __nv_bfloat16 h3 = __float2bfloat16(v.w);
    hi[2 * i]     = __nv_bfloat162(h0, h1);
    hi[2 * i + 1] = __nv_bfloat162(h2, h3);
    lo[2 * i]     = __nv_bfloat162(
        __float2bfloat16(v.x - __bfloat162float(h0)),
        __float2bfloat16(v.y - __bfloat162float(h1)));
    lo[2 * i + 1] = __nv_bfloat162(
        __float2bfloat16(v.z - __bfloat162float(h2)),
        __float2bfloat16(v.w - __bfloat162float(h3)));
}

// fp32 -> single fp16 conversion (4 elements/thread)
__global__ void cvt16_4(const float4* __restrict__ src,
                        __half2* __restrict__ dst, size_t n4) {
    size_t i = (size_t)blockIdx.x * blockDim.x + threadIdx.x;
    if (i >= n4) return;
    float4 v = src[i];
    dst[2 * i]     = __floats2half2_rn(v.x, v.y);
    dst[2 * i + 1] = __floats2half2_rn(v.z, v.w);
}

// convert ALL feat columns to fp16 hi/lo for the 2-pass final GEMM
__global__ void cvt_feat16() {
    size_t i = (size_t)blockIdx.x * blockDim.x + threadIdx.x;
    if (i >= (size_t)kMP * kF / 4) return;
    size_t row = i / (kF / 4);
    size_t col = (i % (kF / 4)) * 4;
    float4 v = make_float4(0.f, 0.f, 0.f, 0.f);
    if (row < (size_t)kMR)
        v = *(const float4*)(g_feat + row * kF + col);
    size_t o = row * kF + col;
    float vv[4] = { v.x, v.y, v.z, v.w };
#pragma unroll
    for (int q = 0; q < 4; q++) {
        __half h = __float2half_rn(vv[q]);
        g_Fhi[o + q] = h;
        g_Flo[o + q] = __float2half_rn(vv[q] - __half2float(h));
    }
}

// ---------------------------------------------------------------------------
// Generalized bf16x3 HMMA GEMM (round-9 proven config)
// ---------------------------------------------------------------------------
namespace outg {
constexpr int BM = 128, BN = 128, BK = 64;
constexpr int HALF = 16384;
constexpr int STAGE = 4 * HALF;
constexpr int SMEM_SZ = 2 * STAGE;          // 131072
}

__device__ __forceinline__ void hg_prefetch(
    const __nv_bfloat16* __restrict__ Ah, const __nv_bfloat16* __restrict__ Al,
    int lda,
    const __nv_bfloat16* __restrict__ Bh, const __nv_bfloat16* __restrict__ Bl,
    int ldb, int k0, uint32_t buf, int tid, int m0, int n0) {
    using namespace outg;
#pragma unroll
    for (int i = 0; i < 4; i++) {
        int id = tid + i * 256;
        int row = id >> 3, c = id & 7;
        uint32_t off = (uint32_t)(row << 7) + (c << 4);
        uint32_t sw = off ^ ((off >> 3) & 0x70);
        size_t ga = (size_t)(m0 + row) * lda + k0 + c * 8;
        size_t gb = (size_t)(n0 + row) * ldb + k0 + c * 8;
        CP_ASYNC16(buf + sw, Ah + ga);
        CP_ASYNC16(buf + HALF + sw, Al + ga);
        CP_ASYNC16(buf + 2 * HALF + sw, Bh + gb);
        CP_ASYNC16(buf + 3 * HALF + sw, Bl + gb);
    }
}

__device__ __forceinline__ void hg_compute(uint32_t buf, int lane,
                                           int wm, int wn,
                                           float acc[2][8][4]) {
    using namespace outg;
    const int g = lane >> 3, r = lane & 7;
#pragma unroll
    for (int ks = 0; ks < 4; ks++) {
        uint32_t ahi[2][4], alo[2][4];
#pragma unroll
        for (int mi = 0; mi < 2; mi++) {
            int row = wm + mi * 16 + ((g & 1) << 3) + r;
            int chunk = ks * 2 + (g >> 1);
            uint32_t off = (uint32_t)(row << 7) + (chunk << 4);
            uint32_t sw = off ^ ((off >> 3) & 0x70);
            ldsm4(ahi[mi], buf + sw);
            ldsm4(alo[mi], buf + HALF + sw);
        }
        uint32_t bhi[4][4], blo[4][4];
#pragma unroll
        for (int np = 0; np < 4; np++) {
            int row = wn + np * 16 + ((g >> 1) << 3) + r;
            int chunk = ks * 2 + (g & 1);
            uint32_t off = (uint32_t)(row << 7) + (chunk << 4);
            uint32_t sw = off ^ ((off >> 3) & 0x70);
            ldsm4(bhi[np], buf + 2 * HALF + sw);
            ldsm4(blo[np], buf + 3 * HALF + sw);
        }
#pragma unroll
        for (int mi = 0; mi < 2; mi++) {
#pragma unroll
            for (int np = 0; np < 4; np++) {
#pragma unroll
                for (int a = 0; a < 2; a++) {
                    uint32_t bh[2] = { bhi[np][2 * a], bhi[np][2 * a + 1] };
                    uint32_t bl[2] = { blo[np][2 * a], blo[np][2 * a + 1] };
                    float* d = acc[mi][np * 2 + a];
                    mma16816(d, ahi[mi], bh);
                    mma16816(d, ahi[mi], bl);
                    mma16816(d, alo[mi], bh);
                }
            }
        }
    }
}

__global__ __launch_bounds__(256, 1)
void hgemm(const __nv_bfloat16* __restrict__ Ah,
           const __nv_bfloat16* __restrict__ Al, int lda,
           const __nv_bfloat16* __restrict__ Bh,
           const __nv_bfloat16* __restrict__ Bl, int ldb,
           const float* __restrict__ bias, float* __restrict__ C, int ldc,
           int M, int K) {
    using namespace outg;
    extern __shared__ char smem[];
    const uint32_t sb = smem_u32(smem);
    const int tid = threadIdx.x;
    const int wid = tid >> 5, lane = tid & 31;
    const int m0 = blockIdx.x * BM;
    const int n0 = blockIdx.y * BN;
    const int wm = (wid & 3) * 32;
    const int wn = (wid >> 2) * 64;
    const int nslab = K / BK;

    float acc[2][8][4];
#pragma unroll
    for (int i = 0; i < 2; i++)
#pragma unroll
        for (int j = 0; j < 8; j++)
#pragma unroll
            for (int q = 0; q < 4; q++) acc[i][j][q] = 0.f;

    hg_prefetch(Ah, Al, lda, Bh, Bl, ldb, 0, sb, tid, m0, n0);
    CP_COMMIT();
    hg_prefetch(Ah, Al, lda, Bh, Bl, ldb, BK, sb + STAGE, tid, m0, n0);
    CP_COMMIT();

    for (int s = 0; s < nslab; s++) {
        const int st = s & 1;
        if (s == nslab - 1) { CP_WAIT0(); } else { CP_WAIT1(); }
        __syncthreads();
        hg_compute(sb + st * STAGE, lane, wm, wn, acc);
        __syncthreads();
        if (s + 2 < nslab) {
            hg_prefetch(Ah, Al, lda, Bh, Bl, ldb, (s + 2) * BK,
                        sb + st * STAGE, tid, m0, n0);
            CP_COMMIT();
        }
    }

    const int r0 = m0 + wm + (lane >> 2);
    const int c0 = n0 + wn + (lane & 3) * 2;
#pragma unroll
    for (int mi = 0; mi < 2; mi++) {
#pragma unroll
        for (int ni = 0; ni < 8; ni++) {
            int row = r0 + mi * 16;
            int col = c0 + ni * 8;
            const float* d = acc[mi][ni];
            float b0 = bias ? bias[col] : 0.f;
            float b1 = bias ? bias[col + 1] : 0.f;
            if (row < M) {
                C[(size_t)row * ldc + col]     = d[0] + b0;
                C[(size_t)row * ldc + col + 1] = d[1] + b1;
            }
            if (row + 8 < M) {
                C[(size_t)(row + 8) * ldc + col]     = d[2] + b0;
                C[(size_t)(row + 8) * ldc + col + 1] = d[3] + b1;
            }
        }
    }
}

// ---------------------------------------------------------------------------
// 2-pass fp16 HMMA GEMM for the final projection:
//   C = (Ahi + Alo)[M,K] * B[N,K]^T + bias,  A split fp16, B single fp16.
// Tile 128x128x64, 3 smem sections per stage (Ahi|Alo|B), 2-stage cp.async.
// ---------------------------------------------------------------------------
namespace outh {
constexpr int BM = 128, BN = 128, BK = 64;
constexpr int HALF = 16384;
constexpr int STAGE = 3 * HALF;             // 49152
constexpr int SMEM_SZ = 2 * STAGE;          // 98304
}

__device__ __forceinline__ void h2_prefetch(
    const __half* __restrict__ Ah, const __half* __restrict__ Al, int lda,
    const __half* __restrict__ Bm, int ldb,
    int k0, uint32_t buf, int tid, int m0, int n0) {
    using namespace outh;
#pragma unroll
    for (int i = 0; i < 4; i++) {
        int id = tid + i * 256;
        int row = id >> 3, c = id & 7;
        uint32_t off = (uint32_t)(row << 7) + (c << 4);
        uint32_t sw = off ^ ((off >> 3) & 0x70);
        size_t ga = (size_t)(m0 + row) * lda + k0 + c * 8;
        size_t gb = (size_t)(n0 + row) * ldb + k0 + c * 8;
        CP_ASYNC16(buf + sw, Ah + ga);
        CP_ASYNC16(buf + HALF + sw, Al + ga);
        CP_ASYNC16(buf + 2 * HALF + sw, Bm + gb);
    }
}

__device__ __forceinline__ void h2_compute(uint32_t buf, int lane,
                                           int wm, int wn,
                                           float acc[2][8][4]) {
    using namespace outh;
    const int g = lane >> 3, r = lane & 7;
#pragma unroll
    for (int ks = 0; ks < 4; ks++) {
        uint32_t ahi[2][4], alo[2][4];
#pragma unroll
        for (int mi = 0; mi < 2; mi++) {
            int row = wm + mi * 16 + ((g & 1) << 3) + r;
            int chunk = ks * 2 + (g >> 1);
            uint32_t off = (uint32_t)(row << 7) + (chunk << 4);
            uint32_t sw = off ^ ((off >> 3) & 0x70);
            ldsm4(ahi[mi], buf + sw);
            ldsm4(alo[mi], buf + HALF + sw);
        }
        uint32_t bfr[4][4];
#pragma unroll
        for (int np = 0; np < 4; np++) {
            int row = wn + np * 16 + ((g >> 1) << 3) + r;
            int chunk = ks * 2 + (g & 1);
            uint32_t off = (uint32_t)(row << 7) + (chunk << 4);
            uint32_t sw = off ^ ((off >> 3) & 0x70);
            ldsm4(bfr[np], buf + 2 * HALF + sw);
        }
#pragma unroll
        for (int mi = 0; mi < 2; mi++) {
#pragma unroll
            for (int np = 0; np < 4; np++) {
#pragma unroll
                for (int a = 0; a < 2; a++) {
                    uint32_t bh[2] = { bfr[np][2 * a], bfr[np][2 * a + 1] };
                    float* d = acc[mi][np * 2 + a];
                    mma16816h(d, ahi[mi], bh);
                    mma16816h(d, alo[mi], bh);
                }
            }
        }
    }
}

__global__ __launch_bounds__(256, 1)
void hgemm2(const __half* __restrict__ Ah, const __half* __restrict__ Al,
            int lda,
            const __half* __restrict__ Bm, int ldb,
            const float* __restrict__ bias, float* __restrict__ C, int ldc,
            int M, int K) {
    using namespace outh;
    extern __shared__ char smem[];
    const uint32_t sb = smem_u32(smem);
    const int tid = threadIdx.x;
    const int wid = tid >> 5, lane = tid & 31;
    const int m0 = blockIdx.x * BM;
    const int n0 = blockIdx.y * BN;
    const int wm = (wid & 3) * 32;
    const int wn = (wid >> 2) * 64;
    const int nslab = K / BK;

    float acc[2][8][4];
#pragma unroll
    for (int i = 0; i < 2; i++)
#pragma unroll
        for (int j = 0; j < 8; j++)
#pragma unroll
            for (int q = 0; q < 4; q++) acc[i][j][q] = 0.f;

    h2_prefetch(Ah, Al, lda, Bm, ldb, 0, sb, tid, m0, n0);
    CP_COMMIT();
    h2_prefetch(Ah, Al, lda, Bm, ldb, BK, sb + STAGE, tid, m0, n0);
    CP_COMMIT();

    for (int s = 0; s < nslab; s++) {
        const int st = s & 1;
        if (s == nslab - 1) { CP_WAIT0(); } else { CP_WAIT1(); }
        __syncthreads();
        h2_compute(sb + st * STAGE, lane, wm, wn, acc);
        __syncthreads();
        if (s + 2 < nslab) {
            h2_prefetch(Ah, Al, lda, Bm, ldb, (s + 2) * BK,
                        sb + st * STAGE, tid, m0, n0);
            CP_COMMIT();
        }
    }

    const int r0 = m0 + wm + (lane >> 2);
    const int c0 = n0 + wn + (lane & 3) * 2;
#pragma unroll
    for (int mi = 0; mi < 2; mi++) {
#pragma unroll
        for (int ni = 0; ni < 8; ni++) {
            int row = r0 + mi * 16;
            int col = c0 + ni * 8;
            const float* d = acc[mi][ni];
            float b0 = bias[col], b1 = bias[col + 1];
            if (row < M) {
                C[(size_t)row * ldc + col]     = d[0] + b0;
                C[(size_t)row * ldc + col + 1] = d[1] + b1;
            }
            if (row + 8 < M) {
                C[(size_t)(row + 8) * ldc + col]     = d[2] + b0;
                C[(size_t)(row + 8) * ldc + col + 1] = d[3] + b1;
            }
        }
    }
}

// ---------------------------------------------------------------------------
// Fused encoder recurrence step, k-lane packed FFMA2 inner loop.
// ---------------------------------------------------------------------------
__global__ __launch_bounds__(256)
void enc_step_fused(int s,
                    const float* __restrict__ Wh_f,
                    const float* __restrict__ Wh_b,
                    const float* __restrict__ bh_f,
                    const float* __restrict__ bh_b) {
    constexpr int BK = 32;
    constexpr int LDA = BK + 4;   // 36 floats = 144B rows (16B aligned)
    __shared__ __align__(16) float As[64][LDA];
    __shared__ __align__(16) float Bs[48][LDA];
    const int tid = threadIdx.x;
    const int dir = blockIdx.y;
    const int j0 = blockIdx.x * 16;
    const float* hread = g_h[s & 1] + dir * (kB * kH);
    float* hwrite = g_h[(s + 1) & 1] + dir * (kB * kH);
    const float* Wh = dir ? Wh_b : Wh_f;
    const float* bh = dir ? bh_b : bh_f;
    const float* gxbase = dir ? g_gxb : g_gxf;
    const int gpos = dir ? (kS - 1 - s) : s;

    const int tm = (tid >> 4) << 2;   // 0..60, 4 rows/thread
    const int tn = tid & 15;          // gate column within 16-wide tile

    unsigned long long acc[4][3];
#pragma unroll
    for (int i = 0; i < 4; i++)
#pragma unroll
        for (int q = 0; q < 3; q++) acc[i][q] = 0ull;

    for (int k0 = 0; k0 < kH; k0 += BK) {
#pragma unroll
        for (int h = 0; h < 2; h++) {
            int id = tid + h * 256;
            int r = id >> 3, cc = (id & 7) << 2;
            *(float4*)&As[r][cc] =
                *(const float4*)(hread + (size_t)r * kH + k0 + cc);
        }
#pragma unroll
        for (int h = 0; h < 2; h++) {
            int id = tid + h * 256;
            if (id < 384) {
                int r = id >> 3, cc = (id & 7) << 2;
                int sec = r >> 4, wi = r & 15;
                *(float4*)&Bs[r][cc] = *(const float4*)(Wh +
                    (size_t)(sec * kH + j0 + wi) * kH + k0 + cc);
            }
        }
        __syncthreads();
#pragma unroll
        for (int k = 0; k < BK; k += 2) {
            unsigned long long b0 = *(const unsigned long long*)&Bs[tn][k];
            unsigned long long b1 = *(const unsigned long long*)&Bs[16 + tn][k];
            unsigned long long b2 = *(const unsigned long long*)&Bs[32 + tn][k];
#pragma unroll
            for (int i = 0; i < 4; i++) {
                unsigned long long a =
                    *(const unsigned long long*)&As[tm + i][k];
                fma2(acc[i][0], a, b0);
                fma2(acc[i][1], a, b1);
                fma2(acc[i][2], a, b2);
            }
        }
        __syncthreads();
    }

    const int j = j0 + tn;
    const float bhr = bh[j], bhz = bh[kH + j], bhn = bh[2 * kH + j];
#pragma unroll
    for (int i = 0; i < 4; i++) {
        int b = tm + i;
        float ghr = lo2(acc[i][0]) + hi2(acc[i][0]) + bhr;
        float ghz = lo2(acc[i][1]) + hi2(acc[i][1]) + bhz;
        float ghn = lo2(acc[i][2]) + hi2(acc[i][2]) + bhn;
        const float* gx = gxbase + ((size_t)gpos * kB + b) * kG;
        float r = 1.f / (1.f + expf(-(gx[j] + ghr)));
        float z = 1.f / (1.f + expf(-(gx[kH + j] + ghz)));
        float n = tanhf(gx[2 * kH + j] + r * ghn);
        float hold = hread[(size_t)b * kH + j];
        float h2 = (1.f - z) * n + z * hold;
        hwrite[(size_t)b * kH + j] = h2;
        g_enc[((size_t)b * kS + gpos) * (2 * kH) + dir * kH + j] = h2;
    }
}

// ---------------------------------------------------------------------------
// Small-M GEMM body (FFMA2)
// ---------------------------------------------------------------------------
__device__ __forceinline__
void gemm64_body(const float* __restrict__ A, int lda,
                 const float* __restrict__ Bm, int ldb,
                 const float* __restrict__ bias,
                 float* __restrict__ C, int ldc,
                 int K, int act, int nb) {
    constexpr int BK = 32;
    __shared__ __align__(16) float As[BK][64];
    __shared__ __align__(16) float Bs[BK][64];
    const int tid = threadIdx.x;
    const int bn = nb * 64;
    const int lr = tid >> 3;
    const int lc = (tid & 7) << 2;
    const int tm = (tid >> 4) << 2;
    const int tn = (tid & 15) << 2;

    unsigned long long acc[4][2];
#pragma unroll
    for (int i = 0; i < 4; i++) { acc[i][0] = 0ull; acc[i][1] = 0ull; }

    for (int k0 = 0; k0 < K; k0 += BK) {
#pragma unroll
        for (int h = 0; h < 2; h++) {
            int r = lr + h * 32;
            float4 v = *(const float4*)(A + (size_t)r * lda + k0 + lc);
            As[lc + 0][r] = v.x; As[lc + 1][r] = v.y;
            As[lc + 2][r] = v.z; As[lc + 3][r] = v.w;
            float4 w = *(const float4*)(Bm + (size_t)(bn + r) * ldb + k0 + lc);
            Bs[lc + 0][r] = w.x; Bs[lc + 1][r] = w.y;
            Bs[lc + 2][r] = w.z; Bs[lc + 3][r] = w.w;
        }
        __syncthreads();
#pragma unroll
        for (int k = 0; k < BK; k++) {
            float4 af = *(const float4*)&As[k][tm];
            unsigned long long aa[4];
            aa[0] = pk2(af.x); aa[1] = pk2(af.y);
            aa[2] = pk2(af.z); aa[3] = pk2(af.w);
            ulonglong2 bv = *(const ulonglong2*)&Bs[k][tn];
#pragma unroll
            for (int i = 0; i < 4; i++) {
                fma2(acc[i][0], aa[i], bv.x);
                fma2(acc[i][1], aa[i], bv.y);
            }
        }
        __syncthreads();
    }
#pragma unroll
    for (int i = 0; i < 4; i++) {
        int col = bn + tn;
        float4 v;
        v.x = lo2(acc[i][0]); v.y = hi2(acc[i][0]);
        v.z = lo2(acc[i][1]); v.w = hi2(acc[i][1]);
        if (bias) {
            v.x += bias[col + 0]; v.y += bias[col + 1];
            v.z += bias[col + 2]; v.w += bias[col + 3];
        }
        if (act == 1) {
            v.x = tanhf(v.x); v.y = tanhf(v.y);
            v.z = tanhf(v.z); v.w = tanhf(v.w);
        }
        *(float4*)(C + (size_t)(tm + i) * ldc + col) = v;
    }
}

__global__ __launch_bounds__(256)
void gemm64(const float* __restrict__ A, int lda,
            const float* __restrict__ Bm, int ldb,
            const float* __restrict__ bias,
            float* __restrict__ C, int ldc, int K, int act) {
    gemm64_body(A, lda, Bm, ldb, bias, C, ldc, K, act, blockIdx.x);
}

// Decoder pre-attention GEMMs, K-split 2: hp (32 blocks) + ghd (96 blocks)
__global__ __launch_bounds__(256)
void dec_pre_gemm(const float* __restrict__ W_attn,
                  const float* __restrict__ Wh_d,
                  const float* __restrict__ bh_d) {
    int x = blockIdx.x;
    if (x < 32) {
        int ks = x >> 4, nb = x & 15;
        gemm64_body(g_hdec + ks * 512, kH, W_attn + ks * 512, kG, nullptr,
                    g_hp + (size_t)ks * kB * kH, kH, 512, 0, nb);
    } else {
        int i = x - 32;
        int ks = i / 48, nb = i % 48;
        gemm64_body(g_hdec + ks * 512, kH, Wh_d + ks * 512, kH,
                    ks == 0 ? bh_d : nullptr,
                    g_ghd + (size_t)ks * kB * kG, kG, 512, 0, nb);
    }
}

// ---------------------------------------------------------------------------
__global__ void hcat_kernel() {
    int idx = blockIdx.x * blockDim.x + threadIdx.x;
    if (idx >= 2 * kB * kH) return;
    int dir = idx / (kB * kH);
    int rem = idx - dir * (kB * kH);
    int b = rem / kH, j = rem - b * kH;
    g_hcat[(size_t)b * 2 * kH + dir * kH + j] = g_h[0][idx];
}

// ---------------------------------------------------------------------------
// Fully fused decoder step (round-9 proven: one CTA per batch, 512 threads)
// ---------------------------------------------------------------------------
__global__ __launch_bounds__(512)
void attn_step_fused(const int* __restrict__ src,
                     const float* __restrict__ v_attn,
                     const float* __restrict__ gxet_t,
                     float* __restrict__ feat_t) {
    int b = blockIdx.x;
    __shared__ float sc[kS];
    __shared__ float sgxw[kG];
    int tid = threadIdx.x, warp = tid >> 5, lane = tid & 31;
    const float* hp0 = g_hp + (size_t)b * kH;
    const float* hp1 = g_hp + (size_t)kB * kH + (size_t)b * kH;

    for (int s = warp; s < kS; s += 16) {
        const float* ep = g_encproj + ((size_t)b * kS + s) * kH;
        float p = 0.f;
        for (int j = lane; j < kH; j += 32)
            p += v_attn[j] * tanhf(hp0[j] + hp1[j] + ep[j]);
#pragma unroll
        for (int o = 16; o; o >>= 1) p += __shfl_xor_sync(0xffffffffu, p, o);
        if (lane == 0) sc[s] = (src[s * kB + b] != kPAD) ? p : -1e10f;
    }
    __syncthreads();

    if (tid < 32) {
        float v1 = sc[tid];
        float v2 = (tid + 32 < kS) ? sc[tid + 32] : -1e30f;
        float mx = fmaxf(v1, v2);
#pragma unroll
        for (int o = 16; o; o >>= 1) mx = fmaxf(mx, __shfl_xor_sync(0xffffffffu, mx, o));
        float e1 = expf(v1 - mx);
        float e2 = (tid + 32 < kS) ? expf(v2 - mx) : 0.f;
        float sm = e1 + e2;
#pragma unroll
        for (int o = 16; o; o >>= 1) sm += __shfl_xor_sync(0xffffffffu, sm, o);
        float inv = 1.f / sm;
        sc[tid] = e1 * inv;
        if (tid + 32 < kS) sc[tid + 32] = e2 * inv;
    }
    __syncthreads();

    for (int c4 = tid; c4 < 2 * kH / 4; c4 += 512) {
        float4 acc = make_float4(0.f, 0.f, 0.f, 0.f);
        const float4* base = (const float4*)(g_enc + (size_t)b * kS * 2 * kH) + c4;
#pragma unroll 8
        for (int s = 0; s < kS; s++) {
            float a = sc[s];
            float4 e = base[s * (2 * kH / 4)];
            acc.x += a * e.x; acc.y += a * e.y;
            acc.z += a * e.z; acc.w += a * e.w;
        }
        ((float4*)(feat_t + (size_t)b * kF + kH))[c4] = acc;
    }
    for (int c4 = tid; c4 < kG / 4; c4 += 512) {
        float4 acc = make_float4(0.f, 0.f, 0.f, 0.f);
        const float4* base = (const float4*)(g_encWi + (size_t)b * kS * kG) + c4;
#pragma unroll 8
        for (int s = 0; s < kS; s++) {
            float a = sc[s];
            float4 e = base[s * (kG / 4)];
            acc.x += a * e.x; acc.y += a * e.y;
            acc.z += a * e.z; acc.w += a * e.w;
        }
        *(float4*)(sgxw + c4 * 4) = acc;
    }
    __syncthreads();

    const float* q0 = g_ghd + (size_t)b * kG;
    const float* q1 = g_ghd + (size_t)kB * kG + (size_t)b * kG;
    const float* gx = gxet_t + (size_t)b * kG;
    for (int j = tid; j < kH; j += 512) {
        float h = g_hdec[(size_t)b * kH + j];
        float xr = gx[j] + sgxw[j];
        float xz = gx[kH + j] + sgxw[kH + j];
        float xn = gx[2 * kH + j] + sgxw[2 * kH + j];
        float ghr = q0[j] + q1[j];
        float ghz = q0[kH + j] + q1[kH + j];
        float ghn = q0[2 * kH + j] + q1[2 * kH + j];
        float r = 1.f / (1.f + expf(-(xr + ghr)));
        float z = 1.f / (1.f + expf(-(xz + ghz)));
        float n = tanhf(xn + r * ghn);
        float h2 = (1.f - z) * n + z * h;
        g_hdec[(size_t)b * kH + j] = h2;
        feat_t[(size_t)b * kF + j] = h2;
    }
}

// ---------------------------------------------------------------------------
// Host orchestration (two-stream fork/join, graph-capturable)
// ---------------------------------------------------------------------------
extern "C" void kernel_launch(void* const* d_in, const int* in_sizes, int n_in,
                              void* d_out, int out_size) {
    const int*   src     = (const int*)d_in[0];
    const int*   trg     = (const int*)d_in[1];
    const float* emb_enc = (const float*)d_in[2];
    const float* Wi_f    = (const float*)d_in[3];
    const float* Wh_f    = (const float*)d_in[4];
    const float* bi_f    = (const float*)d_in[5];
    const float* bh_f    = (const float*)d_in[6];
    const float* Wi_b    = (const float*)d_in[7];
    const float* Wh_b    = (const float*)d_in[8];
    const float* bi_b    = (const float*)d_in[9];
    const float* bh_b    = (const float*)d_in[10];
    const float* W_fc    = (const float*)d_in[11];
    const float* b_fc    = (const float*)d_in[12];
    const float* W_attn  = (const float*)d_in[13];
    const float* b_attn  = (const float*)d_in[14];
    const float* v_attn  = (const float*)d_in[15];
    const float* emb_dec = (const float*)d_in[16];
    const float* Wi_d    = (const float*)d_in[17];
    const float* Wh_d    = (const float*)d_in[18];
    const float* bi_d    = (const float*)d_in[19];
    const float* bh_d    = (const float*)d_in[20];
    const float* W_out   = (const float*)d_in[21];
    const float* b_out   = (const float*)d_in[22];
    float* out = (float*)d_out;

    float *p_enc, *p_ep, *p_encWi, *p_hcat, *p_hdec, *p_gxet, *p_feat,
          *p_gxf, *p_gxb;
    __nv_bfloat16 *p_Ahi, *p_Alo, *p_Ehi, *p_Elo;
    __nv_bfloat16 *p_Wifh, *p_Wifl, *p_Wibh, *p_Wibl;
    __nv_bfloat16 *p_Widh, *p_Widl, *p_Wah, *p_Wal, *p_Ench, *p_Encl;
    __half *p_Fhi, *p_Flo, *p_Bf16;
    cudaGetSymbolAddress((void**)&p_enc, g_enc);
    cudaGetSymbolAddress((void**)&p_ep, g_encproj);
    cudaGetSymbolAddress((void**)&p_encWi, g_encWi);
    cudaGetSymbolAddress((void**)&p_hcat, g_hcat);
    cudaGetSymbolAddress((void**)&p_hdec, g_hdec);
    cudaGetSymbolAddress((void**)&p_gxet, g_gxet);
    cudaGetSymbolAddress((void**)&p_feat, g_feat);
    cudaGetSymbolAddress((void**)&p_gxf, g_gxf);
    cudaGetSymbolAddress((void**)&p_gxb, g_gxb);
    cudaGetSymbolAddress((void**)&p_Ahi, g_Ahi);
    cudaGetSymbolAddress((void**)&p_Alo, g_Alo);
    cudaGetSymbolAddress((void**)&p_Ehi, g_Ehi);
    cudaGetSymbolAddress((void**)&p_Elo, g_Elo);
    cudaGetSymbolAddress((void**)&p_Wifh, g_Wifh);
    cudaGetSymbolAddress((void**)&p_Wifl, g_Wifl);
    cudaGetSymbolAddress((void**)&p_Wibh, g_Wibh);
    cudaGetSymbolAddress((void**)&p_Wibl, g_Wibl);
    cudaGetSymbolAddress((void**)&p_Widh, g_Widh);
    cudaGetSymbolAddress((void**)&p_Widl, g_Widl);
    cudaGetSymbolAddress((void**)&p_Wah, g_Wah);
    cudaGetSymbolAddress((void**)&p_Wal, g_Wal);
    cudaGetSymbolAddress((void**)&p_Ench, g_Ench);
    cudaGetSymbolAddress((void**)&p_Encl, g_Encl);
    cudaGetSymbolAddress((void**)&p_Fhi, g_Fhi);
    cudaGetSymbolAddress((void**)&p_Flo, g_Flo);
    cudaGetSymbolAddress((void**)&p_Bf16, g_Bf16);

    static cudaStream_t s1 = nullptr;
    static cudaEvent_t evFork = nullptr, evJoin = nullptr;
    if (s1 == nullptr) {
        cudaStreamCreateWithFlags(&s1, cudaStreamNonBlocking);
        cudaEventCreateWithFlags(&evFork, cudaEventDisableTiming);
        cudaEventCreateWithFlags(&evJoin, cudaEventDisableTiming);
        cudaFuncSetAttribute(hgemm,
                             cudaFuncAttributeMaxDynamicSharedMemorySize,
                             outg::SMEM_SZ);
        cudaFuncSetAttribute(hgemm2,
                             cudaFuncAttributeMaxDynamicSharedMemorySize,
                             outh::SMEM_SZ);
    }

    // fork side stream off the capture stream
    cudaEventRecord(evFork, 0);
    cudaStreamWaitEvent(s1, evFork, 0);

    // --- main stream: encoder-critical path ---
    init_kernel<<<((size_t)kB * kV + 255) / 256, 256>>>(out);
    enc_embed_kernel<<<kME, 128>>>(src, emb_enc);
    {
        size_t n4 = (size_t)kG * kE / 4;
        cvt_split4<<<(unsigned)((n4 + 255) / 256), 256>>>(
            (const float4*)Wi_f, (__nv_bfloat162*)p_Wifh,
            (__nv_bfloat162*)p_Wifl, n4);
        cvt_split4<<<(unsigned)((n4 + 255) / 256), 256>>>(
            (const float4*)Wi_b, (__nv_bfloat162*)p_Wibh,
            (__nv_bfloat162*)p_Wibl, n4);
    }
    // --- side stream: decoder-prep + big weight conversions ---
    dec_embed_all<<<kMR, 128, 0, s1>>>(trg, emb_dec);
    // --- main: input-gate GEMMs ---
    hgemm<<<dim3(kME / 128, kG / 128), 256, outg::SMEM_SZ>>>(
        p_Ehi, p_Elo, kE, p_Wifh, p_Wifl, kE, bi_f, p_gxf, kG, kME, kE);
    hgemm<<<dim3(kME / 128, kG / 128), 256, outg::SMEM_SZ>>>(
        p_Ehi, p_Elo, kE, p_Wibh, p_Wibl, kE, bi_b, p_gxb, kG, kME, kE);
    // --- side stream continues ---
    {
        size_t n4 = (size_t)kG * kXW / 4;
        cvt_split4<<<(unsigned)((n4 + 255) / 256), 256, 0, s1>>>(
            (const float4*)Wi_d, (__nv_bfloat162*)p_Widh,
            (__nv_bfloat162*)p_Widl, n4);
        n4 = (size_t)kH * kG / 4;
        cvt_split4<<<(unsigned)((n4 + 255) / 256), 256, 0, s1>>>(
            (const float4*)W_attn, (__nv_bfloat162*)p_Wah,
            (__nv_bfloat162*)p_Wal, n4);
        hgemm<<<dim3(kMP / 128, kG / 128), 256, outg::SMEM_SZ, s1>>>(
            p_Ahi + 3 * kH, p_Alo + 3 * kH, kF, p_Widh, p_Widl, kXW, bi_d,
            p_gxet, kG, kMR, kE);
        // W_out -> single fp16 (2-pass final GEMM needs only one array)
        n4 = (size_t)kV * kF / 4;
        cvt16_4<<<(unsigned)((n4 + 255) / 256), 256, 0, s1>>>(
            (const float4*)W_out, (__half2*)p_Bf16, n4);
    }
    cudaEventRecord(evJoin, s1);

    // --- main: encoder recurrence (overlaps side stream) ---
    for (int s = 0; s < kS; s++)
        enc_step_fused<<<dim3(64, 2), 256>>>(s, Wh_f, Wh_b, bh_f, bh_b);

    // decoder init hidden
    hcat_kernel<<<(2 * kB * kH) / 256, 256>>>();
    gemm64<<<kH / 64, 256>>>(p_hcat, 2 * kH, W_fc, 2 * kH, b_fc,
                             p_hdec, kH, 2 * kH, 1);

    // encoder split + attention projection + encWi (needs side stream)
    {
        size_t n4 = (size_t)kME * 2 * kH / 4;
        cvt_split4<<<(unsigned)((n4 + 255) / 256), 256>>>(
            (const float4*)p_enc, (__nv_bfloat162*)p_Ench,
            (__nv_bfloat162*)p_Encl, n4);
        cudaStreamWaitEvent(0, evJoin, 0);
        hgemm<<<dim3(kME / 128, kH / 128), 256, outg::SMEM_SZ>>>(
            p_Ench, p_Encl, 2 * kH, p_Wah + kH, p_Wal + kH, kG, b_attn,
            p_ep, kH, kME, 2 * kH);
        hgemm<<<dim3(kME / 128, kG / 128), 256, outg::SMEM_SZ>>>(
            p_Ench, p_Encl, 2 * kH, p_Widh + kE, p_Widl + kE, kXW,
            (const float*)nullptr, p_encWi, kG, kME, 2 * kH);
    }

    // decoder loop: 2 launches per step (round-9 proven schedule)
    for (int t = 0; t < kT - 1; t++) {
        float* feat_t = p_feat + (size_t)t * kB * kF;
        dec_pre_gemm<<<128, 256>>>(W_attn, Wh_d, bh_d);
        attn_step_fused<<<kB, 512>>>(src, v_attn,
                                     p_gxet + (size_t)t * kB * kG, feat_t);
    }

    // fp16-convert features, 2-pass fp16 output projection
    {
        size_t n = (size_t)kMP * kF / 4;
        cvt_feat16<<<(unsigned)((n + 255) / 256), 256>>>();
        hgemm2<<<dim3(kMP / 128, kV / 128), 256, outh::SMEM_SZ>>>(
            p_Fhi, p_Flo, kF, p_Bf16, kF, b_out,
            out + (size_t)kB * kV, kV, kMR, kF);
    }
}

// round 15
// speedup vs baseline: 1.3214x; 1.1548x over previous
#include <cuda_runtime.h>
#include <cuda_bf16.h>
#include <cuda_fp16.h>
#include <math.h>
#include <stdint.h>

// ---------------------------------------------------------------------------
// Problem constants
// ---------------------------------------------------------------------------
namespace {
constexpr int kS = 48;          // source length
constexpr int kT = 32;          // target length
constexpr int kB = 64;          // batch
constexpr int kH = 1024;        // hidden
constexpr int kE = 512;         // embed
constexpr int kV = 32000;       // vocab
constexpr int kG = 3 * kH;      // 3072 gates
constexpr int kF = 3 * kH + kE; // 3584 out-proj features
constexpr int kXW = kE + 2*kH;  // 2560 decoder GRU input width
constexpr int kPAD = 1;
constexpr int kMR = (kT - 1) * kB; // 1984 output rows
constexpr int kMP = 2048;          // padded rows for tensor GEMM
constexpr int kME = kS * kB;       // 3072 encoder rows
}

// ---------------------------------------------------------------------------
// Packed fp32x2 helpers (FFMA2)
// ---------------------------------------------------------------------------
__device__ __forceinline__ unsigned long long pk2(float x) {
    unsigned long long r;
    unsigned u = __float_as_uint(x);
    asm("mov.b64 %0, {%1, %1};" : "=l"(r) : "r"(u));
    return r;
}
__device__ __forceinline__ void fma2(unsigned long long& d,
                                     unsigned long long a,
                                     unsigned long long b) {
    asm("fma.rn.f32x2 %0, %1, %2, %0;" : "+l"(d) : "l"(a), "l"(b));
}
__device__ __forceinline__ float lo2(unsigned long long v) {
    return __uint_as_float((unsigned)v);
}
__device__ __forceinline__ float hi2(unsigned long long v) {
    return __uint_as_float((unsigned)(v >> 32));
}

// ---------------------------------------------------------------------------
// Plain-PTX helpers: cp.async / ldmatrix / mma.sync
// ---------------------------------------------------------------------------
__device__ __forceinline__ uint32_t smem_u32(const void* p) {
    uint32_t a;
    asm("{ .reg .u64 t; cvta.to.shared.u64 t, %1; cvt.u32.u64 %0, t; }"
        : "=r"(a) : "l"(p));
    return a;
}
#define CP_ASYNC16(dst, src) \
    asm volatile("cp.async.cg.shared.global [%0], [%1], 16;" \
                 :: "r"(dst), "l"(src) : "memory")
#define CP_COMMIT() asm volatile("cp.async.commit_group;" ::: "memory")
#define CP_WAIT1()  asm volatile("cp.async.wait_group 1;" ::: "memory")
#define CP_WAIT0()  asm volatile("cp.async.wait_group 0;" ::: "memory")

__device__ __forceinline__ void ldsm4(uint32_t* r, uint32_t addr) {
    asm volatile("ldmatrix.sync.aligned.m8n8.x4.shared.b16 {%0,%1,%2,%3}, [%4];"
                 : "=r"(r[0]), "=r"(r[1]), "=r"(r[2]), "=r"(r[3])
                 : "r"(addr));
}
__device__ __forceinline__ void mma16816(float* d, const uint32_t* a,
                                         const uint32_t* b) {
    asm volatile(
        "mma.sync.aligned.m16n8k16.row.col.f32.bf16.bf16.f32 "
        "{%0,%1,%2,%3}, {%4,%5,%6,%7}, {%8,%9}, {%0,%1,%2,%3};"
        : "+f"(d[0]), "+f"(d[1]), "+f"(d[2]), "+f"(d[3])
        : "r"(a[0]), "r"(a[1]), "r"(a[2]), "r"(a[3]),
          "r"(b[0]), "r"(b[1]));
}
__device__ __forceinline__ void mma16816h(float* d, const uint32_t* a,
                                          const uint32_t* b) {
    asm volatile(
        "mma.sync.aligned.m16n8k16.row.col.f32.f16.f16.f32 "
        "{%0,%1,%2,%3}, {%4,%5,%6,%7}, {%8,%9}, {%0,%1,%2,%3};"
        : "+f"(d[0]), "+f"(d[1]), "+f"(d[2]), "+f"(d[3])
        : "r"(a[0]), "r"(a[1]), "r"(a[2]), "r"(a[3]),
          "r"(b[0]), "r"(b[1]));
}

// ---------------------------------------------------------------------------
// Persistent scratch
// ---------------------------------------------------------------------------
__device__ float g_emb[(size_t)kME * kE];
__device__ float g_gxf[(size_t)kME * kG];
__device__ float g_gxb[(size_t)kME * kG];
__device__ float g_enc[(size_t)kME * 2 * kH];      // [b][s][2H]
__device__ float g_encproj[(size_t)kME * kH];
__device__ float g_encWi[(size_t)kME * kG];        // enc @ Wi_d[:,E:]^T
__device__ float g_h[2][2 * kB * kH];              // double-buffered h_f|h_b
__device__ float g_hcat[kB * 2 * kH];
__device__ float g_hdec[kB * kH];
__device__ float g_hp[2 * kB * kH];                // 2 K-partials
__device__ float g_ghd[2 * kB * kG];               // 2 K-partials
__device__ float g_gxet[(size_t)kMR * kG];
__device__ float g_feat[(size_t)kMR * kF];         // [h2, w, et] per step
// bf16 split operands for bf16x3 HMMA GEMMs
__device__ __nv_bfloat16 g_Ahi[(size_t)kMP * kF];  // decoder et cols
__device__ __nv_bfloat16 g_Alo[(size_t)kMP * kF];
__device__ __nv_bfloat16 g_Ehi[(size_t)kME * kE];  // encoder embeddings
__device__ __nv_bfloat16 g_Elo[(size_t)kME * kE];
__device__ __nv_bfloat16 g_Wifh[(size_t)kG * kE];  // Wi_f
__device__ __nv_bfloat16 g_Wifl[(size_t)kG * kE];
__device__ __nv_bfloat16 g_Wibh[(size_t)kG * kE];  // Wi_b
__device__ __nv_bfloat16 g_Wibl[(size_t)kG * kE];
__device__ __nv_bfloat16 g_Widh[(size_t)kG * kXW]; // Wi_d (full)
__device__ __nv_bfloat16 g_Widl[(size_t)kG * kXW];
__device__ __nv_bfloat16 g_Wah[(size_t)kH * kG];   // W_attn (full)
__device__ __nv_bfloat16 g_Wal[(size_t)kH * kG];
__device__ __nv_bfloat16 g_Ench[(size_t)kME * 2 * kH];
__device__ __nv_bfloat16 g_Encl[(size_t)kME * 2 * kH];
// fp16 operands for the 2-pass final GEMM (A split, B single)
__device__ __half g_Fhi[(size_t)kMP * kF];         // feat hi
__device__ __half g_Flo[(size_t)kMP * kF];         // feat lo
__device__ __half g_Bf16[(size_t)kV * kF];         // W_out fp16
// fp16 read-copies for the decoder-loop streamed operands
__device__ __half g_encWi16[(size_t)kME * kG];
__device__ __half g_enc16[(size_t)kME * 2 * kH];
__device__ __half g_ep16[(size_t)kME * kH];

// ---------------------------------------------------------------------------
__global__ void init_kernel(float* __restrict__ out0) {
    size_t i = (size_t)blockIdx.x * blockDim.x + threadIdx.x;
    if (i < (size_t)kB * kV) out0[i] = 0.f;
    if (i < (size_t)2 * kB * kH) g_h[0][i] = 0.f;
}

// encoder embedding gather + bf16 split emit
__global__ void enc_embed_kernel(const int* __restrict__ src,
                                 const float* __restrict__ table) {
    int row = blockIdx.x;
    int tok = src[row];
    float4 v = ((const float4*)(table + (size_t)tok * kE))[threadIdx.x];
    ((float4*)(g_emb + (size_t)row * kE))[threadIdx.x] = v;
    size_t o = (size_t)row * kE + threadIdx.x * 4;
    float vv[4] = { v.x, v.y, v.z, v.w };
#pragma unroll
    for (int q = 0; q < 4; q++) {
        __nv_bfloat16 h = __float2bfloat16(vv[q]);
        g_Ehi[o + q] = h;
        g_Elo[o + q] = __float2bfloat16(vv[q] - __bfloat162float(h));
    }
}

// decoder embeddings -> feat float + bf16 split into g_Ahi/g_Alo et columns
__global__ void dec_embed_all(const int* __restrict__ trg,
                              const float* __restrict__ emb_dec) {
    int row = blockIdx.x;
    int tok = trg[row];
    float4 v = ((const float4*)(emb_dec + (size_t)tok * kE))[threadIdx.x];
    ((float4*)(g_feat + (size_t)row * kF + 3 * kH))[threadIdx.x] = v;
    size_t o = (size_t)row * kF + 3 * kH + threadIdx.x * 4;
    float vv[4] = { v.x, v.y, v.z, v.w };
#pragma unroll
    for (int q = 0; q < 4; q++) {
        __nv_bfloat16 h = __float2bfloat16(vv[q]);
        g_Ahi[o + q] = h;
        g_Alo[o + q] = __float2bfloat16(vv[q] - __bfloat162float(h));
    }
}

// ---------------------------------------------------------------------------
// bf16 split conversion (4 elements/thread, fully vectorized)
// ---------------------------------------------------------------------------
__global__ void cvt_split4(const float4* __restrict__ src,
                           __nv_bfloat162* __restrict__ hi,
                           __nv_bfloat162* __restrict__ lo, size_t n4) {
    size_t i = (size_t)blockIdx.x * blockDim.x + threadIdx.x;
    if (i >= n4) return;
    float4 v = src[i];
    __nv_bfloat16 h0 = __float2bfloat16(v.x);
    __nv_bfloat16 h1 = __float2bfloat16(v.y);
    __nv_bfloat16 h2 = __float2bfloat16(v.z);
    __nv_bfloat16 h3 = __float2bfloat16(v.w);
    hi[2 * i]     = __nv_bfloat162(h0, h1);
    hi[2 * i + 1] = __nv_bfloat162(h2, h3);
    lo[2 * i]     = __nv_bfloat162(
        __float2bfloat16(v.x - __bfloat162float(h0)),
        __float2bfloat16(v.y - __bfloat162float(h1)));
    lo[2 * i + 1] = __nv_bfloat162(
        __float2bfloat16(v.z - __bfloat162float(h2)),
        __float2bfloat16(v.w - __bfloat162float(h3)));
}

// fp32 -> single fp16 conversion (4 elements/thread)
__global__ void cvt16_4(const float4* __restrict__ src,
                        __half2* __restrict__ dst, size_t n4) {
    size_t i = (size_t)blockIdx.x * blockDim.x + threadIdx.x;
    if (i >= n4) return;
    float4 v = src[i];
    dst[2 * i]     = __floats2half2_rn(v.x, v.y);
    dst[2 * i + 1] = __floats2half2_rn(v.z, v.w);
}

// convert ALL feat columns to fp16 hi/lo for the 2-pass final GEMM
__global__ void cvt_feat16() {
    size_t i = (size_t)blockIdx.x * blockDim.x + threadIdx.x;
    if (i >= (size_t)kMP * kF / 4) return;
    size_t row = i / (kF / 4);
    size_t col = (i % (kF / 4)) * 4;
    float4 v = make_float4(0.f, 0.f, 0.f, 0.f);
    if (row < (size_t)kMR)
        v = *(const float4*)(g_feat + row * kF + col);
    size_t o = row * kF + col;
    float vv[4] = { v.x, v.y, v.z, v.w };
#pragma unroll
    for (int q = 0; q < 4; q++) {
        __half h = __float2half_rn(vv[q]);
        g_Fhi[o + q] = h;
        g_Flo[o + q] = __float2half_rn(vv[q] - __half2float(h));
    }
}

// ---------------------------------------------------------------------------
// Generalized bf16x3 HMMA GEMM (round-9 proven config)
// ---------------------------------------------------------------------------
namespace outg {
constexpr int BM = 128, BN = 128, BK = 64;
constexpr int HALF = 16384;
constexpr int STAGE = 4 * HALF;
constexpr int SMEM_SZ = 2 * STAGE;          // 131072
}

__device__ __forceinline__ void hg_prefetch(
    const __nv_bfloat16* __restrict__ Ah, const __nv_bfloat16* __restrict__ Al,
    int lda,
    const __nv_bfloat16* __restrict__ Bh, const __nv_bfloat16* __restrict__ Bl,
    int ldb, int k0, uint32_t buf, int tid, int m0, int n0) {
    using namespace outg;
#pragma unroll
    for (int i = 0; i < 4; i++) {
        int id = tid + i * 256;
        int row = id >> 3, c = id & 7;
        uint32_t off = (uint32_t)(row << 7) + (c << 4);
        uint32_t sw = off ^ ((off >> 3) & 0x70);
        size_t ga = (size_t)(m0 + row) * lda + k0 + c * 8;
        size_t gb = (size_t)(n0 + row) * ldb + k0 + c * 8;
        CP_ASYNC16(buf + sw, Ah + ga);
        CP_ASYNC16(buf + HALF + sw, Al + ga);
        CP_ASYNC16(buf + 2 * HALF + sw, Bh + gb);
        CP_ASYNC16(buf + 3 * HALF + sw, Bl + gb);
    }
}

__device__ __forceinline__ void hg_compute(uint32_t buf, int lane,
                                           int wm, int wn,
                                           float acc[2][8][4]) {
    using namespace outg;
    const int g = lane >> 3, r = lane & 7;
#pragma unroll
    for (int ks = 0; ks < 4; ks++) {
        uint32_t ahi[2][4], alo[2][4];
#pragma unroll
        for (int mi = 0; mi < 2; mi++) {
            int row = wm + mi * 16 + ((g & 1) << 3) + r;
            int chunk = ks * 2 + (g >> 1);
            uint32_t off = (uint32_t)(row << 7) + (chunk << 4);
            uint32_t sw = off ^ ((off >> 3) & 0x70);
            ldsm4(ahi[mi], buf + sw);
            ldsm4(alo[mi], buf + HALF + sw);
        }
        uint32_t bhi[4][4], blo[4][4];
#pragma unroll
        for (int np = 0; np < 4; np++) {
            int row = wn + np * 16 + ((g >> 1) << 3) + r;
            int chunk = ks * 2 + (g & 1);
            uint32_t off = (uint32_t)(row << 7) + (chunk << 4);
            uint32_t sw = off ^ ((off >> 3) & 0x70);
            ldsm4(bhi[np], buf + 2 * HALF + sw);
            ldsm4(blo[np], buf + 3 * HALF + sw);
        }
#pragma unroll
        for (int mi = 0; mi < 2; mi++) {
#pragma unroll
            for (int np = 0; np < 4; np++) {
#pragma unroll
                for (int a = 0; a < 2; a++) {
                    uint32_t bh[2] = { bhi[np][2 * a], bhi[np][2 * a + 1] };
                    uint32_t bl[2] = { blo[np][2 * a], blo[np][2 * a + 1] };
                    float* d = acc[mi][np * 2 + a];
                    mma16816(d, ahi[mi], bh);
                    mma16816(d, ahi[mi], bl);
                    mma16816(d, alo[mi], bh);
                }
            }
        }
    }
}

__global__ __launch_bounds__(256, 1)
void hgemm(const __nv_bfloat16* __restrict__ Ah,
           const __nv_bfloat16* __restrict__ Al, int lda,
           const __nv_bfloat16* __restrict__ Bh,
           const __nv_bfloat16* __restrict__ Bl, int ldb,
           const float* __restrict__ bias, float* __restrict__ C, int ldc,
           int M, int K) {
    using namespace outg;
    extern __shared__ char smem[];
    const uint32_t sb = smem_u32(smem);
    const int tid = threadIdx.x;
    const int wid = tid >> 5, lane = tid & 31;
    const int m0 = blockIdx.x * BM;
    const int n0 = blockIdx.y * BN;
    const int wm = (wid & 3) * 32;
    const int wn = (wid >> 2) * 64;
    const int nslab = K / BK;

    float acc[2][8][4];
#pragma unroll
    for (int i = 0; i < 2; i++)
#pragma unroll
        for (int j = 0; j < 8; j++)
#pragma unroll
            for (int q = 0; q < 4; q++) acc[i][j][q] = 0.f;

    hg_prefetch(Ah, Al, lda, Bh, Bl, ldb, 0, sb, tid, m0, n0);
    CP_COMMIT();
    hg_prefetch(Ah, Al, lda, Bh, Bl, ldb, BK, sb + STAGE, tid, m0, n0);
    CP_COMMIT();

    for (int s = 0; s < nslab; s++) {
        const int st = s & 1;
        if (s == nslab - 1) { CP_WAIT0(); } else { CP_WAIT1(); }
        __syncthreads();
        hg_compute(sb + st * STAGE, lane, wm, wn, acc);
        __syncthreads();
        if (s + 2 < nslab) {
            hg_prefetch(Ah, Al, lda, Bh, Bl, ldb, (s + 2) * BK,
                        sb + st * STAGE, tid, m0, n0);
            CP_COMMIT();
        }
    }

    const int r0 = m0 + wm + (lane >> 2);
    const int c0 = n0 + wn + (lane & 3) * 2;
#pragma unroll
    for (int mi = 0; mi < 2; mi++) {
#pragma unroll
        for (int ni = 0; ni < 8; ni++) {
            int row = r0 + mi * 16;
            int col = c0 + ni * 8;
            const float* d = acc[mi][ni];
            float b0 = bias ? bias[col] : 0.f;
            float b1 = bias ? bias[col + 1] : 0.f;
            if (row < M) {
                C[(size_t)row * ldc + col]     = d[0] + b0;
                C[(size_t)row * ldc + col + 1] = d[1] + b1;
            }
            if (row + 8 < M) {
                C[(size_t)(row + 8) * ldc + col]     = d[2] + b0;
                C[(size_t)(row + 8) * ldc + col + 1] = d[3] + b1;
            }
        }
    }
}

// ---------------------------------------------------------------------------
// 2-pass fp16 HMMA GEMM for the final projection
// ---------------------------------------------------------------------------
namespace outh {
constexpr int BM = 128, BN = 128, BK = 64;
constexpr int HALF = 16384;
constexpr int STAGE = 3 * HALF;             // 49152
constexpr int SMEM_SZ = 2 * STAGE;          // 98304
}

__device__ __forceinline__ void h2_prefetch(
    const __half* __restrict__ Ah, const __half* __restrict__ Al, int lda,
    const __half* __restrict__ Bm, int ldb,
    int k0, uint32_t buf, int tid, int m0, int n0) {
    using namespace outh;
#pragma unroll
    for (int i = 0; i < 4; i++) {
        int id = tid + i * 256;
        int row = id >> 3, c = id & 7;
        uint32_t off = (uint32_t)(row << 7) + (c << 4);
        uint32_t sw = off ^ ((off >> 3) & 0x70);
        size_t ga = (size_t)(m0 + row) * lda + k0 + c * 8;
        size_t gb = (size_t)(n0 + row) * ldb + k0 + c * 8;
        CP_ASYNC16(buf + sw, Ah + ga);
        CP_ASYNC16(buf + HALF + sw, Al + ga);
        CP_ASYNC16(buf + 2 * HALF + sw, Bm + gb);
    }
}

__device__ __forceinline__ void h2_compute(uint32_t buf, int lane,
                                           int wm, int wn,
                                           float acc[2][8][4]) {
    using namespace outh;
    const int g = lane >> 3, r = lane & 7;
#pragma unroll
    for (int ks = 0; ks < 4; ks++) {
        uint32_t ahi[2][4], alo[2][4];
#pragma unroll
        for (int mi = 0; mi < 2; mi++) {
            int row = wm + mi * 16 + ((g & 1) << 3) + r;
            int chunk = ks * 2 + (g >> 1);
            uint32_t off = (uint32_t)(row << 7) + (chunk << 4);
            uint32_t sw = off ^ ((off >> 3) & 0x70);
            ldsm4(ahi[mi], buf + sw);
            ldsm4(alo[mi], buf + HALF + sw);
        }
        uint32_t bfr[4][4];
#pragma unroll
        for (int np = 0; np < 4; np++) {
            int row = wn + np * 16 + ((g >> 1) << 3) + r;
            int chunk = ks * 2 + (g & 1);
            uint32_t off = (uint32_t)(row << 7) + (chunk << 4);
            uint32_t sw = off ^ ((off >> 3) & 0x70);
            ldsm4(bfr[np], buf + 2 * HALF + sw);
        }
#pragma unroll
        for (int mi = 0; mi < 2; mi++) {
#pragma unroll
            for (int np = 0; np < 4; np++) {
#pragma unroll
                for (int a = 0; a < 2; a++) {
                    uint32_t bh[2] = { bfr[np][2 * a], bfr[np][2 * a + 1] };
                    float* d = acc[mi][np * 2 + a];
                    mma16816h(d, ahi[mi], bh);
                    mma16816h(d, alo[mi], bh);
                }
            }
        }
    }
}

__global__ __launch_bounds__(256, 1)
void hgemm2(const __half* __restrict__ Ah, const __half* __restrict__ Al,
            int lda,
            const __half* __restrict__ Bm, int ldb,
            const float* __restrict__ bias, float* __restrict__ C, int ldc,
            int M, int K) {
    using namespace outh;
    extern __shared__ char smem[];
    const uint32_t sb = smem_u32(smem);
    const int tid = threadIdx.x;
    const int wid = tid >> 5, lane = tid & 31;
    const int m0 = blockIdx.x * BM;
    const int n0 = blockIdx.y * BN;
    const int wm = (wid & 3) * 32;
    const int wn = (wid >> 2) * 64;
    const int nslab = K / BK;

    float acc[2][8][4];
#pragma unroll
    for (int i = 0; i < 2; i++)
#pragma unroll
        for (int j = 0; j < 8; j++)
#pragma unroll
            for (int q = 0; q < 4; q++) acc[i][j][q] = 0.f;

    h2_prefetch(Ah, Al, lda, Bm, ldb, 0, sb, tid, m0, n0);
    CP_COMMIT();
    h2_prefetch(Ah, Al, lda, Bm, ldb, BK, sb + STAGE, tid, m0, n0);
    CP_COMMIT();

    for (int s = 0; s < nslab; s++) {
        const int st = s & 1;
        if (s == nslab - 1) { CP_WAIT0(); } else { CP_WAIT1(); }
        __syncthreads();
        h2_compute(sb + st * STAGE, lane, wm, wn, acc);
        __syncthreads();
        if (s + 2 < nslab) {
            h2_prefetch(Ah, Al, lda, Bm, ldb, (s + 2) * BK,
                        sb + st * STAGE, tid, m0, n0);
            CP_COMMIT();
        }
    }

    const int r0 = m0 + wm + (lane >> 2);
    const int c0 = n0 + wn + (lane & 3) * 2;
#pragma unroll
    for (int mi = 0; mi < 2; mi++) {
#pragma unroll
        for (int ni = 0; ni < 8; ni++) {
            int row = r0 + mi * 16;
            int col = c0 + ni * 8;
            const float* d = acc[mi][ni];
            float b0 = bias[col], b1 = bias[col + 1];
            if (row < M) {
                C[(size_t)row * ldc + col]     = d[0] + b0;
                C[(size_t)row * ldc + col + 1] = d[1] + b1;
            }
            if (row + 8 < M) {
                C[(size_t)(row + 8) * ldc + col]     = d[2] + b0;
                C[(size_t)(row + 8) * ldc + col + 1] = d[3] + b1;
            }
        }
    }
}

// ---------------------------------------------------------------------------
// Fused encoder recurrence step, k-lane packed FFMA2 inner loop.
// ---------------------------------------------------------------------------
__global__ __launch_bounds__(256)
void enc_step_fused(int s,
                    const float* __restrict__ Wh_f,
                    const float* __restrict__ Wh_b,
                    const float* __restrict__ bh_f,
                    const float* __restrict__ bh_b) {
    constexpr int BK = 32;
    constexpr int LDA = BK + 4;   // 36 floats = 144B rows (16B aligned)
    __shared__ __align__(16) float As[64][LDA];
    __shared__ __align__(16) float Bs[48][LDA];
    const int tid = threadIdx.x;
    const int dir = blockIdx.y;
    const int j0 = blockIdx.x * 16;
    const float* hread = g_h[s & 1] + dir * (kB * kH);
    float* hwrite = g_h[(s + 1) & 1] + dir * (kB * kH);
    const float* Wh = dir ? Wh_b : Wh_f;
    const float* bh = dir ? bh_b : bh_f;
    const float* gxbase = dir ? g_gxb : g_gxf;
    const int gpos = dir ? (kS - 1 - s) : s;

    const int tm = (tid >> 4) << 2;   // 0..60, 4 rows/thread
    const int tn = tid & 15;          // gate column within 16-wide tile

    unsigned long long acc[4][3];
#pragma unroll
    for (int i = 0; i < 4; i++)
#pragma unroll
        for (int q = 0; q < 3; q++) acc[i][q] = 0ull;

    for (int k0 = 0; k0 < kH; k0 += BK) {
#pragma unroll
        for (int h = 0; h < 2; h++) {
            int id = tid + h * 256;
            int r = id >> 3, cc = (id & 7) << 2;
            *(float4*)&As[r][cc] =
                *(const float4*)(hread + (size_t)r * kH + k0 + cc);
        }
#pragma unroll
        for (int h = 0; h < 2; h++) {
            int id = tid + h * 256;
            if (id < 384) {
                int r = id >> 3, cc = (id & 7) << 2;
                int sec = r >> 4, wi = r & 15;
                *(float4*)&Bs[r][cc] = *(const float4*)(Wh +
                    (size_t)(sec * kH + j0 + wi) * kH + k0 + cc);
            }
        }
        __syncthreads();
#pragma unroll
        for (int k = 0; k < BK; k += 2) {
            unsigned long long b0 = *(const unsigned long long*)&Bs[tn][k];
            unsigned long long b1 = *(const unsigned long long*)&Bs[16 + tn][k];
            unsigned long long b2 = *(const unsigned long long*)&Bs[32 + tn][k];
#pragma unroll
            for (int i = 0; i < 4; i++) {
                unsigned long long a =
                    *(const unsigned long long*)&As[tm + i][k];
                fma2(acc[i][0], a, b0);
                fma2(acc[i][1], a, b1);
                fma2(acc[i][2], a, b2);
            }
        }
        __syncthreads();
    }

    const int j = j0 + tn;
    const float bhr = bh[j], bhz = bh[kH + j], bhn = bh[2 * kH + j];
#pragma unroll
    for (int i = 0; i < 4; i++) {
        int b = tm + i;
        float ghr = lo2(acc[i][0]) + hi2(acc[i][0]) + bhr;
        float ghz = lo2(acc[i][1]) + hi2(acc[i][1]) + bhz;
        float ghn = lo2(acc[i][2]) + hi2(acc[i][2]) + bhn;
        const float* gx = gxbase + ((size_t)gpos * kB + b) * kG;
        float r = 1.f / (1.f + expf(-(gx[j] + ghr)));
        float z = 1.f / (1.f + expf(-(gx[kH + j] + ghz)));
        float n = tanhf(gx[2 * kH + j] + r * ghn);
        float hold = hread[(size_t)b * kH + j];
        float h2 = (1.f - z) * n + z * hold;
        hwrite[(size_t)b * kH + j] = h2;
        g_enc[((size_t)b * kS + gpos) * (2 * kH) + dir * kH + j] = h2;
    }
}

// ---------------------------------------------------------------------------
// Small-M GEMM body (FFMA2)
// ---------------------------------------------------------------------------
__device__ __forceinline__
void gemm64_body(const float* __restrict__ A, int lda,
                 const float* __restrict__ Bm, int ldb,
                 const float* __restrict__ bias,
                 float* __restrict__ C, int ldc,
                 int K, int act, int nb) {
    constexpr int BK = 32;
    __shared__ __align__(16) float As[BK][64];
    __shared__ __align__(16) float Bs[BK][64];
    const int tid = threadIdx.x;
    const int bn = nb * 64;
    const int lr = tid >> 3;
    const int lc = (tid & 7) << 2;
    const int tm = (tid >> 4) << 2;
    const int tn = (tid & 15) << 2;

    unsigned long long acc[4][2];
#pragma unroll
    for (int i = 0; i < 4; i++) { acc[i][0] = 0ull; acc[i][1] = 0ull; }

    for (int k0 = 0; k0 < K; k0 += BK) {
#pragma unroll
        for (int h = 0; h < 2; h++) {
            int r = lr + h * 32;
            float4 v = *(const float4*)(A + (size_t)r * lda + k0 + lc);
            As[lc + 0][r] = v.x; As[lc + 1][r] = v.y;
            As[lc + 2][r] = v.z; As[lc + 3][r] = v.w;
            float4 w = *(const float4*)(Bm + (size_t)(bn + r) * ldb + k0 + lc);
            Bs[lc + 0][r] = w.x; Bs[lc + 1][r] = w.y;
            Bs[lc + 2][r] = w.z; Bs[lc + 3][r] = w.w;
        }
        __syncthreads();
#pragma unroll
        for (int k = 0; k < BK; k++) {
            float4 af = *(const float4*)&As[k][tm];
            unsigned long long aa[4];
            aa[0] = pk2(af.x); aa[1] = pk2(af.y);
            aa[2] = pk2(af.z); aa[3] = pk2(af.w);
            ulonglong2 bv = *(const ulonglong2*)&Bs[k][tn];
#pragma unroll
            for (int i = 0; i < 4; i++) {
                fma2(acc[i][0], aa[i], bv.x);
                fma2(acc[i][1], aa[i], bv.y);
            }
        }
        __syncthreads();
    }
#pragma unroll
    for (int i = 0; i < 4; i++) {
        int col = bn + tn;
        float4 v;
        v.x = lo2(acc[i][0]); v.y = hi2(acc[i][0]);
        v.z = lo2(acc[i][1]); v.w = hi2(acc[i][1]);
        if (bias) {
            v.x += bias[col + 0]; v.y += bias[col + 1];
            v.z += bias[col + 2]; v.w += bias[col + 3];
        }
        if (act == 1) {
            v.x = tanhf(v.x); v.y = tanhf(v.y);
            v.z = tanhf(v.z); v.w = tanhf(v.w);
        }
        *(float4*)(C + (size_t)(tm + i) * ldc + col) = v;
    }
}

__global__ __launch_bounds__(256)
void gemm64(const float* __restrict__ A, int lda,
            const float* __restrict__ Bm, int ldb,
            const float* __restrict__ bias,
            float* __restrict__ C, int ldc, int K, int act) {
    gemm64_body(A, lda, Bm, ldb, bias, C, ldc, K, act, blockIdx.x);
}

// Decoder pre-attention GEMMs, K-split 2: hp (32 blocks) + ghd (96 blocks)
__global__ __launch_bounds__(256)
void dec_pre_gemm(const float* __restrict__ W_attn,
                  const float* __restrict__ Wh_d,
                  const float* __restrict__ bh_d) {
    int x = blockIdx.x;
    if (x < 32) {
        int ks = x >> 4, nb = x & 15;
        gemm64_body(g_hdec + ks * 512, kH, W_attn + ks * 512, kG, nullptr,
                    g_hp + (size_t)ks * kB * kH, kH, 512, 0, nb);
    } else {
        int i = x - 32;
        int ks = i / 48, nb = i % 48;
        gemm64_body(g_hdec + ks * 512, kH, Wh_d + ks * 512, kH,
                    ks == 0 ? bh_d : nullptr,
                    g_ghd + (size_t)ks * kB * kG, kG, 512, 0, nb);
    }
}

// ---------------------------------------------------------------------------
__global__ void hcat_kernel() {
    int idx = blockIdx.x * blockDim.x + threadIdx.x;
    if (idx >= 2 * kB * kH) return;
    int dir = idx / (kB * kH);
    int rem = idx - dir * (kB * kH);
    int b = rem / kH, j = rem - b * kH;
    g_hcat[(size_t)b * 2 * kH + dir * kH + j] = g_h[0][idx];
}

// ---------------------------------------------------------------------------
// Fully fused decoder step — fp16 streamed operands (encproj/enc/encWi).
// One CTA per batch element, 512 threads.
// ---------------------------------------------------------------------------
__global__ __launch_bounds__(512)
void attn_step_fused(const int* __restrict__ src,
                     const float* __restrict__ v_attn,
                     const float* __restrict__ gxet_t,
                     float* __restrict__ feat_t) {
    int b = blockIdx.x;
    __shared__ float sc[kS];
    __shared__ float sgxw[kG];
    int tid = threadIdx.x, warp = tid >> 5, lane = tid & 31;
    const float* hp0 = g_hp + (size_t)b * kH;
    const float* hp1 = g_hp + (size_t)kB * kH + (size_t)b * kH;

    // 1. attention scores (fp16 encproj, 2 cols/lane-iter)
    for (int s = warp; s < kS; s += 16) {
        const __half2* ep = (const __half2*)(g_ep16 + ((size_t)b * kS + s) * kH);
        float p = 0.f;
        for (int j2 = lane; j2 < kH / 2; j2 += 32) {
            float2 e = __half22float2(ep[j2]);
            float2 a0 = ((const float2*)hp0)[j2];
            float2 a1 = ((const float2*)hp1)[j2];
            float2 va = ((const float2*)v_attn)[j2];
            p += va.x * tanhf(a0.x + a1.x + e.x);
            p += va.y * tanhf(a0.y + a1.y + e.y);
        }
#pragma unroll
        for (int o = 16; o; o >>= 1) p += __shfl_xor_sync(0xffffffffu, p, o);
        if (lane == 0) sc[s] = (src[s * kB + b] != kPAD) ? p : -1e10f;
    }
    __syncthreads();

    // 2. softmax over S=48
    if (tid < 32) {
        float v1 = sc[tid];
        float v2 = (tid + 32 < kS) ? sc[tid + 32] : -1e30f;
        float mx = fmaxf(v1, v2);
#pragma unroll
        for (int o = 16; o; o >>= 1) mx = fmaxf(mx, __shfl_xor_sync(0xffffffffu, mx, o));
        float e1 = expf(v1 - mx);
        float e2 = (tid + 32 < kS) ? expf(v2 - mx) : 0.f;
        float sm = e1 + e2;
#pragma unroll
        for (int o = 16; o; o >>= 1) sm += __shfl_xor_sync(0xffffffffu, sm, o);
        float inv = 1.f / sm;
        sc[tid] = e1 * inv;
        if (tid + 32 < kS) sc[tid + 32] = e2 * inv;
    }
    __syncthreads();

    // 3a. context w = a @ enc16 (8 fp16 cols per chunk)
    for (int c8 = tid; c8 < 2 * kH / 8; c8 += 512) {
        float acc[8];
#pragma unroll
        for (int q = 0; q < 8; q++) acc[q] = 0.f;
        const uint4* base = (const uint4*)(g_enc16 + (size_t)b * kS * 2 * kH) + c8;
#pragma unroll 4
        for (int s = 0; s < kS; s++) {
            uint4 v = base[s * (2 * kH / 8)];
            float a = sc[s];
            __half2 p0 = *reinterpret_cast<__half2*>(&v.x);
            __half2 p1 = *reinterpret_cast<__half2*>(&v.y);
            __half2 p2 = *reinterpret_cast<__half2*>(&v.z);
            __half2 p3 = *reinterpret_cast<__half2*>(&v.w);
            float2 f0 = __half22float2(p0), f1 = __half22float2(p1);
            float2 f2 = __half22float2(p2), f3 = __half22float2(p3);
            acc[0] += a * f0.x; acc[1] += a * f0.y;
            acc[2] += a * f1.x; acc[3] += a * f1.y;
            acc[4] += a * f2.x; acc[5] += a * f2.y;
            acc[6] += a * f3.x; acc[7] += a * f3.y;
        }
        float* dst = feat_t + (size_t)b * kF + kH + c8 * 8;
        *(float4*)dst = make_float4(acc[0], acc[1], acc[2], acc[3]);
        *(float4*)(dst + 4) = make_float4(acc[4], acc[5], acc[6], acc[7]);
    }
    // 3b. gxw = a @ encWi16 (8 fp16 cols per chunk -> smem)
    for (int c8 = tid; c8 < kG / 8; c8 += 512) {
        float acc[8];
#pragma unroll
        for (int q = 0; q < 8; q++) acc[q] = 0.f;
        const uint4* base = (const uint4*)(g_encWi16 + (size_t)b * kS * kG) + c8;
#pragma unroll 4
        for (int s = 0; s < kS; s++) {
            uint4 v = base[s * (kG / 8)];
            float a = sc[s];
            __half2 p0 = *reinterpret_cast<__half2*>(&v.x);
            __half2 p1 = *reinterpret_cast<__half2*>(&v.y);
            __half2 p2 = *reinterpret_cast<__half2*>(&v.z);
            __half2 p3 = *reinterpret_cast<__half2*>(&v.w);
            float2 f0 = __half22float2(p0), f1 = __half22float2(p1);
            float2 f2 = __half22float2(p2), f3 = __half22float2(p3);
            acc[0] += a * f0.x; acc[1] += a * f0.y;
            acc[2] += a * f1.x; acc[3] += a * f1.y;
            acc[4] += a * f2.x; acc[5] += a * f2.y;
            acc[6] += a * f3.x; acc[7] += a * f3.y;
        }
        float* dst = sgxw + c8 * 8;
        *(float4*)dst = make_float4(acc[0], acc[1], acc[2], acc[3]);
        *(float4*)(dst + 4) = make_float4(acc[4], acc[5], acc[6], acc[7]);
    }
    __syncthreads();

    // 4. GRU gate -> h2
    const float* q0 = g_ghd + (size_t)b * kG;
    const float* q1 = g_ghd + (size_t)kB * kG + (size_t)b * kG;
    const float* gx = gxet_t + (size_t)b * kG;
    for (int j = tid; j < kH; j += 512) {
        float h = g_hdec[(size_t)b * kH + j];
        float xr = gx[j] + sgxw[j];
        float xz = gx[kH + j] + sgxw[kH + j];
        float xn = gx[2 * kH + j] + sgxw[2 * kH + j];
        float ghr = q0[j] + q1[j];
        float ghz = q0[kH + j] + q1[kH + j];
        float ghn = q0[2 * kH + j] + q1[2 * kH + j];
        float r = 1.f / (1.f + expf(-(xr + ghr)));
        float z = 1.f / (1.f + expf(-(xz + ghz)));
        float n = tanhf(xn + r * ghn);
        float h2 = (1.f - z) * n + z * h;
        g_hdec[(size_t)b * kH + j] = h2;
        feat_t[(size_t)b * kF + j] = h2;
    }
}

// ---------------------------------------------------------------------------
// Host orchestration (two-stream fork/join, graph-capturable)
// ---------------------------------------------------------------------------
extern "C" void kernel_launch(void* const* d_in, const int* in_sizes, int n_in,
                              void* d_out, int out_size) {
    const int*   src     = (const int*)d_in[0];
    const int*   trg     = (const int*)d_in[1];
    const float* emb_enc = (const float*)d_in[2];
    const float* Wi_f    = (const float*)d_in[3];
    const float* Wh_f    = (const float*)d_in[4];
    const float* bi_f    = (const float*)d_in[5];
    const float* bh_f    = (const float*)d_in[6];
    const float* Wi_b    = (const float*)d_in[7];
    const float* Wh_b    = (const float*)d_in[8];
    const float* bi_b    = (const float*)d_in[9];
    const float* bh_b    = (const float*)d_in[10];
    const float* W_fc    = (const float*)d_in[11];
    const float* b_fc    = (const float*)d_in[12];
    const float* W_attn  = (const float*)d_in[13];
    const float* b_attn  = (const float*)d_in[14];
    const float* v_attn  = (const float*)d_in[15];
    const float* emb_dec = (const float*)d_in[16];
    const float* Wi_d    = (const float*)d_in[17];
    const float* Wh_d    = (const float*)d_in[18];
    const float* bi_d    = (const float*)d_in[19];
    const float* bh_d    = (const float*)d_in[20];
    const float* W_out   = (const float*)d_in[21];
    const float* b_out   = (const float*)d_in[22];
    float* out = (float*)d_out;

    float *p_enc, *p_ep, *p_encWi, *p_hcat, *p_hdec, *p_gxet, *p_feat,
          *p_gxf, *p_gxb;
    __nv_bfloat16 *p_Ahi, *p_Alo, *p_Ehi, *p_Elo;
    __nv_bfloat16 *p_Wifh, *p_Wifl, *p_Wibh, *p_Wibl;
    __nv_bfloat16 *p_Widh, *p_Widl, *p_Wah, *p_Wal, *p_Ench, *p_Encl;
    __half *p_Fhi, *p_Flo, *p_Bf16, *p_encWi16, *p_enc16, *p_ep16;
    cudaGetSymbolAddress((void**)&p_enc, g_enc);
    cudaGetSymbolAddress((void**)&p_ep, g_encproj);
    cudaGetSymbolAddress((void**)&p_encWi, g_encWi);
    cudaGetSymbolAddress((void**)&p_hcat, g_hcat);
    cudaGetSymbolAddress((void**)&p_hdec, g_hdec);
    cudaGetSymbolAddress((void**)&p_gxet, g_gxet);
    cudaGetSymbolAddress((void**)&p_feat, g_feat);
    cudaGetSymbolAddress((void**)&p_gxf, g_gxf);
    cudaGetSymbolAddress((void**)&p_gxb, g_gxb);
    cudaGetSymbolAddress((void**)&p_Ahi, g_Ahi);
    cudaGetSymbolAddress((void**)&p_Alo, g_Alo);
    cudaGetSymbolAddress((void**)&p_Ehi, g_Ehi);
    cudaGetSymbolAddress((void**)&p_Elo, g_Elo);
    cudaGetSymbolAddress((void**)&p_Wifh, g_Wifh);
    cudaGetSymbolAddress((void**)&p_Wifl, g_Wifl);
    cudaGetSymbolAddress((void**)&p_Wibh, g_Wibh);
    cudaGetSymbolAddress((void**)&p_Wibl, g_Wibl);
    cudaGetSymbolAddress((void**)&p_Widh, g_Widh);
    cudaGetSymbolAddress((void**)&p_Widl, g_Widl);
    cudaGetSymbolAddress((void**)&p_Wah, g_Wah);
    cudaGetSymbolAddress((void**)&p_Wal, g_Wal);
    cudaGetSymbolAddress((void**)&p_Ench, g_Ench);
    cudaGetSymbolAddress((void**)&p_Encl, g_Encl);
    cudaGetSymbolAddress((void**)&p_Fhi, g_Fhi);
    cudaGetSymbolAddress((void**)&p_Flo, g_Flo);
    cudaGetSymbolAddress((void**)&p_Bf16, g_Bf16);
    cudaGetSymbolAddress((void**)&p_encWi16, g_encWi16);
    cudaGetSymbolAddress((void**)&p_enc16, g_enc16);
    cudaGetSymbolAddress((void**)&p_ep16, g_ep16);

    static cudaStream_t s1 = nullptr;
    static cudaEvent_t evFork = nullptr, evJoin = nullptr;
    if (s1 == nullptr) {
        cudaStreamCreateWithFlags(&s1, cudaStreamNonBlocking);
        cudaEventCreateWithFlags(&evFork, cudaEventDisableTiming);
        cudaEventCreateWithFlags(&evJoin, cudaEventDisableTiming);
        cudaFuncSetAttribute(hgemm,
                             cudaFuncAttributeMaxDynamicSharedMemorySize,
                             outg::SMEM_SZ);
        cudaFuncSetAttribute(hgemm2,
                             cudaFuncAttributeMaxDynamicSharedMemorySize,
                             outh::SMEM_SZ);
    }

    // fork side stream off the capture stream
    cudaEventRecord(evFork, 0);
    cudaStreamWaitEvent(s1, evFork, 0);

    // --- main stream: encoder-critical path ---
    init_kernel<<<((size_t)kB * kV + 255) / 256, 256>>>(out);
    enc_embed_kernel<<<kME, 128>>>(src, emb_enc);
    {
        size_t n4 = (size_t)kG * kE / 4;
        cvt_split4<<<(unsigned)((n4 + 255) / 256), 256>>>(
            (const float4*)Wi_f, (__nv_bfloat162*)p_Wifh,
            (__nv_bfloat162*)p_Wifl, n4);
        cvt_split4<<<(unsigned)((n4 + 255) / 256), 256>>>(
            (const float4*)Wi_b, (__nv_bfloat162*)p_Wibh,
            (__nv_bfloat162*)p_Wibl, n4);
    }
    // --- side stream: decoder-prep + big weight conversions ---
    dec_embed_all<<<kMR, 128, 0, s1>>>(trg, emb_dec);
    // --- main: input-gate GEMMs ---
    hgemm<<<dim3(kME / 128, kG / 128), 256, outg::SMEM_SZ>>>(
        p_Ehi, p_Elo, kE, p_Wifh, p_Wifl, kE, bi_f, p_gxf, kG, kME, kE);
    hgemm<<<dim3(kME / 128, kG / 128), 256, outg::SMEM_SZ>>>(
        p_Ehi, p_Elo, kE, p_Wibh, p_Wibl, kE, bi_b, p_gxb, kG, kME, kE);
    // --- side stream continues ---
    {
        size_t n4 = (size_t)kG * kXW / 4;
        cvt_split4<<<(unsigned)((n4 + 255) / 256), 256, 0, s1>>>(
            (const float4*)Wi_d, (__nv_bfloat162*)p_Widh,
            (__nv_bfloat162*)p_Widl, n4);
        n4 = (size_t)kH * kG / 4;
        cvt_split4<<<(unsigned)((n4 + 255) / 256), 256, 0, s1>>>(
            (const float4*)W_attn, (__nv_bfloat162*)p_Wah,
            (__nv_bfloat162*)p_Wal, n4);
        hgemm<<<dim3(kMP / 128, kG / 128), 256, outg::SMEM_SZ, s1>>>(
            p_Ahi + 3 * kH, p_Alo + 3 * kH, kF, p_Widh, p_Widl, kXW, bi_d,
            p_gxet, kG, kMR, kE);
        // W_out -> single fp16
        n4 = (size_t)kV * kF / 4;
        cvt16_4<<<(unsigned)((n4 + 255) / 256), 256, 0, s1>>>(
            (const float4*)W_out, (__half2*)p_Bf16, n4);
    }
    cudaEventRecord(evJoin, s1);

    // --- main: encoder recurrence (overlaps side stream) ---
    for (int s = 0; s < kS; s++)
        enc_step_fused<<<dim3(64, 2), 256>>>(s, Wh_f, Wh_b, bh_f, bh_b);

    // decoder init hidden
    hcat_kernel<<<(2 * kB * kH) / 256, 256>>>();
    gemm64<<<kH / 64, 256>>>(p_hcat, 2 * kH, W_fc, 2 * kH, b_fc,
                             p_hdec, kH, 2 * kH, 1);

    // encoder split + attention projection + encWi (needs side stream)
    {
        size_t n4 = (size_t)kME * 2 * kH / 4;
        cvt_split4<<<(unsigned)((n4 + 255) / 256), 256>>>(
            (const float4*)p_enc, (__nv_bfloat162*)p_Ench,
            (__nv_bfloat162*)p_Encl, n4);
        // enc fp16 read-copy for the decoder loop
        cvt16_4<<<(unsigned)((n4 + 255) / 256), 256>>>(
            (const float4*)p_enc, (__half2*)p_enc16, n4);
        cudaStreamWaitEvent(0, evJoin, 0);
        hgemm<<<dim3(kME / 128, kH / 128), 256, outg::SMEM_SZ>>>(
            p_Ench, p_Encl, 2 * kH, p_Wah + kH, p_Wal + kH, kG, b_attn,
            p_ep, kH, kME, 2 * kH);
        hgemm<<<dim3(kME / 128, kG / 128), 256, outg::SMEM_SZ>>>(
            p_Ench, p_Encl, 2 * kH, p_Widh + kE, p_Widl + kE, kXW,
            (const float*)nullptr, p_encWi, kG, kME, 2 * kH);
        // fp16 read-copies of encproj and encWi
        size_t m4 = (size_t)kME * kH / 4;
        cvt16_4<<<(unsigned)((m4 + 255) / 256), 256>>>(
            (const float4*)p_ep, (__half2*)p_ep16, m4);
        m4 = (size_t)kME * kG / 4;
        cvt16_4<<<(unsigned)((m4 + 255) / 256), 256>>>(
            (const float4*)p_encWi, (__half2*)p_encWi16, m4);
    }

    // decoder loop: 2 launches per step
    for (int t = 0; t < kT - 1; t++) {
        float* feat_t = p_feat + (size_t)t * kB * kF;
        dec_pre_gemm<<<128, 256>>>(W_attn, Wh_d, bh_d);
        attn_step_fused<<<kB, 512>>>(src, v_attn,
                                     p_gxet + (size_t)t * kB * kG, feat_t);
    }

    // fp16-convert features, 2-pass fp16 output projection
    {
        size_t n = (size_t)kMP * kF / 4;
        cvt_feat16<<<(unsigned)((n + 255) / 256), 256>>>();
        hgemm2<<<dim3(kMP / 128, kV / 128), 256, outh::SMEM_SZ>>>(
            p_Fhi, p_Flo, kF, p_Bf16, kF, b_out,
            out + (size_t)kB * kV, kV, kMR, kF);
    }
}

// round 16
// speedup vs baseline: 1.5527x; 1.1751x over previous
#include <cuda_runtime.h>
#include <cuda_bf16.h>
#include <cuda_fp16.h>
#include <math.h>
#include <stdint.h>

// ---------------------------------------------------------------------------
// Problem constants
// ---------------------------------------------------------------------------
namespace {
constexpr int kS = 48;          // source length
constexpr int kT = 32;          // target length
constexpr int kB = 64;          // batch
constexpr int kH = 1024;        // hidden
constexpr int kE = 512;         // embed
constexpr int kV = 32000;       // vocab
constexpr int kG = 3 * kH;      // 3072 gates
constexpr int kF = 3 * kH + kE; // 3584 out-proj features
constexpr int kXW = kE + 2*kH;  // 2560 decoder GRU input width
constexpr int kPAD = 1;
constexpr int kMR = (kT - 1) * kB; // 1984 output rows
constexpr int kMP = 2048;          // padded rows for tensor GEMM
constexpr int kME = kS * kB;       // 3072 encoder rows
}

// ---------------------------------------------------------------------------
// Packed fp32x2 helpers (FFMA2)
// ---------------------------------------------------------------------------
__device__ __forceinline__ unsigned long long pk2(float x) {
    unsigned long long r;
    unsigned u = __float_as_uint(x);
    asm("mov.b64 %0, {%1, %1};" : "=l"(r) : "r"(u));
    return r;
}
__device__ __forceinline__ void fma2(unsigned long long& d,
                                     unsigned long long a,
                                     unsigned long long b) {
    asm("fma.rn.f32x2 %0, %1, %2, %0;" : "+l"(d) : "l"(a), "l"(b));
}
__device__ __forceinline__ float lo2(unsigned long long v) {
    return __uint_as_float((unsigned)v);
}
__device__ __forceinline__ float hi2(unsigned long long v) {
    return __uint_as_float((unsigned)(v >> 32));
}

// ---------------------------------------------------------------------------
// Plain-PTX helpers: cp.async / ldmatrix / mma.sync
// ---------------------------------------------------------------------------
__device__ __forceinline__ uint32_t smem_u32(const void* p) {
    uint32_t a;
    asm("{ .reg .u64 t; cvta.to.shared.u64 t, %1; cvt.u32.u64 %0, t; }"
        : "=r"(a) : "l"(p));
    return a;
}
#define CP_ASYNC16(dst, src) \
    asm volatile("cp.async.cg.shared.global [%0], [%1], 16;" \
                 :: "r"(dst), "l"(src) : "memory")
#define CP_COMMIT() asm volatile("cp.async.commit_group;" ::: "memory")
#define CP_WAIT1()  asm volatile("cp.async.wait_group 1;" ::: "memory")
#define CP_WAIT0()  asm volatile("cp.async.wait_group 0;" ::: "memory")

__device__ __forceinline__ void ldsm4(uint32_t* r, uint32_t addr) {
    asm volatile("ldmatrix.sync.aligned.m8n8.x4.shared.b16 {%0,%1,%2,%3}, [%4];"
                 : "=r"(r[0]), "=r"(r[1]), "=r"(r[2]), "=r"(r[3])
                 : "r"(addr));
}
__device__ __forceinline__ void mma16816(float* d, const uint32_t* a,
                                         const uint32_t* b) {
    asm volatile(
        "mma.sync.aligned.m16n8k16.row.col.f32.bf16.bf16.f32 "
        "{%0,%1,%2,%3}, {%4,%5,%6,%7}, {%8,%9}, {%0,%1,%2,%3};"
        : "+f"(d[0]), "+f"(d[1]), "+f"(d[2]), "+f"(d[3])
        : "r"(a[0]), "r"(a[1]), "r"(a[2]), "r"(a[3]),
          "r"(b[0]), "r"(b[1]));
}
__device__ __forceinline__ void mma16816h(float* d, const uint32_t* a,
                                          const uint32_t* b) {
    asm volatile(
        "mma.sync.aligned.m16n8k16.row.col.f32.f16.f16.f32 "
        "{%0,%1,%2,%3}, {%4,%5,%6,%7}, {%8,%9}, {%0,%1,%2,%3};"
        : "+f"(d[0]), "+f"(d[1]), "+f"(d[2]), "+f"(d[3])
        : "r"(a[0]), "r"(a[1]), "r"(a[2]), "r"(a[3]),
          "r"(b[0]), "r"(b[1]));
}

// ---------------------------------------------------------------------------
// Persistent scratch
// ---------------------------------------------------------------------------
__device__ float g_emb[(size_t)kME * kE];
__device__ float g_gxf[(size_t)kME * kG];
__device__ float g_gxb[(size_t)kME * kG];
__device__ float g_enc[(size_t)kME * 2 * kH];      // [b][s][2H]
__device__ float g_h[2][2 * kB * kH];              // double-buffered h_f|h_b
__device__ float g_hcat[kB * 2 * kH];
__device__ float g_hdec[kB * kH];
__device__ float g_hp[2 * kB * kH];                // 2 K-partials
__device__ float g_ghd[2 * kB * kG];               // 2 K-partials
__device__ float g_gxet[(size_t)kMR * kG];
__device__ float g_feat[(size_t)kMR * kF];         // [h2, w, et] per step
// bf16 split operands for bf16x3 HMMA GEMMs (recurrence-feeding paths)
__device__ __nv_bfloat16 g_Ahi[(size_t)kMP * kF];  // decoder et cols
__device__ __nv_bfloat16 g_Alo[(size_t)kMP * kF];
__device__ __nv_bfloat16 g_Ehi[(size_t)kME * kE];  // encoder embeddings
__device__ __nv_bfloat16 g_Elo[(size_t)kME * kE];
__device__ __nv_bfloat16 g_Wifh[(size_t)kG * kE];  // Wi_f
__device__ __nv_bfloat16 g_Wifl[(size_t)kG * kE];
__device__ __nv_bfloat16 g_Wibh[(size_t)kG * kE];  // Wi_b
__device__ __nv_bfloat16 g_Wibl[(size_t)kG * kE];
__device__ __nv_bfloat16 g_Widh[(size_t)kG * kXW]; // Wi_d (for gxet cols :E)
__device__ __nv_bfloat16 g_Widl[(size_t)kG * kXW];
// fp16 operands (single precision level, calibrated safe)
__device__ __half g_Fh[(size_t)kMP * kF];          // feat fp16
__device__ __half g_Bf16[(size_t)kV * kF];         // W_out fp16
__device__ __half g_Wid16[(size_t)kG * kXW];       // Wi_d fp16 (for encWi)
__device__ __half g_Wa16[(size_t)kH * kG];         // W_attn fp16 (for encproj)
__device__ __half g_encWi16[(size_t)kME * kG];
__device__ __half g_enc16[(size_t)kME * 2 * kH];
__device__ __half g_ep16[(size_t)kME * kH];

// ---------------------------------------------------------------------------
__global__ void init_kernel(float* __restrict__ out0) {
    size_t i = (size_t)blockIdx.x * blockDim.x + threadIdx.x;
    if (i < (size_t)kB * kV) out0[i] = 0.f;
    if (i < (size_t)2 * kB * kH) g_h[0][i] = 0.f;
}

// encoder embedding gather + bf16 split emit
__global__ void enc_embed_kernel(const int* __restrict__ src,
                                 const float* __restrict__ table) {
    int row = blockIdx.x;
    int tok = src[row];
    float4 v = ((const float4*)(table + (size_t)tok * kE))[threadIdx.x];
    ((float4*)(g_emb + (size_t)row * kE))[threadIdx.x] = v;
    size_t o = (size_t)row * kE + threadIdx.x * 4;
    float vv[4] = { v.x, v.y, v.z, v.w };
#pragma unroll
    for (int q = 0; q < 4; q++) {
        __nv_bfloat16 h = __float2bfloat16(vv[q]);
        g_Ehi[o + q] = h;
        g_Elo[o + q] = __float2bfloat16(vv[q] - __bfloat162float(h));
    }
}

// decoder embeddings -> feat float + bf16 split into g_Ahi/g_Alo et columns
__global__ void dec_embed_all(const int* __restrict__ trg,
                              const float* __restrict__ emb_dec) {
    int row = blockIdx.x;
    int tok = trg[row];
    float4 v = ((const float4*)(emb_dec + (size_t)tok * kE))[threadIdx.x];
    ((float4*)(g_feat + (size_t)row * kF + 3 * kH))[threadIdx.x] = v;
    size_t o = (size_t)row * kF + 3 * kH + threadIdx.x * 4;
    float vv[4] = { v.x, v.y, v.z, v.w };
#pragma unroll
    for (int q = 0; q < 4; q++) {
        __nv_bfloat16 h = __float2bfloat16(vv[q]);
        g_Ahi[o + q] = h;
        g_Alo[o + q] = __float2bfloat16(vv[q] - __bfloat162float(h));
    }
}

// ---------------------------------------------------------------------------
// bf16 split conversion (4 elements/thread, fully vectorized)
// ---------------------------------------------------------------------------
__global__ void cvt_split4(const float4* __restrict__ src,
                           __nv_bfloat162* __restrict__ hi,
                           __nv_bfloat162* __restrict__ lo, size_t n4) {
    size_t i = (size_t)blockIdx.x * blockDim.x + threadIdx.x;
    if (i >= n4) return;
    float4 v = src[i];
    __nv_bfloat16 h0 = __float2bfloat16(v.x);
    __nv_bfloat16 h1 = __float2bfloat16(v.y);
    __nv_bfloat16 h2 = __float2bfloat16(v.z);
    __nv_bfloat16 h3 = __float2bfloat16(v.w);
    hi[2 * i]     = __nv_bfloat162(h0, h1);
    hi[2 * i + 1] = __nv_bfloat162(h2, h3);
    lo[2 * i]     = __nv_bfloat162(
        __float2bfloat16(v.x - __bfloat162float(h0)),
        __float2bfloat16(v.y - __bfloat162float(h1)));
    lo[2 * i + 1] = __nv_bfloat162(
        __float2bfloat16(v.z - __bfloat162float(h2)),
        __float2bfloat16(v.w - __bfloat162float(h3)));
}

// fp32 -> single fp16 conversion (4 elements/thread)
__global__ void cvt16_4(const float4* __restrict__ src,
                        __half2* __restrict__ dst, size_t n4) {
    size_t i = (size_t)blockIdx.x * blockDim.x + threadIdx.x;
    if (i >= n4) return;
    float4 v = src[i];
    dst[2 * i]     = __floats2half2_rn(v.x, v.y);
    dst[2 * i + 1] = __floats2half2_rn(v.z, v.w);
}

// convert ALL feat columns to single fp16 (padded rows zeroed)
__global__ void cvt_feat16() {
    size_t i = (size_t)blockIdx.x * blockDim.x + threadIdx.x;
    if (i >= (size_t)kMP * kF / 4) return;
    size_t row = i / (kF / 4);
    size_t col = (i % (kF / 4)) * 4;
    float4 v = make_float4(0.f, 0.f, 0.f, 0.f);
    if (row < (size_t)kMR)
        v = *(const float4*)(g_feat + row * kF + col);
    __half2* dst = (__half2*)(g_Fh + row * kF + col);
    dst[0] = __floats2half2_rn(v.x, v.y);
    dst[1] = __floats2half2_rn(v.z, v.w);
}

// ---------------------------------------------------------------------------
// Generalized bf16x3 HMMA GEMM (round-9 proven config)
// ---------------------------------------------------------------------------
namespace outg {
constexpr int BM = 128, BN = 128, BK = 64;
constexpr int HALF = 16384;
constexpr int STAGE = 4 * HALF;
constexpr int SMEM_SZ = 2 * STAGE;          // 131072
}

__device__ __forceinline__ void hg_prefetch(
    const __nv_bfloat16* __restrict__ Ah, const __nv_bfloat16* __restrict__ Al,
    int lda,
    const __nv_bfloat16* __restrict__ Bh, const __nv_bfloat16* __restrict__ Bl,
    int ldb, int k0, uint32_t buf, int tid, int m0, int n0) {
    using namespace outg;
#pragma unroll
    for (int i = 0; i < 4; i++) {
        int id = tid + i * 256;
        int row = id >> 3, c = id & 7;
        uint32_t off = (uint32_t)(row << 7) + (c << 4);
        uint32_t sw = off ^ ((off >> 3) & 0x70);
        size_t ga = (size_t)(m0 + row) * lda + k0 + c * 8;
        size_t gb = (size_t)(n0 + row) * ldb + k0 + c * 8;
        CP_ASYNC16(buf + sw, Ah + ga);
        CP_ASYNC16(buf + HALF + sw, Al + ga);
        CP_ASYNC16(buf + 2 * HALF + sw, Bh + gb);
        CP_ASYNC16(buf + 3 * HALF + sw, Bl + gb);
    }
}

__device__ __forceinline__ void hg_compute(uint32_t buf, int lane,
                                           int wm, int wn,
                                           float acc[2][8][4]) {
    using namespace outg;
    const int g = lane >> 3, r = lane & 7;
#pragma unroll
    for (int ks = 0; ks < 4; ks++) {
        uint32_t ahi[2][4], alo[2][4];
#pragma unroll
        for (int mi = 0; mi < 2; mi++) {
            int row = wm + mi * 16 + ((g & 1) << 3) + r;
            int chunk = ks * 2 + (g >> 1);
            uint32_t off = (uint32_t)(row << 7) + (chunk << 4);
            uint32_t sw = off ^ ((off >> 3) & 0x70);
            ldsm4(ahi[mi], buf + sw);
            ldsm4(alo[mi], buf + HALF + sw);
        }
        uint32_t bhi[4][4], blo[4][4];
#pragma unroll
        for (int np = 0; np < 4; np++) {
            int row = wn + np * 16 + ((g >> 1) << 3) + r;
            int chunk = ks * 2 + (g & 1);
            uint32_t off = (uint32_t)(row << 7) + (chunk << 4);
            uint32_t sw = off ^ ((off >> 3) & 0x70);
            ldsm4(bhi[np], buf + 2 * HALF + sw);
            ldsm4(blo[np], buf + 3 * HALF + sw);
        }
#pragma unroll
        for (int mi = 0; mi < 2; mi++) {
#pragma unroll
            for (int np = 0; np < 4; np++) {
#pragma unroll
                for (int a = 0; a < 2; a++) {
                    uint32_t bh[2] = { bhi[np][2 * a], bhi[np][2 * a + 1] };
                    uint32_t bl[2] = { blo[np][2 * a], blo[np][2 * a + 1] };
                    float* d = acc[mi][np * 2 + a];
                    mma16816(d, ahi[mi], bh);
                    mma16816(d, ahi[mi], bl);
                    mma16816(d, alo[mi], bh);
                }
            }
        }
    }
}

__global__ __launch_bounds__(256, 1)
void hgemm(const __nv_bfloat16* __restrict__ Ah,
           const __nv_bfloat16* __restrict__ Al, int lda,
           const __nv_bfloat16* __restrict__ Bh,
           const __nv_bfloat16* __restrict__ Bl, int ldb,
           const float* __restrict__ bias, float* __restrict__ C, int ldc,
           int M, int K) {
    using namespace outg;
    extern __shared__ char smem[];
    const uint32_t sb = smem_u32(smem);
    const int tid = threadIdx.x;
    const int wid = tid >> 5, lane = tid & 31;
    const int m0 = blockIdx.x * BM;
    const int n0 = blockIdx.y * BN;
    const int wm = (wid & 3) * 32;
    const int wn = (wid >> 2) * 64;
    const int nslab = K / BK;

    float acc[2][8][4];
#pragma unroll
    for (int i = 0; i < 2; i++)
#pragma unroll
        for (int j = 0; j < 8; j++)
#pragma unroll
            for (int q = 0; q < 4; q++) acc[i][j][q] = 0.f;

    hg_prefetch(Ah, Al, lda, Bh, Bl, ldb, 0, sb, tid, m0, n0);
    CP_COMMIT();
    hg_prefetch(Ah, Al, lda, Bh, Bl, ldb, BK, sb + STAGE, tid, m0, n0);
    CP_COMMIT();

    for (int s = 0; s < nslab; s++) {
        const int st = s & 1;
        if (s == nslab - 1) { CP_WAIT0(); } else { CP_WAIT1(); }
        __syncthreads();
        hg_compute(sb + st * STAGE, lane, wm, wn, acc);
        __syncthreads();
        if (s + 2 < nslab) {
            hg_prefetch(Ah, Al, lda, Bh, Bl, ldb, (s + 2) * BK,
                        sb + st * STAGE, tid, m0, n0);
            CP_COMMIT();
        }
    }

    const int r0 = m0 + wm + (lane >> 2);
    const int c0 = n0 + wn + (lane & 3) * 2;
#pragma unroll
    for (int mi = 0; mi < 2; mi++) {
#pragma unroll
        for (int ni = 0; ni < 8; ni++) {
            int row = r0 + mi * 16;
            int col = c0 + ni * 8;
            const float* d = acc[mi][ni];
            float b0 = bias ? bias[col] : 0.f;
            float b1 = bias ? bias[col + 1] : 0.f;
            if (row < M) {
                C[(size_t)row * ldc + col]     = d[0] + b0;
                C[(size_t)row * ldc + col + 1] = d[1] + b1;
            }
            if (row + 8 < M) {
                C[(size_t)(row + 8) * ldc + col]     = d[2] + b0;
                C[(size_t)(row + 8) * ldc + col + 1] = d[3] + b1;
            }
        }
    }
}

// ---------------------------------------------------------------------------
// Single-pass fp16 HMMA GEMM: C = A[M,K] * B[N,K]^T + bias.
// Output either fp32 (Cf) or fp16 (Ch) — exactly one non-null.
// Tile 128x128x64, 2 smem sections per stage, 2-stage cp.async.
// ---------------------------------------------------------------------------
namespace out1 {
constexpr int BM = 128, BN = 128, BK = 64;
constexpr int HALF = 16384;
constexpr int STAGE = 2 * HALF;             // 32768
constexpr int SMEM_SZ = 2 * STAGE;          // 65536
}

__device__ __forceinline__ void h1_prefetch(
    const __half* __restrict__ A, int lda,
    const __half* __restrict__ Bm, int ldb,
    int k0, uint32_t buf, int tid, int m0, int n0) {
    using namespace out1;
#pragma unroll
    for (int i = 0; i < 4; i++) {
        int id = tid + i * 256;
        int row = id >> 3, c = id & 7;
        uint32_t off = (uint32_t)(row << 7) + (c << 4);
        uint32_t sw = off ^ ((off >> 3) & 0x70);
        size_t ga = (size_t)(m0 + row) * lda + k0 + c * 8;
        size_t gb = (size_t)(n0 + row) * ldb + k0 + c * 8;
        CP_ASYNC16(buf + sw, A + ga);
        CP_ASYNC16(buf + HALF + sw, Bm + gb);
    }
}

__device__ __forceinline__ void h1_compute(uint32_t buf, int lane,
                                           int wm, int wn,
                                           float acc[2][8][4]) {
    using namespace out1;
    const int g = lane >> 3, r = lane & 7;
#pragma unroll
    for (int ks = 0; ks < 4; ks++) {
        uint32_t af[2][4];
#pragma unroll
        for (int mi = 0; mi < 2; mi++) {
            int row = wm + mi * 16 + ((g & 1) << 3) + r;
            int chunk = ks * 2 + (g >> 1);
            uint32_t off = (uint32_t)(row << 7) + (chunk << 4);
            uint32_t sw = off ^ ((off >> 3) & 0x70);
            ldsm4(af[mi], buf + sw);
        }
        uint32_t bf[4][4];
#pragma unroll
        for (int np = 0; np < 4; np++) {
            int row = wn + np * 16 + ((g >> 1) << 3) + r;
            int chunk = ks * 2 + (g & 1);
            uint32_t off = (uint32_t)(row << 7) + (chunk << 4);
            uint32_t sw = off ^ ((off >> 3) & 0x70);
            ldsm4(bf[np], buf + HALF + sw);
        }
#pragma unroll
        for (int mi = 0; mi < 2; mi++) {
#pragma unroll
            for (int np = 0; np < 4; np++) {
#pragma unroll
                for (int a = 0; a < 2; a++) {
                    mma16816h(acc[mi][np * 2 + a], af[mi], &bf[np][2 * a]);
                }
            }
        }
    }
}

__global__ __launch_bounds__(256, 1)
void hgemm1(const __half* __restrict__ A, int lda,
            const __half* __restrict__ Bm, int ldb,
            const float* __restrict__ bias,
            float* __restrict__ Cf, __half* __restrict__ Ch, int ldc,
            int M, int K) {
    using namespace out1;
    extern __shared__ char smem[];
    const uint32_t sb = smem_u32(smem);
    const int tid = threadIdx.x;
    const int wid = tid >> 5, lane = tid & 31;
    const int m0 = blockIdx.x * BM;
    const int n0 = blockIdx.y * BN;
    const int wm = (wid & 3) * 32;
    const int wn = (wid >> 2) * 64;
    const int nslab = K / BK;

    float acc[2][8][4];
#pragma unroll
    for (int i = 0; i < 2; i++)
#pragma unroll
        for (int j = 0; j < 8; j++)
#pragma unroll
            for (int q = 0; q < 4; q++) acc[i][j][q] = 0.f;

    h1_prefetch(A, lda, Bm, ldb, 0, sb, tid, m0, n0);
    CP_COMMIT();
    h1_prefetch(A, lda, Bm, ldb, BK, sb + STAGE, tid, m0, n0);
    CP_COMMIT();

    for (int s = 0; s < nslab; s++) {
        const int st = s & 1;
        if (s == nslab - 1) { CP_WAIT0(); } else { CP_WAIT1(); }
        __syncthreads();
        h1_compute(sb + st * STAGE, lane, wm, wn, acc);
        __syncthreads();
        if (s + 2 < nslab) {
            h1_prefetch(A, lda, Bm, ldb, (s + 2) * BK,
                        sb + st * STAGE, tid, m0, n0);
            CP_COMMIT();
        }
    }

    const int r0 = m0 + wm + (lane >> 2);
    const int c0 = n0 + wn + (lane & 3) * 2;
#pragma unroll
    for (int mi = 0; mi < 2; mi++) {
#pragma unroll
        for (int ni = 0; ni < 8; ni++) {
            int row = r0 + mi * 16;
            int col = c0 + ni * 8;
            const float* d = acc[mi][ni];
            float b0 = bias ? bias[col] : 0.f;
            float b1 = bias ? bias[col + 1] : 0.f;
            if (Cf) {
                if (row < M) {
                    Cf[(size_t)row * ldc + col]     = d[0] + b0;
                    Cf[(size_t)row * ldc + col + 1] = d[1] + b1;
                }
                if (row + 8 < M) {
                    Cf[(size_t)(row + 8) * ldc + col]     = d[2] + b0;
                    Cf[(size_t)(row + 8) * ldc + col + 1] = d[3] + b1;
                }
            } else {
                if (row < M) {
                    Ch[(size_t)row * ldc + col]     = __float2half_rn(d[0] + b0);
                    Ch[(size_t)row * ldc + col + 1] = __float2half_rn(d[1] + b1);
                }
                if (row + 8 < M) {
                    Ch[(size_t)(row + 8) * ldc + col]     = __float2half_rn(d[2] + b0);
                    Ch[(size_t)(row + 8) * ldc + col + 1] = __float2half_rn(d[3] + b1);
                }
            }
        }
    }
}

// ---------------------------------------------------------------------------
// Fused encoder recurrence step, k-lane packed FFMA2 inner loop.
// Also emits fp16 enc16 copy inline.
// ---------------------------------------------------------------------------
__global__ __launch_bounds__(256)
void enc_step_fused(int s,
                    const float* __restrict__ Wh_f,
                    const float* __restrict__ Wh_b,
                    const float* __restrict__ bh_f,
                    const float* __restrict__ bh_b) {
    constexpr int BK = 32;
    constexpr int LDA = BK + 4;   // 36 floats = 144B rows (16B aligned)
    __shared__ __align__(16) float As[64][LDA];
    __shared__ __align__(16) float Bs[48][LDA];
    const int tid = threadIdx.x;
    const int dir = blockIdx.y;
    const int j0 = blockIdx.x * 16;
    const float* hread = g_h[s & 1] + dir * (kB * kH);
    float* hwrite = g_h[(s + 1) & 1] + dir * (kB * kH);
    const float* Wh = dir ? Wh_b : Wh_f;
    const float* bh = dir ? bh_b : bh_f;
    const float* gxbase = dir ? g_gxb : g_gxf;
    const int gpos = dir ? (kS - 1 - s) : s;

    const int tm = (tid >> 4) << 2;   // 0..60, 4 rows/thread
    const int tn = tid & 15;          // gate column within 16-wide tile

    unsigned long long acc[4][3];
#pragma unroll
    for (int i = 0; i < 4; i++)
#pragma unroll
        for (int q = 0; q < 3; q++) acc[i][q] = 0ull;

    for (int k0 = 0; k0 < kH; k0 += BK) {
#pragma unroll
        for (int h = 0; h < 2; h++) {
            int id = tid + h * 256;
            int r = id >> 3, cc = (id & 7) << 2;
            *(float4*)&As[r][cc] =
                *(const float4*)(hread + (size_t)r * kH + k0 + cc);
        }
#pragma unroll
        for (int h = 0; h < 2; h++) {
            int id = tid + h * 256;
            if (id < 384) {
                int r = id >> 3, cc = (id & 7) << 2;
                int sec = r >> 4, wi = r & 15;
                *(float4*)&Bs[r][cc] = *(const float4*)(Wh +
                    (size_t)(sec * kH + j0 + wi) * kH + k0 + cc);
            }
        }
        __syncthreads();
#pragma unroll
        for (int k = 0; k < BK; k += 2) {
            unsigned long long b0 = *(const unsigned long long*)&Bs[tn][k];
            unsigned long long b1 = *(const unsigned long long*)&Bs[16 + tn][k];
            unsigned long long b2 = *(const unsigned long long*)&Bs[32 + tn][k];
#pragma unroll
            for (int i = 0; i < 4; i++) {
                unsigned long long a =
                    *(const unsigned long long*)&As[tm + i][k];
                fma2(acc[i][0], a, b0);
                fma2(acc[i][1], a, b1);
                fma2(acc[i][2], a, b2);
            }
        }
        __syncthreads();
    }

    const int j = j0 + tn;
    const float bhr = bh[j], bhz = bh[kH + j], bhn = bh[2 * kH + j];
#pragma unroll
    for (int i = 0; i < 4; i++) {
        int b = tm + i;
        float ghr = lo2(acc[i][0]) + hi2(acc[i][0]) + bhr;
        float ghz = lo2(acc[i][1]) + hi2(acc[i][1]) + bhz;
        float ghn = lo2(acc[i][2]) + hi2(acc[i][2]) + bhn;
        const float* gx = gxbase + ((size_t)gpos * kB + b) * kG;
        float r = 1.f / (1.f + expf(-(gx[j] + ghr)));
        float z = 1.f / (1.f + expf(-(gx[kH + j] + ghz)));
        float n = tanhf(gx[2 * kH + j] + r * ghn);
        float hold = hread[(size_t)b * kH + j];
        float h2 = (1.f - z) * n + z * hold;
        hwrite[(size_t)b * kH + j] = h2;
        size_t eo = ((size_t)b * kS + gpos) * (2 * kH) + dir * kH + j;
        g_enc[eo] = h2;
        g_enc16[eo] = __float2half_rn(h2);
    }
}

// ---------------------------------------------------------------------------
// Small-M GEMM body (FFMA2)
// ---------------------------------------------------------------------------
__device__ __forceinline__
void gemm64_body(const float* __restrict__ A, int lda,
                 const float* __restrict__ Bm, int ldb,
                 const float* __restrict__ bias,
                 float* __restrict__ C, int ldc,
                 int K, int act, int nb) {
    constexpr int BK = 32;
    __shared__ __align__(16) float As[BK][64];
    __shared__ __align__(16) float Bs[BK][64];
    const int tid = threadIdx.x;
    const int bn = nb * 64;
    const int lr = tid >> 3;
    const int lc = (tid & 7) << 2;
    const int tm = (tid >> 4) << 2;
    const int tn = (tid & 15) << 2;

    unsigned long long acc[4][2];
#pragma unroll
    for (int i = 0; i < 4; i++) { acc[i][0] = 0ull; acc[i][1] = 0ull; }

    for (int k0 = 0; k0 < K; k0 += BK) {
#pragma unroll
        for (int h = 0; h < 2; h++) {
            int r = lr + h * 32;
            float4 v = *(const float4*)(A + (size_t)r * lda + k0 + lc);
            As[lc + 0][r] = v.x; As[lc + 1][r] = v.y;
            As[lc + 2][r] = v.z; As[lc + 3][r] = v.w;
            float4 w = *(const float4*)(Bm + (size_t)(bn + r) * ldb + k0 + lc);
            Bs[lc + 0][r] = w.x; Bs[lc + 1][r] = w.y;
            Bs[lc + 2][r] = w.z; Bs[lc + 3][r] = w.w;
        }
        __syncthreads();
#pragma unroll
        for (int k = 0; k < BK; k++) {
            float4 af = *(const float4*)&As[k][tm];
            unsigned long long aa[4];
            aa[0] = pk2(af.x); aa[1] = pk2(af.y);
            aa[2] = pk2(af.z); aa[3] = pk2(af.w);
            ulonglong2 bv = *(const ulonglong2*)&Bs[k][tn];
#pragma unroll
            for (int i = 0; i < 4; i++) {
                fma2(acc[i][0], aa[i], bv.x);
                fma2(acc[i][1], aa[i], bv.y);
            }
        }
        __syncthreads();
    }
#pragma unroll
    for (int i = 0; i < 4; i++) {
        int col = bn + tn;
        float4 v;
        v.x = lo2(acc[i][0]); v.y = hi2(acc[i][0]);
        v.z = lo2(acc[i][1]); v.w = hi2(acc[i][1]);
        if (bias) {
            v.x += bias[col + 0]; v.y += bias[col + 1];
            v.z += bias[col + 2]; v.w += bias[col + 3];
        }
        if (act == 1) {
            v.x = tanhf(v.x); v.y = tanhf(v.y);
            v.z = tanhf(v.z); v.w = tanhf(v.w);
        }
        *(float4*)(C + (size_t)(tm + i) * ldc + col) = v;
    }
}

__global__ __launch_bounds__(256)
void gemm64(const float* __restrict__ A, int lda,
            const float* __restrict__ Bm, int ldb,
            const float* __restrict__ bias,
            float* __restrict__ C, int ldc, int K, int act) {
    gemm64_body(A, lda, Bm, ldb, bias, C, ldc, K, act, blockIdx.x);
}

// Decoder pre-attention GEMMs, K-split 2: hp (32 blocks) + ghd (96 blocks)
__global__ __launch_bounds__(256)
void dec_pre_gemm(const float* __restrict__ W_attn,
                  const float* __restrict__ Wh_d,
                  const float* __restrict__ bh_d) {
    int x = blockIdx.x;
    if (x < 32) {
        int ks = x >> 4, nb = x & 15;
        gemm64_body(g_hdec + ks * 512, kH, W_attn + ks * 512, kG, nullptr,
                    g_hp + (size_t)ks * kB * kH, kH, 512, 0, nb);
    } else {
        int i = x - 32;
        int ks = i / 48, nb = i % 48;
        gemm64_body(g_hdec + ks * 512, kH, Wh_d + ks * 512, kH,
                    ks == 0 ? bh_d : nullptr,
                    g_ghd + (size_t)ks * kB * kG, kG, 512, 0, nb);
    }
}

// ---------------------------------------------------------------------------
__global__ void hcat_kernel() {
    int idx = blockIdx.x * blockDim.x + threadIdx.x;
    if (idx >= 2 * kB * kH) return;
    int dir = idx / (kB * kH);
    int rem = idx - dir * (kB * kH);
    int b = rem / kH, j = rem - b * kH;
    g_hcat[(size_t)b * 2 * kH + dir * kH + j] = g_h[0][idx];
}

// ---------------------------------------------------------------------------
// Fully fused decoder step — fp16 streamed operands (round-15 proven).
// ---------------------------------------------------------------------------
__global__ __launch_bounds__(512)
void attn_step_fused(const int* __restrict__ src,
                     const float* __restrict__ v_attn,
                     const float* __restrict__ gxet_t,
                     float* __restrict__ feat_t) {
    int b = blockIdx.x;
    __shared__ float sc[kS];
    __shared__ float sgxw[kG];
    int tid = threadIdx.x, warp = tid >> 5, lane = tid & 31;
    const float* hp0 = g_hp + (size_t)b * kH;
    const float* hp1 = g_hp + (size_t)kB * kH + (size_t)b * kH;

    for (int s = warp; s < kS; s += 16) {
        const __half2* ep = (const __half2*)(g_ep16 + ((size_t)b * kS + s) * kH);
        float p = 0.f;
        for (int j2 = lane; j2 < kH / 2; j2 += 32) {
            float2 e = __half22float2(ep[j2]);
            float2 a0 = ((const float2*)hp0)[j2];
            float2 a1 = ((const float2*)hp1)[j2];
            float2 va = ((const float2*)v_attn)[j2];
            p += va.x * tanhf(a0.x + a1.x + e.x);
            p += va.y * tanhf(a0.y + a1.y + e.y);
        }
#pragma unroll
        for (int o = 16; o; o >>= 1) p += __shfl_xor_sync(0xffffffffu, p, o);
        if (lane == 0) sc[s] = (src[s * kB + b] != kPAD) ? p : -1e10f;
    }
    __syncthreads();

    if (tid < 32) {
        float v1 = sc[tid];
        float v2 = (tid + 32 < kS) ? sc[tid + 32] : -1e30f;
        float mx = fmaxf(v1, v2);
#pragma unroll
        for (int o = 16; o; o >>= 1) mx = fmaxf(mx, __shfl_xor_sync(0xffffffffu, mx, o));
        float e1 = expf(v1 - mx);
        float e2 = (tid + 32 < kS) ? expf(v2 - mx) : 0.f;
        float sm = e1 + e2;
#pragma unroll
        for (int o = 16; o; o >>= 1) sm += __shfl_xor_sync(0xffffffffu, sm, o);
        float inv = 1.f / sm;
        sc[tid] = e1 * inv;
        if (tid + 32 < kS) sc[tid + 32] = e2 * inv;
    }
    __syncthreads();

    for (int c8 = tid; c8 < 2 * kH / 8; c8 += 512) {
        float acc[8];
#pragma unroll
        for (int q = 0; q < 8; q++) acc[q] = 0.f;
        const uint4* base = (const uint4*)(g_enc16 + (size_t)b * kS * 2 * kH) + c8;
#pragma unroll 4
        for (int s = 0; s < kS; s++) {
            uint4 v = base[s * (2 * kH / 8)];
            float a = sc[s];
            __half2 p0 = *reinterpret_cast<__half2*>(&v.x);
            __half2 p1 = *reinterpret_cast<__half2*>(&v.y);
            __half2 p2 = *reinterpret_cast<__half2*>(&v.z);
            __half2 p3 = *reinterpret_cast<__half2*>(&v.w);
            float2 f0 = __half22float2(p0), f1 = __half22float2(p1);
            float2 f2 = __half22float2(p2), f3 = __half22float2(p3);
            acc[0] += a * f0.x; acc[1] += a * f0.y;
            acc[2] += a * f1.x; acc[3] += a * f1.y;
            acc[4] += a * f2.x; acc[5] += a * f2.y;
            acc[6] += a * f3.x; acc[7] += a * f3.y;
        }
        float* dst = feat_t + (size_t)b * kF + kH + c8 * 8;
        *(float4*)dst = make_float4(acc[0], acc[1], acc[2], acc[3]);
        *(float4*)(dst + 4) = make_float4(acc[4], acc[5], acc[6], acc[7]);
    }
    for (int c8 = tid; c8 < kG / 8; c8 += 512) {
        float acc[8];
#pragma unroll
        for (int q = 0; q < 8; q++) acc[q] = 0.f;
        const uint4* base = (const uint4*)(g_encWi16 + (size_t)b * kS * kG) + c8;
#pragma unroll 4
        for (int s = 0; s < kS; s++) {
            uint4 v = base[s * (kG / 8)];
            float a = sc[s];
            __half2 p0 = *reinterpret_cast<__half2*>(&v.x);
            __half2 p1 = *reinterpret_cast<__half2*>(&v.y);
            __half2 p2 = *reinterpret_cast<__half2*>(&v.z);
            __half2 p3 = *reinterpret_cast<__half2*>(&v.w);
            float2 f0 = __half22float2(p0), f1 = __half22float2(p1);
            float2 f2 = __half22float2(p2), f3 = __half22float2(p3);
            acc[0] += a * f0.x; acc[1] += a * f0.y;
            acc[2] += a * f1.x; acc[3] += a * f1.y;
            acc[4] += a * f2.x; acc[5] += a * f2.y;
            acc[6] += a * f3.x; acc[7] += a * f3.y;
        }
        float* dst = sgxw + c8 * 8;
        *(float4*)dst = make_float4(acc[0], acc[1], acc[2], acc[3]);
        *(float4*)(dst + 4) = make_float4(acc[4], acc[5], acc[6], acc[7]);
    }
    __syncthreads();

    const float* q0 = g_ghd + (size_t)b * kG;
    const float* q1 = g_ghd + (size_t)kB * kG + (size_t)b * kG;
    const float* gx = gxet_t + (size_t)b * kG;
    for (int j = tid; j < kH; j += 512) {
        float h = g_hdec[(size_t)b * kH + j];
        float xr = gx[j] + sgxw[j];
        float xz = gx[kH + j] + sgxw[kH + j];
        float xn = gx[2 * kH + j] + sgxw[2 * kH + j];
        float ghr = q0[j] + q1[j];
        float ghz = q0[kH + j] + q1[kH + j];
        float ghn = q0[2 * kH + j] + q1[2 * kH + j];
        float r = 1.f / (1.f + expf(-(xr + ghr)));
        float z = 1.f / (1.f + expf(-(xz + ghz)));
        float n = tanhf(xn + r * ghn);
        float h2 = (1.f - z) * n + z * h;
        g_hdec[(size_t)b * kH + j] = h2;
        feat_t[(size_t)b * kF + j] = h2;
    }
}

// ---------------------------------------------------------------------------
// Host orchestration (two-stream fork/join, graph-capturable)
// ---------------------------------------------------------------------------
extern "C" void kernel_launch(void* const* d_in, const int* in_sizes, int n_in,
                              void* d_out, int out_size) {
    const int*   src     = (const int*)d_in[0];
    const int*   trg     = (const int*)d_in[1];
    const float* emb_enc = (const float*)d_in[2];
    const float* Wi_f    = (const float*)d_in[3];
    const float* Wh_f    = (const float*)d_in[4];
    const float* bi_f    = (const float*)d_in[5];
    const float* bh_f    = (const float*)d_in[6];
    const float* Wi_b    = (const float*)d_in[7];
    const float* Wh_b    = (const float*)d_in[8];
    const float* bi_b    = (const float*)d_in[9];
    const float* bh_b    = (const float*)d_in[10];
    const float* W_fc    = (const float*)d_in[11];
    const float* b_fc    = (const float*)d_in[12];
    const float* W_attn  = (const float*)d_in[13];
    const float* b_attn  = (const float*)d_in[14];
    const float* v_attn  = (const float*)d_in[15];
    const float* emb_dec = (const float*)d_in[16];
    const float* Wi_d    = (const float*)d_in[17];
    const float* Wh_d    = (const float*)d_in[18];
    const float* bi_d    = (const float*)d_in[19];
    const float* bh_d    = (const float*)d_in[20];
    const float* W_out   = (const float*)d_in[21];
    const float* b_out   = (const float*)d_in[22];
    float* out = (float*)d_out;

    float *p_hcat, *p_hdec, *p_gxet, *p_feat, *p_gxf, *p_gxb;
    __nv_bfloat16 *p_Ahi, *p_Alo, *p_Ehi, *p_Elo;
    __nv_bfloat16 *p_Wifh, *p_Wifl, *p_Wibh, *p_Wibl, *p_Widh, *p_Widl;
    __half *p_Fh, *p_Bf16, *p_Wid16, *p_Wa16, *p_encWi16, *p_enc16, *p_ep16;
    cudaGetSymbolAddress((void**)&p_hcat, g_hcat);
    cudaGetSymbolAddress((void**)&p_hdec, g_hdec);
    cudaGetSymbolAddress((void**)&p_gxet, g_gxet);
    cudaGetSymbolAddress((void**)&p_feat, g_feat);
    cudaGetSymbolAddress((void**)&p_gxf, g_gxf);
    cudaGetSymbolAddress((void**)&p_gxb, g_gxb);
    cudaGetSymbolAddress((void**)&p_Ahi, g_Ahi);
    cudaGetSymbolAddress((void**)&p_Alo, g_Alo);
    cudaGetSymbolAddress((void**)&p_Ehi, g_Ehi);
    cudaGetSymbolAddress((void**)&p_Elo, g_Elo);
    cudaGetSymbolAddress((void**)&p_Wifh, g_Wifh);
    cudaGetSymbolAddress((void**)&p_Wifl, g_Wifl);
    cudaGetSymbolAddress((void**)&p_Wibh, g_Wibh);
    cudaGetSymbolAddress((void**)&p_Wibl, g_Wibl);
    cudaGetSymbolAddress((void**)&p_Widh, g_Widh);
    cudaGetSymbolAddress((void**)&p_Widl, g_Widl);
    cudaGetSymbolAddress((void**)&p_Fh, g_Fh);
    cudaGetSymbolAddress((void**)&p_Bf16, g_Bf16);
    cudaGetSymbolAddress((void**)&p_Wid16, g_Wid16);
    cudaGetSymbolAddress((void**)&p_Wa16, g_Wa16);
    cudaGetSymbolAddress((void**)&p_encWi16, g_encWi16);
    cudaGetSymbolAddress((void**)&p_enc16, g_enc16);
    cudaGetSymbolAddress((void**)&p_ep16, g_ep16);

    static cudaStream_t s1 = nullptr;
    static cudaEvent_t evFork = nullptr, evJoin = nullptr;
    if (s1 == nullptr) {
        cudaStreamCreateWithFlags(&s1, cudaStreamNonBlocking);
        cudaEventCreateWithFlags(&evFork, cudaEventDisableTiming);
        cudaEventCreateWithFlags(&evJoin, cudaEventDisableTiming);
        cudaFuncSetAttribute(hgemm,
                             cudaFuncAttributeMaxDynamicSharedMemorySize,
                             outg::SMEM_SZ);
        cudaFuncSetAttribute(hgemm1,
                             cudaFuncAttributeMaxDynamicSharedMemorySize,
                             out1::SMEM_SZ);
    }

    // fork side stream off the capture stream
    cudaEventRecord(evFork, 0);
    cudaStreamWaitEvent(s1, evFork, 0);

    // --- main stream: encoder-critical path ---
    init_kernel<<<((size_t)kB * kV + 255) / 256, 256>>>(out);
    enc_embed_kernel<<<kME, 128>>>(src, emb_enc);
    {
        size_t n4 = (size_t)kG * kE / 4;
        cvt_split4<<<(unsigned)((n4 + 255) / 256), 256>>>(
            (const float4*)Wi_f, (__nv_bfloat162*)p_Wifh,
            (__nv_bfloat162*)p_Wifl, n4);
        cvt_split4<<<(unsigned)((n4 + 255) / 256), 256>>>(
            (const float4*)Wi_b, (__nv_bfloat162*)p_Wibh,
            (__nv_bfloat162*)p_Wibl, n4);
    }
    // --- side stream: decoder-prep + weight conversions ---
    dec_embed_all<<<kMR, 128, 0, s1>>>(trg, emb_dec);
    // --- main: input-gate GEMMs ---
    hgemm<<<dim3(kME / 128, kG / 128), 256, outg::SMEM_SZ>>>(
        p_Ehi, p_Elo, kE, p_Wifh, p_Wifl, kE, bi_f, p_gxf, kG, kME, kE);
    hgemm<<<dim3(kME / 128, kG / 128), 256, outg::SMEM_SZ>>>(
        p_Ehi, p_Elo, kE, p_Wibh, p_Wibl, kE, bi_b, p_gxb, kG, kME, kE);
    // --- side stream continues ---
    {
        size_t n4 = (size_t)kG * kXW / 4;
        cvt_split4<<<(unsigned)((n4 + 255) / 256), 256, 0, s1>>>(
            (const float4*)Wi_d, (__nv_bfloat162*)p_Widh,
            (__nv_bfloat162*)p_Widl, n4);
        cvt16_4<<<(unsigned)((n4 + 255) / 256), 256, 0, s1>>>(
            (const float4*)Wi_d, (__half2*)p_Wid16, n4);
        n4 = (size_t)kH * kG / 4;
        cvt16_4<<<(unsigned)((n4 + 255) / 256), 256, 0, s1>>>(
            (const float4*)W_attn, (__half2*)p_Wa16, n4);
        hgemm<<<dim3(kMP / 128, kG / 128), 256, outg::SMEM_SZ, s1>>>(
            p_Ahi + 3 * kH, p_Alo + 3 * kH, kF, p_Widh, p_Widl, kXW, bi_d,
            p_gxet, kG, kMR, kE);
        n4 = (size_t)kV * kF / 4;
        cvt16_4<<<(unsigned)((n4 + 255) / 256), 256, 0, s1>>>(
            (const float4*)W_out, (__half2*)p_Bf16, n4);
    }
    cudaEventRecord(evJoin, s1);

    // --- main: encoder recurrence (emits enc + enc16; overlaps side stream)
    for (int s = 0; s < kS; s++)
        enc_step_fused<<<dim3(64, 2), 256>>>(s, Wh_f, Wh_b, bh_f, bh_b);

    // decoder init hidden
    hcat_kernel<<<(2 * kB * kH) / 256, 256>>>();
    gemm64<<<kH / 64, 256>>>(p_hcat, 2 * kH, W_fc, 2 * kH, b_fc,
                             p_hdec, kH, 2 * kH, 1);

    // attention projection + encWi — single-pass fp16 GEMMs, fp16 output
    cudaStreamWaitEvent(0, evJoin, 0);
    hgemm1<<<dim3(kME / 128, kH / 128), 256, out1::SMEM_SZ>>>(
        p_enc16, 2 * kH, p_Wa16 + kH, kG, b_attn,
        (float*)nullptr, p_ep16, kH, kME, 2 * kH);
    hgemm1<<<dim3(kME / 128, kG / 128), 256, out1::SMEM_SZ>>>(
        p_enc16, 2 * kH, p_Wid16 + kE, kXW, (const float*)nullptr,
        (float*)nullptr, p_encWi16, kG, kME, 2 * kH);

    // decoder loop: 2 launches per step
    for (int t = 0; t < kT - 1; t++) {
        float* feat_t = p_feat + (size_t)t * kB * kF;
        dec_pre_gemm<<<128, 256>>>(W_attn, Wh_d, bh_d);
        attn_step_fused<<<kB, 512>>>(src, v_attn,
                                     p_gxet + (size_t)t * kB * kG, feat_t);
    }

    // fp16-convert features, single-pass fp16 output projection
    {
        size_t n = (size_t)kMP * kF / 4;
        cvt_feat16<<<(unsigned)((n + 255) / 256), 256>>>();
        hgemm1<<<dim3(kMP / 128, kV / 128), 256, out1::SMEM_SZ>>>(
            p_Fh, kF, p_Bf16, kF, b_out,
            out + (size_t)kB * kV, (__half*)nullptr, kV, kMR, kF);
    }
}

// round 17
// speedup vs baseline: 1.7094x; 1.1009x over previous
#include <cuda_runtime.h>
#include <cuda_fp16.h>
#include <math.h>
#include <stdint.h>

// ---------------------------------------------------------------------------
// Problem constants
// ---------------------------------------------------------------------------
namespace {
constexpr int kS = 48;          // source length
constexpr int kT = 32;          // target length
constexpr int kB = 64;          // batch
constexpr int kH = 1024;        // hidden
constexpr int kE = 512;         // embed
constexpr int kV = 32000;       // vocab
constexpr int kG = 3 * kH;      // 3072 gates
constexpr int kF = 3 * kH + kE; // 3584 out-proj features
constexpr int kXW = kE + 2*kH;  // 2560 decoder GRU input width
constexpr int kPAD = 1;
constexpr int kMR = (kT - 1) * kB; // 1984 output rows
constexpr int kMP = 2048;          // padded rows for tensor GEMM
constexpr int kME = kS * kB;       // 3072 encoder rows
}

// ---------------------------------------------------------------------------
// Packed fp32x2 helpers (FFMA2)
// ---------------------------------------------------------------------------
__device__ __forceinline__ unsigned long long pk2(float x) {
    unsigned long long r;
    unsigned u = __float_as_uint(x);
    asm("mov.b64 %0, {%1, %1};" : "=l"(r) : "r"(u));
    return r;
}
__device__ __forceinline__ void fma2(unsigned long long& d,
                                     unsigned long long a,
                                     unsigned long long b) {
    asm("fma.rn.f32x2 %0, %1, %2, %0;" : "+l"(d) : "l"(a), "l"(b));
}
__device__ __forceinline__ float lo2(unsigned long long v) {
    return __uint_as_float((unsigned)v);
}
__device__ __forceinline__ float hi2(unsigned long long v) {
    return __uint_as_float((unsigned)(v >> 32));
}

// ---------------------------------------------------------------------------
// Plain-PTX helpers: cp.async / ldmatrix / mma.sync (fp16)
// ---------------------------------------------------------------------------
__device__ __forceinline__ uint32_t smem_u32(const void* p) {
    uint32_t a;
    asm("{ .reg .u64 t; cvta.to.shared.u64 t, %1; cvt.u32.u64 %0, t; }"
        : "=r"(a) : "l"(p));
    return a;
}
#define CP_ASYNC16(dst, src) \
    asm volatile("cp.async.cg.shared.global [%0], [%1], 16;" \
                 :: "r"(dst), "l"(src) : "memory")
#define CP_COMMIT() asm volatile("cp.async.commit_group;" ::: "memory")
#define CP_WAIT1()  asm volatile("cp.async.wait_group 1;" ::: "memory")
#define CP_WAIT0()  asm volatile("cp.async.wait_group 0;" ::: "memory")

__device__ __forceinline__ void ldsm4(uint32_t* r, uint32_t addr) {
    asm volatile("ldmatrix.sync.aligned.m8n8.x4.shared.b16 {%0,%1,%2,%3}, [%4];"
                 : "=r"(r[0]), "=r"(r[1]), "=r"(r[2]), "=r"(r[3])
                 : "r"(addr));
}
__device__ __forceinline__ void mma16816h(float* d, const uint32_t* a,
                                          const uint32_t* b) {
    asm volatile(
        "mma.sync.aligned.m16n8k16.row.col.f32.f16.f16.f32 "
        "{%0,%1,%2,%3}, {%4,%5,%6,%7}, {%8,%9}, {%0,%1,%2,%3};"
        : "+f"(d[0]), "+f"(d[1]), "+f"(d[2]), "+f"(d[3])
        : "r"(a[0]), "r"(a[1]), "r"(a[2]), "r"(a[3]),
          "r"(b[0]), "r"(b[1]));
}

// ---------------------------------------------------------------------------
// Persistent scratch
// ---------------------------------------------------------------------------
__device__ float g_gxf[(size_t)kME * kG];
__device__ float g_gxb[(size_t)kME * kG];
__device__ float g_h[2][2 * kB * kH];              // double-buffered h_f|h_b
__device__ float g_hcat[kB * 2 * kH];
__device__ float g_hdec[kB * kH];
__device__ float g_hp[2 * kB * kH];                // 2 K-partials
__device__ float g_ghd[2 * kB * kG];               // 2 K-partials
__device__ float g_gxet[(size_t)kMR * kG];
__device__ float g_feat[(size_t)kMR * kF];         // [h2, w, et] per step
// fp16 operands (single precision level, calibrated safe)
__device__ __half g_Eh16[(size_t)kME * kE];        // encoder embeddings fp16
__device__ __half g_Wif16[(size_t)kG * kE];        // Wi_f fp16
__device__ __half g_Wib16[(size_t)kG * kE];        // Wi_b fp16
__device__ __half g_Fh[(size_t)kMP * kF];          // feat fp16 (et cols early)
__device__ __half g_Bf16[(size_t)kV * kF];         // W_out fp16
__device__ __half g_Wid16[(size_t)kG * kXW];       // Wi_d fp16
__device__ __half g_Wa16[(size_t)kH * kG];         // W_attn fp16
__device__ __half g_encWi16[(size_t)kME * kG];
__device__ __half g_enc16[(size_t)kME * 2 * kH];
__device__ __half g_ep16[(size_t)kME * kH];

// ---------------------------------------------------------------------------
__global__ void init_kernel(float* __restrict__ out0) {
    size_t i = (size_t)blockIdx.x * blockDim.x + threadIdx.x;
    if (i < (size_t)kB * kV) out0[i] = 0.f;
    if (i < (size_t)2 * kB * kH) g_h[0][i] = 0.f;
}

// encoder embedding gather -> fp16
__global__ void enc_embed_kernel(const int* __restrict__ src,
                                 const float* __restrict__ table) {
    int row = blockIdx.x;
    int tok = src[row];
    float4 v = ((const float4*)(table + (size_t)tok * kE))[threadIdx.x];
    __half2* dst = (__half2*)(g_Eh16 + (size_t)row * kE) + threadIdx.x * 2;
    dst[0] = __floats2half2_rn(v.x, v.y);
    dst[1] = __floats2half2_rn(v.z, v.w);
}

// decoder embeddings -> feat fp32 + g_Fh fp16 et columns
__global__ void dec_embed_all(const int* __restrict__ trg,
                              const float* __restrict__ emb_dec) {
    int row = blockIdx.x;
    int tok = trg[row];
    float4 v = ((const float4*)(emb_dec + (size_t)tok * kE))[threadIdx.x];
    ((float4*)(g_feat + (size_t)row * kF + 3 * kH))[threadIdx.x] = v;
    __half2* dst = (__half2*)(g_Fh + (size_t)row * kF + 3 * kH) + threadIdx.x * 2;
    dst[0] = __floats2half2_rn(v.x, v.y);
    dst[1] = __floats2half2_rn(v.z, v.w);
}

// fp32 -> single fp16 conversion (4 elements/thread)
__global__ void cvt16_4(const float4* __restrict__ src,
                        __half2* __restrict__ dst, size_t n4) {
    size_t i = (size_t)blockIdx.x * blockDim.x + threadIdx.x;
    if (i >= n4) return;
    float4 v = src[i];
    dst[2 * i]     = __floats2half2_rn(v.x, v.y);
    dst[2 * i + 1] = __floats2half2_rn(v.z, v.w);
}

// convert ALL feat columns to single fp16 (padded rows zeroed)
__global__ void cvt_feat16() {
    size_t i = (size_t)blockIdx.x * blockDim.x + threadIdx.x;
    if (i >= (size_t)kMP * kF / 4) return;
    size_t row = i / (kF / 4);
    size_t col = (i % (kF / 4)) * 4;
    float4 v = make_float4(0.f, 0.f, 0.f, 0.f);
    if (row < (size_t)kMR)
        v = *(const float4*)(g_feat + row * kF + col);
    __half2* dst = (__half2*)(g_Fh + row * kF + col);
    dst[0] = __floats2half2_rn(v.x, v.y);
    dst[1] = __floats2half2_rn(v.z, v.w);
}

// ---------------------------------------------------------------------------
// Single-pass fp16 HMMA GEMM: C = A[M,K] * B[N,K]^T + bias.
// Output either fp32 (Cf) or fp16 (Ch) — exactly one non-null.
// Tile 128x128x64, 2 smem sections per stage, 2-stage cp.async.
// ---------------------------------------------------------------------------
namespace out1 {
constexpr int BM = 128, BN = 128, BK = 64;
constexpr int HALF = 16384;
constexpr int STAGE = 2 * HALF;             // 32768
constexpr int SMEM_SZ = 2 * STAGE;          // 65536
}

__device__ __forceinline__ void h1_prefetch(
    const __half* __restrict__ A, int lda,
    const __half* __restrict__ Bm, int ldb,
    int k0, uint32_t buf, int tid, int m0, int n0) {
    using namespace out1;
#pragma unroll
    for (int i = 0; i < 4; i++) {
        int id = tid + i * 256;
        int row = id >> 3, c = id & 7;
        uint32_t off = (uint32_t)(row << 7) + (c << 4);
        uint32_t sw = off ^ ((off >> 3) & 0x70);
        size_t ga = (size_t)(m0 + row) * lda + k0 + c * 8;
        size_t gb = (size_t)(n0 + row) * ldb + k0 + c * 8;
        CP_ASYNC16(buf + sw, A + ga);
        CP_ASYNC16(buf + HALF + sw, Bm + gb);
    }
}

__device__ __forceinline__ void h1_compute(uint32_t buf, int lane,
                                           int wm, int wn,
                                           float acc[2][8][4]) {
    using namespace out1;
    const int g = lane >> 3, r = lane & 7;
#pragma unroll
    for (int ks = 0; ks < 4; ks++) {
        uint32_t af[2][4];
#pragma unroll
        for (int mi = 0; mi < 2; mi++) {
            int row = wm + mi * 16 + ((g & 1) << 3) + r;
            int chunk = ks * 2 + (g >> 1);
            uint32_t off = (uint32_t)(row << 7) + (chunk << 4);
            uint32_t sw = off ^ ((off >> 3) & 0x70);
            ldsm4(af[mi], buf + sw);
        }
        uint32_t bf[4][4];
#pragma unroll
        for (int np = 0; np < 4; np++) {
            int row = wn + np * 16 + ((g >> 1) << 3) + r;
            int chunk = ks * 2 + (g & 1);
            uint32_t off = (uint32_t)(row << 7) + (chunk << 4);
            uint32_t sw = off ^ ((off >> 3) & 0x70);
            ldsm4(bf[np], buf + HALF + sw);
        }
#pragma unroll
        for (int mi = 0; mi < 2; mi++) {
#pragma unroll
            for (int np = 0; np < 4; np++) {
#pragma unroll
                for (int a = 0; a < 2; a++) {
                    mma16816h(acc[mi][np * 2 + a], af[mi], &bf[np][2 * a]);
                }
            }
        }
    }
}

__global__ __launch_bounds__(256, 1)
void hgemm1(const __half* __restrict__ A, int lda,
            const __half* __restrict__ Bm, int ldb,
            const float* __restrict__ bias,
            float* __restrict__ Cf, __half* __restrict__ Ch, int ldc,
            int M, int K) {
    using namespace out1;
    extern __shared__ char smem[];
    const uint32_t sb = smem_u32(smem);
    const int tid = threadIdx.x;
    const int wid = tid >> 5, lane = tid & 31;
    const int m0 = blockIdx.x * BM;
    const int n0 = blockIdx.y * BN;
    const int wm = (wid & 3) * 32;
    const int wn = (wid >> 2) * 64;
    const int nslab = K / BK;

    float acc[2][8][4];
#pragma unroll
    for (int i = 0; i < 2; i++)
#pragma unroll
        for (int j = 0; j < 8; j++)
#pragma unroll
            for (int q = 0; q < 4; q++) acc[i][j][q] = 0.f;

    h1_prefetch(A, lda, Bm, ldb, 0, sb, tid, m0, n0);
    CP_COMMIT();
    h1_prefetch(A, lda, Bm, ldb, BK, sb + STAGE, tid, m0, n0);
    CP_COMMIT();

    for (int s = 0; s < nslab; s++) {
        const int st = s & 1;
        if (s == nslab - 1) { CP_WAIT0(); } else { CP_WAIT1(); }
        __syncthreads();
        h1_compute(sb + st * STAGE, lane, wm, wn, acc);
        __syncthreads();
        if (s + 2 < nslab) {
            h1_prefetch(A, lda, Bm, ldb, (s + 2) * BK,
                        sb + st * STAGE, tid, m0, n0);
            CP_COMMIT();
        }
    }

    const int r0 = m0 + wm + (lane >> 2);
    const int c0 = n0 + wn + (lane & 3) * 2;
#pragma unroll
    for (int mi = 0; mi < 2; mi++) {
#pragma unroll
        for (int ni = 0; ni < 8; ni++) {
            int row = r0 + mi * 16;
            int col = c0 + ni * 8;
            const float* d = acc[mi][ni];
            float b0 = bias ? bias[col] : 0.f;
            float b1 = bias ? bias[col + 1] : 0.f;
            if (Cf) {
                if (row < M) {
                    Cf[(size_t)row * ldc + col]     = d[0] + b0;
                    Cf[(size_t)row * ldc + col + 1] = d[1] + b1;
                }
                if (row + 8 < M) {
                    Cf[(size_t)(row + 8) * ldc + col]     = d[2] + b0;
                    Cf[(size_t)(row + 8) * ldc + col + 1] = d[3] + b1;
                }
            } else {
                if (row < M) {
                    Ch[(size_t)row * ldc + col]     = __float2half_rn(d[0] + b0);
                    Ch[(size_t)row * ldc + col + 1] = __float2half_rn(d[1] + b1);
                }
                if (row + 8 < M) {
                    Ch[(size_t)(row + 8) * ldc + col]     = __float2half_rn(d[2] + b0);
                    Ch[(size_t)(row + 8) * ldc + col + 1] = __float2half_rn(d[3] + b1);
                }
            }
        }
    }
}

// ---------------------------------------------------------------------------
// Fused encoder recurrence step, k-lane packed FFMA2 inner loop.
// Emits fp16 enc16 directly (fp32 enc master no longer needed).
// ---------------------------------------------------------------------------
__global__ __launch_bounds__(256)
void enc_step_fused(int s,
                    const float* __restrict__ Wh_f,
                    const float* __restrict__ Wh_b,
                    const float* __restrict__ bh_f,
                    const float* __restrict__ bh_b) {
    constexpr int BK = 32;
    constexpr int LDA = BK + 4;   // 36 floats = 144B rows (16B aligned)
    __shared__ __align__(16) float As[64][LDA];
    __shared__ __align__(16) float Bs[48][LDA];
    const int tid = threadIdx.x;
    const int dir = blockIdx.y;
    const int j0 = blockIdx.x * 16;
    const float* hread = g_h[s & 1] + dir * (kB * kH);
    float* hwrite = g_h[(s + 1) & 1] + dir * (kB * kH);
    const float* Wh = dir ? Wh_b : Wh_f;
    const float* bh = dir ? bh_b : bh_f;
    const float* gxbase = dir ? g_gxb : g_gxf;
    const int gpos = dir ? (kS - 1 - s) : s;

    const int tm = (tid >> 4) << 2;   // 0..60, 4 rows/thread
    const int tn = tid & 15;          // gate column within 16-wide tile

    unsigned long long acc[4][3];
#pragma unroll
    for (int i = 0; i < 4; i++)
#pragma unroll
        for (int q = 0; q < 3; q++) acc[i][q] = 0ull;

    for (int k0 = 0; k0 < kH; k0 += BK) {
#pragma unroll
        for (int h = 0; h < 2; h++) {
            int id = tid + h * 256;
            int r = id >> 3, cc = (id & 7) << 2;
            *(float4*)&As[r][cc] =
                *(const float4*)(hread + (size_t)r * kH + k0 + cc);
        }
#pragma unroll
        for (int h = 0; h < 2; h++) {
            int id = tid + h * 256;
            if (id < 384) {
                int r = id >> 3, cc = (id & 7) << 2;
                int sec = r >> 4, wi = r & 15;
                *(float4*)&Bs[r][cc] = *(const float4*)(Wh +
                    (size_t)(sec * kH + j0 + wi) * kH + k0 + cc);
            }
        }
        __syncthreads();
#pragma unroll
        for (int k = 0; k < BK; k += 2) {
            unsigned long long b0 = *(const unsigned long long*)&Bs[tn][k];
            unsigned long long b1 = *(const unsigned long long*)&Bs[16 + tn][k];
            unsigned long long b2 = *(const unsigned long long*)&Bs[32 + tn][k];
#pragma unroll
            for (int i = 0; i < 4; i++) {
                unsigned long long a =
                    *(const unsigned long long*)&As[tm + i][k];
                fma2(acc[i][0], a, b0);
                fma2(acc[i][1], a, b1);
                fma2(acc[i][2], a, b2);
            }
        }
        __syncthreads();
    }

    const int j = j0 + tn;
    const float bhr = bh[j], bhz = bh[kH + j], bhn = bh[2 * kH + j];
#pragma unroll
    for (int i = 0; i < 4; i++) {
        int b = tm + i;
        float ghr = lo2(acc[i][0]) + hi2(acc[i][0]) + bhr;
        float ghz = lo2(acc[i][1]) + hi2(acc[i][1]) + bhz;
        float ghn = lo2(acc[i][2]) + hi2(acc[i][2]) + bhn;
        const float* gx = gxbase + ((size_t)gpos * kB + b) * kG;
        float r = 1.f / (1.f + expf(-(gx[j] + ghr)));
        float z = 1.f / (1.f + expf(-(gx[kH + j] + ghz)));
        float n = tanhf(gx[2 * kH + j] + r * ghn);
        float hold = hread[(size_t)b * kH + j];
        float h2 = (1.f - z) * n + z * hold;
        hwrite[(size_t)b * kH + j] = h2;
        size_t eo = ((size_t)b * kS + gpos) * (2 * kH) + dir * kH + j;
        g_enc16[eo] = __float2half_rn(h2);
    }
}

// ---------------------------------------------------------------------------
// Small-M GEMM body (FFMA2)
// ---------------------------------------------------------------------------
__device__ __forceinline__
void gemm64_body(const float* __restrict__ A, int lda,
                 const float* __restrict__ Bm, int ldb,
                 const float* __restrict__ bias,
                 float* __restrict__ C, int ldc,
                 int K, int act, int nb) {
    constexpr int BK = 32;
    __shared__ __align__(16) float As[BK][64];
    __shared__ __align__(16) float Bs[BK][64];
    const int tid = threadIdx.x;
    const int bn = nb * 64;
    const int lr = tid >> 3;
    const int lc = (tid & 7) << 2;
    const int tm = (tid >> 4) << 2;
    const int tn = (tid & 15) << 2;

    unsigned long long acc[4][2];
#pragma unroll
    for (int i = 0; i < 4; i++) { acc[i][0] = 0ull; acc[i][1] = 0ull; }

    for (int k0 = 0; k0 < K; k0 += BK) {
#pragma unroll
        for (int h = 0; h < 2; h++) {
            int r = lr + h * 32;
            float4 v = *(const float4*)(A + (size_t)r * lda + k0 + lc);
            As[lc + 0][r] = v.x; As[lc + 1][r] = v.y;
            As[lc + 2][r] = v.z; As[lc + 3][r] = v.w;
            float4 w = *(const float4*)(Bm + (size_t)(bn + r) * ldb + k0 + lc);
            Bs[lc + 0][r] = w.x; Bs[lc + 1][r] = w.y;
            Bs[lc + 2][r] = w.z; Bs[lc + 3][r] = w.w;
        }
        __syncthreads();
#pragma unroll
        for (int k = 0; k < BK; k++) {
            float4 af = *(const float4*)&As[k][tm];
            unsigned long long aa[4];
            aa[0] = pk2(af.x); aa[1] = pk2(af.y);
            aa[2] = pk2(af.z); aa[3] = pk2(af.w);
            ulonglong2 bv = *(const ulonglong2*)&Bs[k][tn];
#pragma unroll
            for (int i = 0; i < 4; i++) {
                fma2(acc[i][0], aa[i], bv.x);
                fma2(acc[i][1], aa[i], bv.y);
            }
        }
        __syncthreads();
    }
#pragma unroll
    for (int i = 0; i < 4; i++) {
        int col = bn + tn;
        float4 v;
        v.x = lo2(acc[i][0]); v.y = hi2(acc[i][0]);
        v.z = lo2(acc[i][1]); v.w = hi2(acc[i][1]);
        if (bias) {
            v.x += bias[col + 0]; v.y += bias[col + 1];
            v.z += bias[col + 2]; v.w += bias[col + 3];
        }
        if (act == 1) {
            v.x = tanhf(v.x); v.y = tanhf(v.y);
            v.z = tanhf(v.z); v.w = tanhf(v.w);
        }
        *(float4*)(C + (size_t)(tm + i) * ldc + col) = v;
    }
}

__global__ __launch_bounds__(256)
void gemm64(const float* __restrict__ A, int lda,
            const float* __restrict__ Bm, int ldb,
            const float* __restrict__ bias,
            float* __restrict__ C, int ldc, int K, int act) {
    gemm64_body(A, lda, Bm, ldb, bias, C, ldc, K, act, blockIdx.x);
}

// Decoder pre-attention GEMMs, K-split 2: hp (32 blocks) + ghd (96 blocks)
__global__ __launch_bounds__(256)
void dec_pre_gemm(const float* __restrict__ W_attn,
                  const float* __restrict__ Wh_d,
                  const float* __restrict__ bh_d) {
    int x = blockIdx.x;
    if (x < 32) {
        int ks = x >> 4, nb = x & 15;
        gemm64_body(g_hdec + ks * 512, kH, W_attn + ks * 512, kG, nullptr,
                    g_hp + (size_t)ks * kB * kH, kH, 512, 0, nb);
    } else {
        int i = x - 32;
        int ks = i / 48, nb = i % 48;
        gemm64_body(g_hdec + ks * 512, kH, Wh_d + ks * 512, kH,
                    ks == 0 ? bh_d : nullptr,
                    g_ghd + (size_t)ks * kB * kG, kG, 512, 0, nb);
    }
}

// ---------------------------------------------------------------------------
__global__ void hcat_kernel() {
    int idx = blockIdx.x * blockDim.x + threadIdx.x;
    if (idx >= 2 * kB * kH) return;
    int dir = idx / (kB * kH);
    int rem = idx - dir * (kB * kH);
    int b = rem / kH, j = rem - b * kH;
    g_hcat[(size_t)b * 2 * kH + dir * kH + j] = g_h[0][idx];
}

// ---------------------------------------------------------------------------
// Fully fused decoder step — fp16 streamed operands, merged high-MLP sweep.
// ---------------------------------------------------------------------------
__global__ __launch_bounds__(512)
void attn_step_fused(const int* __restrict__ src,
                     const float* __restrict__ v_attn,
                     const float* __restrict__ gxet_t,
                     float* __restrict__ feat_t) {
    int b = blockIdx.x;
    __shared__ float sc[kS];
    __shared__ float sgxw[kG];
    int tid = threadIdx.x, warp = tid >> 5, lane = tid & 31;
    const float* hp0 = g_hp + (size_t)b * kH;
    const float* hp1 = g_hp + (size_t)kB * kH + (size_t)b * kH;

    // 1. attention scores
    for (int s = warp; s < kS; s += 16) {
        const __half2* ep = (const __half2*)(g_ep16 + ((size_t)b * kS + s) * kH);
        float p = 0.f;
        for (int j2 = lane; j2 < kH / 2; j2 += 32) {
            float2 e = __half22float2(ep[j2]);
            float2 a0 = ((const float2*)hp0)[j2];
            float2 a1 = ((const float2*)hp1)[j2];
            float2 va = ((const float2*)v_attn)[j2];
            p += va.x * tanhf(a0.x + a1.x + e.x);
            p += va.y * tanhf(a0.y + a1.y + e.y);
        }
#pragma unroll
        for (int o = 16; o; o >>= 1) p += __shfl_xor_sync(0xffffffffu, p, o);
        if (lane == 0) sc[s] = (src[s * kB + b] != kPAD) ? p : -1e10f;
    }
    __syncthreads();

    // 2. softmax over S=48
    if (tid < 32) {
        float v1 = sc[tid];
        float v2 = (tid + 32 < kS) ? sc[tid + 32] : -1e30f;
        float mx = fmaxf(v1, v2);
#pragma unroll
        for (int o = 16; o; o >>= 1) mx = fmaxf(mx, __shfl_xor_sync(0xffffffffu, mx, o));
        float e1 = expf(v1 - mx);
        float e2 = (tid + 32 < kS) ? expf(v2 - mx) : 0.f;
        float sm = e1 + e2;
#pragma unroll
        for (int o = 16; o; o >>= 1) sm += __shfl_xor_sync(0xffffffffu, sm, o);
        float inv = 1.f / sm;
        sc[tid] = e1 * inv;
        if (tid + 32 < kS) sc[tid + 32] = e2 * inv;
    }
    __syncthreads();

    // 3. merged context-w + gxw sweep: 640 chunks of 8 fp16 columns.
    //    chunks [0,256): context w from enc16; [256,640): gxw from encWi16.
    {
        const uint4* encb = (const uint4*)(g_enc16 + (size_t)b * kS * 2 * kH);
        const uint4* wib  = (const uint4*)(g_encWi16 + (size_t)b * kS * kG);
        for (int ch = tid; ch < 640; ch += 512) {
            const bool isctx = ch < 256;
            const uint4* base = isctx ? (encb + ch) : (wib + (ch - 256));
            const int stride = isctx ? (2 * kH / 8) : (kG / 8);
            float acc[8];
#pragma unroll
            for (int q = 0; q < 8; q++) acc[q] = 0.f;
#pragma unroll 16
            for (int s = 0; s < kS; s++) {
                uint4 v = base[(size_t)s * stride];
                float a = sc[s];
                __half2 p0 = *reinterpret_cast<__half2*>(&v.x);
                __half2 p1 = *reinterpret_cast<__half2*>(&v.y);
                __half2 p2 = *reinterpret_cast<__half2*>(&v.z);
                __half2 p3 = *reinterpret_cast<__half2*>(&v.w);
                float2 f0 = __half22float2(p0), f1 = __half22float2(p1);
                float2 f2 = __half22float2(p2), f3 = __half22float2(p3);
                acc[0] += a * f0.x; acc[1] += a * f0.y;
                acc[2] += a * f1.x; acc[3] += a * f1.y;
                acc[4] += a * f2.x; acc[5] += a * f2.y;
                acc[6] += a * f3.x; acc[7] += a * f3.y;
            }
            float* dst = isctx ? (feat_t + (size_t)b * kF + kH + ch * 8)
                               : (sgxw + (ch - 256) * 8);
            *(float4*)dst = make_float4(acc[0], acc[1], acc[2], acc[3]);
            *(float4*)(dst + 4) = make_float4(acc[4], acc[5], acc[6], acc[7]);
        }
    }
    __syncthreads();

    // 4. GRU gate -> h2
    const float* q0 = g_ghd + (size_t)b * kG;
    const float* q1 = g_ghd + (size_t)kB * kG + (size_t)b * kG;
    const float* gx = gxet_t + (size_t)b * kG;
    for (int j = tid; j < kH; j += 512) {
        float h = g_hdec[(size_t)b * kH + j];
        float xr = gx[j] + sgxw[j];
        float xz = gx[kH + j] + sgxw[kH + j];
        float xn = gx[2 * kH + j] + sgxw[2 * kH + j];
        float ghr = q0[j] + q1[j];
        float ghz = q0[kH + j] + q1[kH + j];
        float ghn = q0[2 * kH + j] + q1[2 * kH + j];
        float r = 1.f / (1.f + expf(-(xr + ghr)));
        float z = 1.f / (1.f + expf(-(xz + ghz)));
        float n = tanhf(xn + r * ghn);
        float h2 = (1.f - z) * n + z * h;
        g_hdec[(size_t)b * kH + j] = h2;
        feat_t[(size_t)b * kF + j] = h2;
    }
}

// ---------------------------------------------------------------------------
// Host orchestration (two-stream fork/join, graph-capturable)
// ---------------------------------------------------------------------------
extern "C" void kernel_launch(void* const* d_in, const int* in_sizes, int n_in,
                              void* d_out, int out_size) {
    const int*   src     = (const int*)d_in[0];
    const int*   trg     = (const int*)d_in[1];
    const float* emb_enc = (const float*)d_in[2];
    const float* Wi_f    = (const float*)d_in[3];
    const float* Wh_f    = (const float*)d_in[4];
    const float* bi_f    = (const float*)d_in[5];
    const float* bh_f    = (const float*)d_in[6];
    const float* Wi_b    = (const float*)d_in[7];
    const float* Wh_b    = (const float*)d_in[8];
    const float* bi_b    = (const float*)d_in[9];
    const float* bh_b    = (const float*)d_in[10];
    const float* W_fc    = (const float*)d_in[11];
    const float* b_fc    = (const float*)d_in[12];
    const float* W_attn  = (const float*)d_in[13];
    const float* b_attn  = (const float*)d_in[14];
    const float* v_attn  = (const float*)d_in[15];
    const float* emb_dec = (const float*)d_in[16];
    const float* Wi_d    = (const float*)d_in[17];
    const float* Wh_d    = (const float*)d_in[18];
    const float* bi_d    = (const float*)d_in[19];
    const float* bh_d    = (const float*)d_in[20];
    const float* W_out   = (const float*)d_in[21];
    const float* b_out   = (const float*)d_in[22];
    float* out = (float*)d_out;

    float *p_hcat, *p_hdec, *p_gxet, *p_feat, *p_gxf, *p_gxb;
    __half *p_Eh16, *p_Wif16, *p_Wib16;
    __half *p_Fh, *p_Bf16, *p_Wid16, *p_Wa16, *p_encWi16, *p_enc16, *p_ep16;
    cudaGetSymbolAddress((void**)&p_hcat, g_hcat);
    cudaGetSymbolAddress((void**)&p_hdec, g_hdec);
    cudaGetSymbolAddress((void**)&p_gxet, g_gxet);
    cudaGetSymbolAddress((void**)&p_feat, g_feat);
    cudaGetSymbolAddress((void**)&p_gxf, g_gxf);
    cudaGetSymbolAddress((void**)&p_gxb, g_gxb);
    cudaGetSymbolAddress((void**)&p_Eh16, g_Eh16);
    cudaGetSymbolAddress((void**)&p_Wif16, g_Wif16);
    cudaGetSymbolAddress((void**)&p_Wib16, g_Wib16);
    cudaGetSymbolAddress((void**)&p_Fh, g_Fh);
    cudaGetSymbolAddress((void**)&p_Bf16, g_Bf16);
    cudaGetSymbolAddress((void**)&p_Wid16, g_Wid16);
    cudaGetSymbolAddress((void**)&p_Wa16, g_Wa16);
    cudaGetSymbolAddress((void**)&p_encWi16, g_encWi16);
    cudaGetSymbolAddress((void**)&p_enc16, g_enc16);
    cudaGetSymbolAddress((void**)&p_ep16, g_ep16);

    static cudaStream_t s1 = nullptr;
    static cudaEvent_t evFork = nullptr, evJoin = nullptr;
    if (s1 == nullptr) {
        cudaStreamCreateWithFlags(&s1, cudaStreamNonBlocking);
        cudaEventCreateWithFlags(&evFork, cudaEventDisableTiming);
        cudaEventCreateWithFlags(&evJoin, cudaEventDisableTiming);
        cudaFuncSetAttribute(hgemm1,
                             cudaFuncAttributeMaxDynamicSharedMemorySize,
                             out1::SMEM_SZ);
    }

    // fork side stream off the capture stream
    cudaEventRecord(evFork, 0);
    cudaStreamWaitEvent(s1, evFork, 0);

    // --- main stream: encoder-critical path ---
    init_kernel<<<((size_t)kB * kV + 255) / 256, 256>>>(out);
    enc_embed_kernel<<<kME, 128>>>(src, emb_enc);
    {
        size_t n4 = (size_t)kG * kE / 4;
        cvt16_4<<<(unsigned)((n4 + 255) / 256), 256>>>(
            (const float4*)Wi_f, (__half2*)p_Wif16, n4);
        cvt16_4<<<(unsigned)((n4 + 255) / 256), 256>>>(
            (const float4*)Wi_b, (__half2*)p_Wib16, n4);
    }
    // --- side stream: decoder-prep + weight conversions ---
    dec_embed_all<<<kMR, 128, 0, s1>>>(trg, emb_dec);
    // --- main: input-gate GEMMs (single-pass fp16, fp32 out) ---
    hgemm1<<<dim3(kME / 128, kG / 128), 256, out1::SMEM_SZ>>>(
        p_Eh16, kE, p_Wif16, kE, bi_f, p_gxf, (__half*)nullptr, kG, kME, kE);
    hgemm1<<<dim3(kME / 128, kG / 128), 256, out1::SMEM_SZ>>>(
        p_Eh16, kE, p_Wib16, kE, bi_b, p_gxb, (__half*)nullptr, kG, kME, kE);
    // --- side stream continues ---
    {
        size_t n4 = (size_t)kG * kXW / 4;
        cvt16_4<<<(unsigned)((n4 + 255) / 256), 256, 0, s1>>>(
            (const float4*)Wi_d, (__half2*)p_Wid16, n4);
        n4 = (size_t)kH * kG / 4;
        cvt16_4<<<(unsigned)((n4 + 255) / 256), 256, 0, s1>>>(
            (const float4*)W_attn, (__half2*)p_Wa16, n4);
        // gxet = et @ Wi_d[:, :E]^T + bi_d  (A = fp16 et cols of g_Fh)
        hgemm1<<<dim3(kMP / 128, kG / 128), 256, out1::SMEM_SZ, s1>>>(
            p_Fh + 3 * kH, kF, p_Wid16, kXW, bi_d,
            p_gxet, (__half*)nullptr, kG, kMR, kE);
        n4 = (size_t)kV * kF / 4;
        cvt16_4<<<(unsigned)((n4 + 255) / 256), 256, 0, s1>>>(
            (const float4*)W_out, (__half2*)p_Bf16, n4);
    }
    cudaEventRecord(evJoin, s1);

    // --- main: encoder recurrence (emits enc16; overlaps side stream) ---
    for (int s = 0; s < kS; s++)
        enc_step_fused<<<dim3(64, 2), 256>>>(s, Wh_f, Wh_b, bh_f, bh_b);

    // decoder init hidden
    hcat_kernel<<<(2 * kB * kH) / 256, 256>>>();
    gemm64<<<kH / 64, 256>>>(p_hcat, 2 * kH, W_fc, 2 * kH, b_fc,
                             p_hdec, kH, 2 * kH, 1);

    // attention projection + encWi — single-pass fp16 GEMMs, fp16 output
    cudaStreamWaitEvent(0, evJoin, 0);
    hgemm1<<<dim3(kME / 128, kH / 128), 256, out1::SMEM_SZ>>>(
        p_enc16, 2 * kH, p_Wa16 + kH, kG, b_attn,
        (float*)nullptr, p_ep16, kH, kME, 2 * kH);
    hgemm1<<<dim3(kME / 128, kG / 128), 256, out1::SMEM_SZ>>>(
        p_enc16, 2 * kH, p_Wid16 + kE, kXW, (const float*)nullptr,
        (float*)nullptr, p_encWi16, kG, kME, 2 * kH);

    // decoder loop: 2 launches per step
    for (int t = 0; t < kT - 1; t++) {
        float* feat_t = p_feat + (size_t)t * kB * kF;
        dec_pre_gemm<<<128, 256>>>(W_attn, Wh_d, bh_d);
        attn_step_fused<<<kB, 512>>>(src, v_attn,
                                     p_gxet + (size_t)t * kB * kG, feat_t);
    }

    // fp16-convert features, single-pass fp16 output projection
    {
        size_t n = (size_t)kMP * kF / 4;
        cvt_feat16<<<(unsigned)((n + 255) / 256), 256>>>();
        hgemm1<<<dim3(kMP / 128, kV / 128), 256, out1::SMEM_SZ>>>(
            p_Fh, kF, p_Bf16, kF, b_out,
            out + (size_t)kB * kV, (__half*)nullptr, kV, kMR, kF);
    }
}